// round 1
// baseline (speedup 1.0000x reference)
#include <cuda_runtime.h>
#include <cuda_bf16.h>
#include <math.h>

#define Bb 2
#define Tt 2048
#define Dd 2048
#define Hh 16
#define HDd 128

// ---------------- scratch (static device globals; no runtime allocation) ----
__device__ float g_qkv[(size_t)Bb * Tt * 3 * Dd];   // [B*T, 3D]
__device__ float g_q[(size_t)Bb * Hh * Tt * HDd];   // [B,H,T,HD]
__device__ float g_k[(size_t)Bb * Hh * Tt * HDd];
__device__ float g_v[(size_t)Bb * Hh * Tt * HDd];
__device__ float g_ao[(size_t)Bb * Tt * Dd];        // attention out, [B,T,D]
__device__ float g_cos[(size_t)Bb * Tt * 64];
__device__ float g_sin[(size_t)Bb * Tt * 64];

// ---------------- RoPE cos/sin table --------------------------------------
// angle computed with the same f32 rounding as the reference (pos_f32 * invfreq_f32),
// then sin/cos evaluated in double for ~exactness at large |angle|.
__global__ void rope_table_kernel(const int* __restrict__ positions) {
    int idx = blockIdx.x * blockDim.x + threadIdx.x;
    if (idx >= Bb * Tt * 64) return;
    int j = idx & 63;
    int bt = idx >> 6;
    int pos = positions[bt];
    // inv_freq = 10000^{-j/64} = 2^{-(j/64)*log2(10000)}
    float inv_freq = exp2f(-(float)j * (13.287712379549449f / 64.0f));
    float ang = (float)pos * inv_freq;
    double da = (double)ang;
    g_cos[idx] = (float)cos(da);
    g_sin[idx] = (float)sin(da);
}

// ---------------- SGEMM: C[M,N] = A[M,K] @ B[K,N], all row-major ----------
// BM=BN=128, BK=8, 256 threads, 8x8 microtile. M%128==0, N%128==0, K%8==0.
__global__ __launch_bounds__(256) void sgemm_kernel(
    const float* __restrict__ A, const float* __restrict__ B,
    float* __restrict__ C, int M, int N, int K) {
    __shared__ float As[8][128];   // transposed A tile: As[k][m]
    __shared__ float Bs[8][128];

    const int tid = threadIdx.x;
    const int bm = blockIdx.y * 128;
    const int bn = blockIdx.x * 128;

    const int arow = tid >> 1, acol = (tid & 1) * 4;   // A tile 128x8
    const int brow = tid >> 5, bcol = (tid & 31) * 4;  // B tile 8x128
    const int tx = tid & 15, ty = tid >> 4;

    float acc[8][8];
#pragma unroll
    for (int i = 0; i < 8; i++)
#pragma unroll
        for (int j = 0; j < 8; j++) acc[i][j] = 0.0f;

    for (int k0 = 0; k0 < K; k0 += 8) {
        float4 av = *(const float4*)(A + (size_t)(bm + arow) * K + k0 + acol);
        float4 bv = *(const float4*)(B + (size_t)(k0 + brow) * N + bn + bcol);
        As[acol + 0][arow] = av.x;
        As[acol + 1][arow] = av.y;
        As[acol + 2][arow] = av.z;
        As[acol + 3][arow] = av.w;
        *(float4*)&Bs[brow][bcol] = bv;
        __syncthreads();
#pragma unroll
        for (int kk = 0; kk < 8; kk++) {
            float a[8], b[8];
            *(float4*)(a + 0) = *(const float4*)&As[kk][ty * 8];
            *(float4*)(a + 4) = *(const float4*)&As[kk][ty * 8 + 4];
            *(float4*)(b + 0) = *(const float4*)&Bs[kk][tx * 8];
            *(float4*)(b + 4) = *(const float4*)&Bs[kk][tx * 8 + 4];
#pragma unroll
            for (int i = 0; i < 8; i++)
#pragma unroll
                for (int j = 0; j < 8; j++) acc[i][j] += a[i] * b[j];
        }
        __syncthreads();
    }
#pragma unroll
    for (int i = 0; i < 8; i++) {
        float* cp = C + (size_t)(bm + ty * 8 + i) * N + bn + tx * 8;
        float4 r0 = make_float4(acc[i][0], acc[i][1], acc[i][2], acc[i][3]);
        float4 r1 = make_float4(acc[i][4], acc[i][5], acc[i][6], acc[i][7]);
        *(float4*)(cp + 0) = r0;
        *(float4*)(cp + 4) = r1;
    }
}

// ---------------- RoPE + RMSNorm + transpose -------------------------------
// grid (H, T, B), block 128. Reads g_qkv row, writes g_q/g_k/g_v [B,H,T,HD].
__global__ void rope_norm_kernel(const float* __restrict__ qw,
                                 const float* __restrict__ kw) {
    const int h = blockIdx.x, t = blockIdx.y, b = blockIdx.z;
    const int hd = threadIdx.x;
    __shared__ float sq[128], sk[128];
    __shared__ float red[8];

    const size_t row = (size_t)(b * Tt + t) * (3 * Dd);
    float qv = g_qkv[row + h * HDd + hd];
    float kv = g_qkv[row + Dd + h * HDd + hd];
    float vv = g_qkv[row + 2 * Dd + h * HDd + hd];
    sq[hd] = qv;
    sk[hd] = kv;
    __syncthreads();

    const int j = hd & 63;
    const int ci = (b * Tt + t) * 64 + j;
    const float c = g_cos[ci], s = g_sin[ci];
    float rq, rk;
    if (hd < 64) {
        rq = sq[hd] * c - sq[hd + 64] * s;
        rk = sk[hd] * c - sk[hd + 64] * s;
    } else {
        rq = sq[hd] * c + sq[hd - 64] * s;
        rk = sk[hd] * c + sk[hd - 64] * s;
    }
    float s2q = rq * rq, s2k = rk * rk;
#pragma unroll
    for (int m = 16; m >= 1; m >>= 1) {
        s2q += __shfl_xor_sync(0xffffffffu, s2q, m);
        s2k += __shfl_xor_sync(0xffffffffu, s2k, m);
    }
    const int w = hd >> 5;
    if ((hd & 31) == 0) { red[w] = s2q; red[4 + w] = s2k; }
    __syncthreads();
    float sumq = red[0] + red[1] + red[2] + red[3];
    float sumk = red[4] + red[5] + red[6] + red[7];
    float iq = rsqrtf(sumq * (1.0f / 128.0f) + 1e-6f);
    float ik = rsqrtf(sumk * (1.0f / 128.0f) + 1e-6f);

    const size_t o = (size_t)((b * Hh + h) * Tt + t) * HDd + hd;
    g_q[o] = rq * iq * qw[hd];
    g_k[o] = rk * ik * kw[hd];
    g_v[o] = vv;
}

// ---------------- Flash attention (causal, fp32) ---------------------------
// grid (T/64, H, B), block 256. Q tile 64 rows x 128, K/V tiles 64 rows.
// Dynamic smem: Qt[128][64] Kt[128][64] Vs[64][128] Ps[64][65]
#define ATTN_SMEM ((8192 + 8192 + 8192 + 64 * 65) * 4)

__global__ __launch_bounds__(256) void attn_kernel() {
    extern __shared__ float sm[];
    float* Qt = sm;            // d-major [128][64]
    float* Kt = sm + 8192;     // d-major [128][64]
    float* Vs = sm + 16384;    // row-major [64][128]
    float* Ps = sm + 24576;    // [64][65] padded

    const int tid = threadIdx.x;
    const int qb = blockIdx.x, h = blockIdx.y, b = blockIdx.z;
    const int tx = tid & 15, ty = tid >> 4;
    const size_t base = (size_t)(b * Hh + h) * Tt * HDd;
    const int qg0 = qb * 64;

    // load Q tile transposed, pre-scaled by 1/sqrt(HD)
    {
        const float scale = 0.08838834764831845f;
        int r = tid >> 2;
        int d0 = (tid & 3) * 32;
        const float* qp = g_q + base + (size_t)(qg0 + r) * 128 + d0;
#pragma unroll
        for (int i = 0; i < 8; i++) {
            float4 v = *(const float4*)(qp + i * 4);
            Qt[(d0 + i * 4 + 0) * 64 + r] = v.x * scale;
            Qt[(d0 + i * 4 + 1) * 64 + r] = v.y * scale;
            Qt[(d0 + i * 4 + 2) * 64 + r] = v.z * scale;
            Qt[(d0 + i * 4 + 3) * 64 + r] = v.w * scale;
        }
    }

    float o[4][8];
#pragma unroll
    for (int i = 0; i < 4; i++)
#pragma unroll
        for (int j = 0; j < 8; j++) o[i][j] = 0.0f;
    float m_run[4], l_run[4];
#pragma unroll
    for (int i = 0; i < 4; i++) { m_run[i] = -1e30f; l_run[i] = 0.0f; }

    for (int kb = 0; kb <= qb; kb++) {
        const int kg0 = kb * 64;
        __syncthreads();   // previous iteration's smem readers done
        // load K tile transposed
        {
            int r = tid >> 2;
            int d0 = (tid & 3) * 32;
            const float* kp = g_k + base + (size_t)(kg0 + r) * 128 + d0;
#pragma unroll
            for (int i = 0; i < 8; i++) {
                float4 v = *(const float4*)(kp + i * 4);
                Kt[(d0 + i * 4 + 0) * 64 + r] = v.x;
                Kt[(d0 + i * 4 + 1) * 64 + r] = v.y;
                Kt[(d0 + i * 4 + 2) * 64 + r] = v.z;
                Kt[(d0 + i * 4 + 3) * 64 + r] = v.w;
            }
            // V tile: straight copy
            const float4* vp = (const float4*)(g_v + base + (size_t)kg0 * 128);
            float4* vd = (float4*)Vs;
#pragma unroll
            for (int i = 0; i < 8; i++) vd[tid + i * 256] = vp[tid + i * 256];
        }
        __syncthreads();

        // S = Q K^T  (each thread: 4 q-rows x 4 k-cols)
        float s[4][4];
#pragma unroll
        for (int i = 0; i < 4; i++)
#pragma unroll
            for (int j = 0; j < 4; j++) s[i][j] = 0.0f;
#pragma unroll 4
        for (int d = 0; d < 128; d++) {
            float a[4], bb[4];
            *(float4*)a = *(const float4*)&Qt[d * 64 + ty * 4];
            *(float4*)bb = *(const float4*)&Kt[d * 64 + tx * 4];
#pragma unroll
            for (int i = 0; i < 4; i++)
#pragma unroll
                for (int j = 0; j < 4; j++) s[i][j] += a[i] * bb[j];
        }

        if (kb == qb) {
#pragma unroll
            for (int i = 0; i < 4; i++)
#pragma unroll
                for (int j = 0; j < 4; j++)
                    if (kg0 + tx * 4 + j > qg0 + ty * 4 + i) s[i][j] = -1e30f;
        }

        // online softmax per row (reduce across 16 tx lanes, width-16 shfl)
#pragma unroll
        for (int i = 0; i < 4; i++) {
            float mt = fmaxf(fmaxf(s[i][0], s[i][1]), fmaxf(s[i][2], s[i][3]));
#pragma unroll
            for (int m = 8; m >= 1; m >>= 1)
                mt = fmaxf(mt, __shfl_xor_sync(0xffffffffu, mt, m, 16));
            float mnew = fmaxf(m_run[i], mt);
            float corr = __expf(m_run[i] - mnew);
            m_run[i] = mnew;
            float psum = 0.0f;
#pragma unroll
            for (int j = 0; j < 4; j++) {
                float p = __expf(s[i][j] - mnew);
                s[i][j] = p;
                psum += p;
            }
#pragma unroll
            for (int m = 8; m >= 1; m >>= 1)
                psum += __shfl_xor_sync(0xffffffffu, psum, m, 16);
            l_run[i] = l_run[i] * corr + psum;
#pragma unroll
            for (int j = 0; j < 8; j++) o[i][j] *= corr;
#pragma unroll
            for (int j = 0; j < 4; j++)
                Ps[(ty * 4 + i) * 65 + tx * 4 + j] = s[i][j];
        }
        __syncthreads();

        // O += P @ V  (each thread: 4 rows x 8 d-cols)
#pragma unroll 2
        for (int kc = 0; kc < 64; kc++) {
            float p0 = Ps[(ty * 4 + 0) * 65 + kc];
            float p1 = Ps[(ty * 4 + 1) * 65 + kc];
            float p2 = Ps[(ty * 4 + 2) * 65 + kc];
            float p3 = Ps[(ty * 4 + 3) * 65 + kc];
            float4 v0 = *(const float4*)&Vs[kc * 128 + tx * 8];
            float4 v1 = *(const float4*)&Vs[kc * 128 + tx * 8 + 4];
            float vv[8] = {v0.x, v0.y, v0.z, v0.w, v1.x, v1.y, v1.z, v1.w};
#pragma unroll
            for (int j = 0; j < 8; j++) {
                o[0][j] += p0 * vv[j];
                o[1][j] += p1 * vv[j];
                o[2][j] += p2 * vv[j];
                o[3][j] += p3 * vv[j];
            }
        }
    }

    // epilogue: normalize, write [B,T,H,HD] == [B,T,D]
#pragma unroll
    for (int i = 0; i < 4; i++) {
        float inv = 1.0f / l_run[i];
        int qg = qg0 + ty * 4 + i;
        float* op = g_ao + ((size_t)(b * Tt + qg) * Hh + h) * HDd + tx * 8;
        float4 r0 = make_float4(o[i][0] * inv, o[i][1] * inv, o[i][2] * inv, o[i][3] * inv);
        float4 r1 = make_float4(o[i][4] * inv, o[i][5] * inv, o[i][6] * inv, o[i][7] * inv);
        *(float4*)(op + 0) = r0;
        *(float4*)(op + 4) = r1;
    }
}

// ---------------- launch ----------------------------------------------------
extern "C" void kernel_launch(void* const* d_in, const int* in_sizes, int n_in,
                              void* d_out, int out_size) {
    const float* x = (const float*)d_in[0];
    // d_in[1] = attn_mask (tril causal) — causality handled analytically
    const int* positions = (const int*)d_in[2];
    const float* qkv_w = (const float*)d_in[3];
    const float* out_w = (const float*)d_in[4];
    const float* q_norm_w = (const float*)d_in[5];
    const float* k_norm_w = (const float*)d_in[6];
    float* out = (float*)d_out;
    (void)in_sizes; (void)n_in; (void)out_size;

    void* p_qkv = nullptr;
    void* p_ao = nullptr;
    cudaGetSymbolAddress(&p_qkv, g_qkv);
    cudaGetSymbolAddress(&p_ao, g_ao);

    // 1) rope table
    rope_table_kernel<<<(Bb * Tt * 64 + 255) / 256, 256>>>(positions);

    // 2) qkv = x @ qkv_w   [4096,2048]x[2048,6144]
    sgemm_kernel<<<dim3(3 * Dd / 128, Bb * Tt / 128), 256>>>(
        x, qkv_w, (float*)p_qkv, Bb * Tt, 3 * Dd, Dd);

    // 3) rope + rmsnorm + transpose
    rope_norm_kernel<<<dim3(Hh, Tt, Bb), 128>>>(q_norm_w, k_norm_w);

    // 4) causal flash attention
    cudaFuncSetAttribute(attn_kernel,
                         cudaFuncAttributeMaxDynamicSharedMemorySize, ATTN_SMEM);
    attn_kernel<<<dim3(Tt / 64, Hh, Bb), 256, ATTN_SMEM>>>();

    // 5) out = attn_out @ out_w   [4096,2048]x[2048,2048]
    sgemm_kernel<<<dim3(Dd / 128, Bb * Tt / 128), 256>>>(
        (const float*)p_ao, out_w, out, Bb * Tt, Dd, Dd);
}

// round 3
// speedup vs baseline: 1.6706x; 1.6706x over previous
#include <cuda_runtime.h>
#include <cuda_bf16.h>
#include <math.h>
#include <stdint.h>

#define Bb 2
#define Tt 2048
#define Dd 2048
#define Hh 16
#define HDd 128

// ================= scratch ==================================================
__device__ float g_qkv[(size_t)Bb * Tt * 3 * Dd];
__device__ float g_q[(size_t)Bb * Hh * Tt * HDd];
__device__ float g_k[(size_t)Bb * Hh * Tt * HDd];
__device__ float g_v[(size_t)Bb * Hh * Tt * HDd];
__device__ float g_ao[(size_t)Bb * Tt * Dd];
__device__ float g_cos[(size_t)Bb * Tt * 64];
__device__ float g_sin[(size_t)Bb * Tt * 64];
// bf16 split operands
__device__ __nv_bfloat16 g_xh[(size_t)Bb * Tt * Dd];
__device__ __nv_bfloat16 g_xl[(size_t)Bb * Tt * Dd];
__device__ __nv_bfloat16 g_aoh[(size_t)Bb * Tt * Dd];
__device__ __nv_bfloat16 g_aol[(size_t)Bb * Tt * Dd];
__device__ __nv_bfloat16 g_wqh[(size_t)3 * Dd * Dd];   // qkv_w^T [6144][2048]
__device__ __nv_bfloat16 g_wql[(size_t)3 * Dd * Dd];
__device__ __nv_bfloat16 g_woh[(size_t)Dd * Dd];       // out_w^T [2048][2048]
__device__ __nv_bfloat16 g_wol[(size_t)Dd * Dd];

// ================= RoPE table ==============================================
__global__ void rope_table_kernel(const int* __restrict__ positions) {
    int idx = blockIdx.x * blockDim.x + threadIdx.x;
    if (idx >= Bb * Tt * 64) return;
    int j = idx & 63;
    int bt = idx >> 6;
    int pos = positions[bt];
    float inv_freq = exp2f(-(float)j * (13.287712379549449f / 64.0f));
    float ang = (float)pos * inv_freq;
    double da = (double)ang;
    g_cos[idx] = (float)cos(da);
    g_sin[idx] = (float)sin(da);
}

// ================= split-convert (elementwise) ==============================
__global__ void convert_split_kernel(const float* __restrict__ in,
                                     __nv_bfloat16* __restrict__ oh,
                                     __nv_bfloat16* __restrict__ ol, int n4) {
    int i = blockIdx.x * blockDim.x + threadIdx.x;
    if (i >= n4) return;
    float4 v = ((const float4*)in)[i];
    __nv_bfloat16 hx = __float2bfloat16(v.x);
    __nv_bfloat16 hy = __float2bfloat16(v.y);
    __nv_bfloat16 hz = __float2bfloat16(v.z);
    __nv_bfloat16 hw = __float2bfloat16(v.w);
    __nv_bfloat16 lx = __float2bfloat16(v.x - __bfloat162float(hx));
    __nv_bfloat16 ly = __float2bfloat16(v.y - __bfloat162float(hy));
    __nv_bfloat16 lz = __float2bfloat16(v.z - __bfloat162float(hz));
    __nv_bfloat16 lw = __float2bfloat16(v.w - __bfloat162float(hw));
    ((__nv_bfloat162*)oh)[2 * i + 0] = __nv_bfloat162(hx, hy);
    ((__nv_bfloat162*)oh)[2 * i + 1] = __nv_bfloat162(hz, hw);
    ((__nv_bfloat162*)ol)[2 * i + 0] = __nv_bfloat162(lx, ly);
    ((__nv_bfloat162*)ol)[2 * i + 1] = __nv_bfloat162(lz, lw);
}

// ================= transpose + split convert ================================
// W[Krows][Ncols] fp32 -> T[Ncols][Krows] bf16 hi/lo
__global__ void transpose_split_kernel(const float* __restrict__ W,
                                       __nv_bfloat16* __restrict__ Th,
                                       __nv_bfloat16* __restrict__ Tl,
                                       int Krows, int Ncols) {
    __shared__ float t[32][33];
    int n0 = blockIdx.x * 32, k0 = blockIdx.y * 32;
    int tx = threadIdx.x, ty = threadIdx.y;
#pragma unroll
    for (int i = ty; i < 32; i += 8)
        t[i][tx] = W[(size_t)(k0 + i) * Ncols + n0 + tx];
    __syncthreads();
#pragma unroll
    for (int i = ty; i < 32; i += 8) {
        float v = t[tx][i];
        __nv_bfloat16 h = __float2bfloat16(v);
        __nv_bfloat16 l = __float2bfloat16(v - __bfloat162float(h));
        size_t o = (size_t)(n0 + i) * Krows + k0 + tx;
        Th[o] = h;
        Tl[o] = l;
    }
}

// ================= mma.sync bf16x3 GEMM =====================================
// C[M,N] = A[M,K] @ B[N,K]^T, A/B as hi/lo bf16 K-major rows.
// Tile 128x128, BK=32, 256 threads (8 warps, 2x4), warp tile 64x32.
// SMEM rows padded to 40 bf16 (80B) -> conflict-free b32 fragment loads.
#define BKP 40
#define TILE_E (128 * BKP)          // elems per operand tile
#define STAGE_E (4 * TILE_E)        // Ah, Al, Bh, Bl
#define GEMM_SMEM (2 * STAGE_E * 2) // bytes (bf16), double buffered = 81920

__device__ __forceinline__ void mma_bf16(float* d, const uint32_t* a, const uint32_t* b) {
    asm volatile(
        "mma.sync.aligned.m16n8k16.row.col.f32.bf16.bf16.f32 "
        "{%0,%1,%2,%3}, {%4,%5,%6,%7}, {%8,%9}, {%0,%1,%2,%3};"
        : "+f"(d[0]), "+f"(d[1]), "+f"(d[2]), "+f"(d[3])
        : "r"(a[0]), "r"(a[1]), "r"(a[2]), "r"(a[3]), "r"(b[0]), "r"(b[1]));
}

__global__ __launch_bounds__(256) void gemm_mma_kernel(
    const __nv_bfloat16* __restrict__ Ah, const __nv_bfloat16* __restrict__ Al,
    const __nv_bfloat16* __restrict__ Bh, const __nv_bfloat16* __restrict__ Bl,
    float* __restrict__ C, int M, int N, int K) {
    extern __shared__ __align__(128) __nv_bfloat16 smem[];
    const int tid = threadIdx.x;
    const int lane = tid & 31;
    const int wid = tid >> 5;
    const int g = lane >> 2;             // 0..7
    const int t2 = (lane & 3) * 2;       // 0,2,4,6
    const int wm = wid & 1, wn = wid >> 1;
    const int m0 = wm * 64, n0 = wn * 32;
    const int bm = blockIdx.y * 128;
    const int bn = blockIdx.x * 128;

    const __nv_bfloat16* srcs[4] = {Ah + (size_t)bm * K, Al + (size_t)bm * K,
                                    Bh + (size_t)bn * K, Bl + (size_t)bn * K};

    uint32_t smem_base;
    asm("{ .reg .u64 t; cvta.to.shared.u64 t, %1; cvt.u32.u64 %0, t; }"
        : "=r"(smem_base) : "l"(smem));

    float acc[4][4][4];
#pragma unroll
    for (int mi = 0; mi < 4; mi++)
#pragma unroll
        for (int ni = 0; ni < 4; ni++)
#pragma unroll
            for (int c = 0; c < 4; c++) acc[mi][ni][c] = 0.0f;

    const int nK = K >> 5;

    // ---- async tile loader: 4 tiles x 128 rows x 4 segs(16B) = 2048 segs ----
    auto load_stage = [&](int s, int kb) {
        const int k0 = kb * 32;
#pragma unroll
        for (int i = 0; i < 8; i++) {
            int idx = i * 256 + tid;            // 0..2047
            int tile = idx >> 9;
            int rem = idx & 511;
            int row = rem >> 2;
            int seg = rem & 3;
            const __nv_bfloat16* gp = srcs[tile] + (size_t)row * K + k0 + seg * 8;
            uint32_t sa = smem_base +
                (uint32_t)(s * STAGE_E + tile * TILE_E + row * BKP + seg * 8) * 2;
            asm volatile("cp.async.ca.shared.global [%0], [%1], 16;"
                         :: "r"(sa), "l"(gp));
        }
    };

    load_stage(0, 0);
    asm volatile("cp.async.commit_group;");

    for (int kb = 0; kb < nK; kb++) {
        const int cur = kb & 1;
        if (kb + 1 < nK) {
            load_stage(cur ^ 1, kb + 1);
            asm volatile("cp.async.commit_group;");
            asm volatile("cp.async.wait_group 1;");
        } else {
            asm volatile("cp.async.wait_group 0;");
        }
        __syncthreads();

        const __nv_bfloat16* sAh = smem + cur * STAGE_E;
        const __nv_bfloat16* sAl = sAh + TILE_E;
        const __nv_bfloat16* sBh = sAh + 2 * TILE_E;
        const __nv_bfloat16* sBl = sAh + 3 * TILE_E;

#pragma unroll
        for (int ks = 0; ks < 32; ks += 16) {
            uint32_t ah[4][4], al[4][4], bh[4][2], bl[4][2];
#pragma unroll
            for (int mi = 0; mi < 4; mi++) {
                int r = m0 + mi * 16 + g;
                ah[mi][0] = *(const uint32_t*)&sAh[r * BKP + ks + t2];
                ah[mi][1] = *(const uint32_t*)&sAh[(r + 8) * BKP + ks + t2];
                ah[mi][2] = *(const uint32_t*)&sAh[r * BKP + ks + t2 + 8];
                ah[mi][3] = *(const uint32_t*)&sAh[(r + 8) * BKP + ks + t2 + 8];
                al[mi][0] = *(const uint32_t*)&sAl[r * BKP + ks + t2];
                al[mi][1] = *(const uint32_t*)&sAl[(r + 8) * BKP + ks + t2];
                al[mi][2] = *(const uint32_t*)&sAl[r * BKP + ks + t2 + 8];
                al[mi][3] = *(const uint32_t*)&sAl[(r + 8) * BKP + ks + t2 + 8];
            }
#pragma unroll
            for (int ni = 0; ni < 4; ni++) {
                int r = n0 + ni * 8 + g;
                bh[ni][0] = *(const uint32_t*)&sBh[r * BKP + ks + t2];
                bh[ni][1] = *(const uint32_t*)&sBh[r * BKP + ks + t2 + 8];
                bl[ni][0] = *(const uint32_t*)&sBl[r * BKP + ks + t2];
                bl[ni][1] = *(const uint32_t*)&sBl[r * BKP + ks + t2 + 8];
            }
#pragma unroll
            for (int mi = 0; mi < 4; mi++)
#pragma unroll
                for (int ni = 0; ni < 4; ni++) {
                    mma_bf16(acc[mi][ni], ah[mi], bh[ni]);
                    mma_bf16(acc[mi][ni], ah[mi], bl[ni]);
                    mma_bf16(acc[mi][ni], al[mi], bh[ni]);
                }
        }
        __syncthreads();
    }

    // ---- epilogue ----
#pragma unroll
    for (int mi = 0; mi < 4; mi++) {
#pragma unroll
        for (int ni = 0; ni < 4; ni++) {
            int row = bm + m0 + mi * 16 + g;
            int col = bn + n0 + ni * 8 + t2;
            *(float2*)&C[(size_t)row * N + col] =
                make_float2(acc[mi][ni][0], acc[mi][ni][1]);
            *(float2*)&C[(size_t)(row + 8) * N + col] =
                make_float2(acc[mi][ni][2], acc[mi][ni][3]);
        }
    }
}

// ================= RoPE + RMSNorm + transpose ===============================
__global__ void rope_norm_kernel(const float* __restrict__ qw,
                                 const float* __restrict__ kw) {
    const int h = blockIdx.x, t = blockIdx.y, b = blockIdx.z;
    const int hd = threadIdx.x;
    __shared__ float sq[128], sk[128];
    __shared__ float red[8];

    const size_t row = (size_t)(b * Tt + t) * (3 * Dd);
    float qv = g_qkv[row + h * HDd + hd];
    float kv = g_qkv[row + Dd + h * HDd + hd];
    float vv = g_qkv[row + 2 * Dd + h * HDd + hd];
    sq[hd] = qv;
    sk[hd] = kv;
    __syncthreads();

    const int j = hd & 63;
    const int ci = (b * Tt + t) * 64 + j;
    const float c = g_cos[ci], s = g_sin[ci];
    float rq, rk;
    if (hd < 64) {
        rq = sq[hd] * c - sq[hd + 64] * s;
        rk = sk[hd] * c - sk[hd + 64] * s;
    } else {
        rq = sq[hd] * c + sq[hd - 64] * s;
        rk = sk[hd] * c + sk[hd - 64] * s;
    }
    float s2q = rq * rq, s2k = rk * rk;
#pragma unroll
    for (int m = 16; m >= 1; m >>= 1) {
        s2q += __shfl_xor_sync(0xffffffffu, s2q, m);
        s2k += __shfl_xor_sync(0xffffffffu, s2k, m);
    }
    const int w = hd >> 5;
    if ((hd & 31) == 0) { red[w] = s2q; red[4 + w] = s2k; }
    __syncthreads();
    float sumq = red[0] + red[1] + red[2] + red[3];
    float sumk = red[4] + red[5] + red[6] + red[7];
    float iq = rsqrtf(sumq * (1.0f / 128.0f) + 1e-6f);
    float ik = rsqrtf(sumk * (1.0f / 128.0f) + 1e-6f);

    const size_t o = (size_t)((b * Hh + h) * Tt + t) * HDd + hd;
    g_q[o] = rq * iq * qw[hd];
    g_k[o] = rk * ik * kw[hd];
    g_v[o] = vv;
}

// ================= Flash attention (causal, fp32) ===========================
#define ATTN_SMEM ((8192 + 8192 + 8192 + 64 * 65) * 4)

__global__ __launch_bounds__(256) void attn_kernel() {
    extern __shared__ float sm[];
    float* Qt = sm;
    float* Kt = sm + 8192;
    float* Vs = sm + 16384;
    float* Ps = sm + 24576;

    const int tid = threadIdx.x;
    const int qb = blockIdx.x, h = blockIdx.y, b = blockIdx.z;
    const int tx = tid & 15, ty = tid >> 4;
    const size_t base = (size_t)(b * Hh + h) * Tt * HDd;
    const int qg0 = qb * 64;

    {
        const float scale = 0.08838834764831845f;
        int r = tid >> 2;
        int d0 = (tid & 3) * 32;
        const float* qp = g_q + base + (size_t)(qg0 + r) * 128 + d0;
#pragma unroll
        for (int i = 0; i < 8; i++) {
            float4 v = *(const float4*)(qp + i * 4);
            Qt[(d0 + i * 4 + 0) * 64 + r] = v.x * scale;
            Qt[(d0 + i * 4 + 1) * 64 + r] = v.y * scale;
            Qt[(d0 + i * 4 + 2) * 64 + r] = v.z * scale;
            Qt[(d0 + i * 4 + 3) * 64 + r] = v.w * scale;
        }
    }

    float o[4][8];
#pragma unroll
    for (int i = 0; i < 4; i++)
#pragma unroll
        for (int j = 0; j < 8; j++) o[i][j] = 0.0f;
    float m_run[4], l_run[4];
#pragma unroll
    for (int i = 0; i < 4; i++) { m_run[i] = -1e30f; l_run[i] = 0.0f; }

    for (int kb = 0; kb <= qb; kb++) {
        const int kg0 = kb * 64;
        __syncthreads();
        {
            int r = tid >> 2;
            int d0 = (tid & 3) * 32;
            const float* kp = g_k + base + (size_t)(kg0 + r) * 128 + d0;
#pragma unroll
            for (int i = 0; i < 8; i++) {
                float4 v = *(const float4*)(kp + i * 4);
                Kt[(d0 + i * 4 + 0) * 64 + r] = v.x;
                Kt[(d0 + i * 4 + 1) * 64 + r] = v.y;
                Kt[(d0 + i * 4 + 2) * 64 + r] = v.z;
                Kt[(d0 + i * 4 + 3) * 64 + r] = v.w;
            }
            const float4* vp = (const float4*)(g_v + base + (size_t)kg0 * 128);
            float4* vd = (float4*)Vs;
#pragma unroll
            for (int i = 0; i < 8; i++) vd[tid + i * 256] = vp[tid + i * 256];
        }
        __syncthreads();

        float s[4][4];
#pragma unroll
        for (int i = 0; i < 4; i++)
#pragma unroll
            for (int j = 0; j < 4; j++) s[i][j] = 0.0f;
#pragma unroll 4
        for (int d = 0; d < 128; d++) {
            float a[4], bb[4];
            *(float4*)a = *(const float4*)&Qt[d * 64 + ty * 4];
            *(float4*)bb = *(const float4*)&Kt[d * 64 + tx * 4];
#pragma unroll
            for (int i = 0; i < 4; i++)
#pragma unroll
                for (int j = 0; j < 4; j++) s[i][j] += a[i] * bb[j];
        }

        if (kb == qb) {
#pragma unroll
            for (int i = 0; i < 4; i++)
#pragma unroll
                for (int j = 0; j < 4; j++)
                    if (kg0 + tx * 4 + j > qg0 + ty * 4 + i) s[i][j] = -1e30f;
        }

#pragma unroll
        for (int i = 0; i < 4; i++) {
            float mt = fmaxf(fmaxf(s[i][0], s[i][1]), fmaxf(s[i][2], s[i][3]));
#pragma unroll
            for (int m = 8; m >= 1; m >>= 1)
                mt = fmaxf(mt, __shfl_xor_sync(0xffffffffu, mt, m, 16));
            float mnew = fmaxf(m_run[i], mt);
            float corr = __expf(m_run[i] - mnew);
            m_run[i] = mnew;
            float psum = 0.0f;
#pragma unroll
            for (int j = 0; j < 4; j++) {
                float p = __expf(s[i][j] - mnew);
                s[i][j] = p;
                psum += p;
            }
#pragma unroll
            for (int m = 8; m >= 1; m >>= 1)
                psum += __shfl_xor_sync(0xffffffffu, psum, m, 16);
            l_run[i] = l_run[i] * corr + psum;
#pragma unroll
            for (int j = 0; j < 8; j++) o[i][j] *= corr;
#pragma unroll
            for (int j = 0; j < 4; j++)
                Ps[(ty * 4 + i) * 65 + tx * 4 + j] = s[i][j];
        }
        __syncthreads();

#pragma unroll 2
        for (int kc = 0; kc < 64; kc++) {
            float p0 = Ps[(ty * 4 + 0) * 65 + kc];
            float p1 = Ps[(ty * 4 + 1) * 65 + kc];
            float p2 = Ps[(ty * 4 + 2) * 65 + kc];
            float p3 = Ps[(ty * 4 + 3) * 65 + kc];
            float4 v0 = *(const float4*)&Vs[kc * 128 + tx * 8];
            float4 v1 = *(const float4*)&Vs[kc * 128 + tx * 8 + 4];
            float vv[8] = {v0.x, v0.y, v0.z, v0.w, v1.x, v1.y, v1.z, v1.w};
#pragma unroll
            for (int j = 0; j < 8; j++) {
                o[0][j] += p0 * vv[j];
                o[1][j] += p1 * vv[j];
                o[2][j] += p2 * vv[j];
                o[3][j] += p3 * vv[j];
            }
        }
    }

#pragma unroll
    for (int i = 0; i < 4; i++) {
        float inv = 1.0f / l_run[i];
        int qg = qg0 + ty * 4 + i;
        float* op = g_ao + ((size_t)(b * Tt + qg) * Hh + h) * HDd + tx * 8;
        float4 r0 = make_float4(o[i][0] * inv, o[i][1] * inv, o[i][2] * inv, o[i][3] * inv);
        float4 r1 = make_float4(o[i][4] * inv, o[i][5] * inv, o[i][6] * inv, o[i][7] * inv);
        *(float4*)(op + 0) = r0;
        *(float4*)(op + 4) = r1;
    }
}

// ================= launch ===================================================
extern "C" void kernel_launch(void* const* d_in, const int* in_sizes, int n_in,
                              void* d_out, int out_size) {
    const float* x = (const float*)d_in[0];
    const int* positions = (const int*)d_in[2];
    const float* qkv_w = (const float*)d_in[3];
    const float* out_w = (const float*)d_in[4];
    const float* q_norm_w = (const float*)d_in[5];
    const float* k_norm_w = (const float*)d_in[6];
    float* out = (float*)d_out;
    (void)in_sizes; (void)n_in; (void)out_size;

    void *p_qkv, *p_ao;
    void *p_xh, *p_xl, *p_aoh, *p_aol, *p_wqh, *p_wql, *p_woh, *p_wol;
    cudaGetSymbolAddress(&p_qkv, g_qkv);
    cudaGetSymbolAddress(&p_ao, g_ao);
    cudaGetSymbolAddress(&p_xh, g_xh);
    cudaGetSymbolAddress(&p_xl, g_xl);
    cudaGetSymbolAddress(&p_aoh, g_aoh);
    cudaGetSymbolAddress(&p_aol, g_aol);
    cudaGetSymbolAddress(&p_wqh, g_wqh);
    cudaGetSymbolAddress(&p_wql, g_wql);
    cudaGetSymbolAddress(&p_woh, g_woh);
    cudaGetSymbolAddress(&p_wol, g_wol);

    static int attr_set = 0;
    if (!attr_set) {
        cudaFuncSetAttribute(attn_kernel, cudaFuncAttributeMaxDynamicSharedMemorySize, ATTN_SMEM);
        cudaFuncSetAttribute(gemm_mma_kernel, cudaFuncAttributeMaxDynamicSharedMemorySize, GEMM_SMEM);
        attr_set = 1;
    }

    const int M = Bb * Tt;  // 4096

    // 1) rope table
    rope_table_kernel<<<(Bb * Tt * 64 + 255) / 256, 256>>>(positions);

    // 2) operand prep
    convert_split_kernel<<<(M * Dd / 4 + 255) / 256, 256>>>(
        x, (__nv_bfloat16*)p_xh, (__nv_bfloat16*)p_xl, M * Dd / 4);
    transpose_split_kernel<<<dim3(3 * Dd / 32, Dd / 32), dim3(32, 8)>>>(
        qkv_w, (__nv_bfloat16*)p_wqh, (__nv_bfloat16*)p_wql, Dd, 3 * Dd);
    transpose_split_kernel<<<dim3(Dd / 32, Dd / 32), dim3(32, 8)>>>(
        out_w, (__nv_bfloat16*)p_woh, (__nv_bfloat16*)p_wol, Dd, Dd);

    // 3) qkv = x @ qkv_w  (mma.sync bf16x3)
    gemm_mma_kernel<<<dim3(3 * Dd / 128, M / 128), 256, GEMM_SMEM>>>(
        (const __nv_bfloat16*)p_xh, (const __nv_bfloat16*)p_xl,
        (const __nv_bfloat16*)p_wqh, (const __nv_bfloat16*)p_wql,
        (float*)p_qkv, M, 3 * Dd, Dd);

    // 4) rope + rmsnorm + transpose
    rope_norm_kernel<<<dim3(Hh, Tt, Bb), 128>>>(q_norm_w, k_norm_w);

    // 5) causal flash attention (fp32)
    attn_kernel<<<dim3(Tt / 64, Hh, Bb), 256, ATTN_SMEM>>>();

    // 6) split attention output, out = ao @ out_w
    convert_split_kernel<<<(M * Dd / 4 + 255) / 256, 256>>>(
        (const float*)p_ao, (__nv_bfloat16*)p_aoh, (__nv_bfloat16*)p_aol, M * Dd / 4);
    gemm_mma_kernel<<<dim3(Dd / 128, M / 128), 256, GEMM_SMEM>>>(
        (const __nv_bfloat16*)p_aoh, (const __nv_bfloat16*)p_aol,
        (const __nv_bfloat16*)p_woh, (const __nv_bfloat16*)p_wol,
        out, M, Dd, Dd);
}

// round 7
// speedup vs baseline: 2.5220x; 1.5096x over previous
#include <cuda_runtime.h>
#include <cuda_bf16.h>
#include <math.h>
#include <stdint.h>

#define Bb 2
#define Tt 2048
#define Dd 2048
#define Hh 16
#define HDd 128

// ================= scratch ==================================================
__device__ float g_qkv[(size_t)Bb * Tt * 3 * Dd];
__device__ float g_cos[(size_t)Bb * Tt * 64];
__device__ float g_sin[(size_t)Bb * Tt * 64];
__device__ __nv_bfloat16 g_xh[(size_t)Bb * Tt * Dd];
__device__ __nv_bfloat16 g_xl[(size_t)Bb * Tt * Dd];
__device__ __nv_bfloat16 g_aoh[(size_t)Bb * Tt * Dd];
__device__ __nv_bfloat16 g_aol[(size_t)Bb * Tt * Dd];
__device__ __nv_bfloat16 g_wqh[(size_t)3 * Dd * Dd];
__device__ __nv_bfloat16 g_wql[(size_t)3 * Dd * Dd];
__device__ __nv_bfloat16 g_woh[(size_t)Dd * Dd];
__device__ __nv_bfloat16 g_wol[(size_t)Dd * Dd];
__device__ __nv_bfloat16 g_qh[(size_t)Bb * Hh * Tt * HDd];
__device__ __nv_bfloat16 g_ql[(size_t)Bb * Hh * Tt * HDd];
__device__ __nv_bfloat16 g_kh[(size_t)Bb * Hh * Tt * HDd];
__device__ __nv_bfloat16 g_kl[(size_t)Bb * Hh * Tt * HDd];
__device__ __nv_bfloat16 g_vh[(size_t)Bb * Hh * Tt * HDd];
__device__ __nv_bfloat16 g_vl[(size_t)Bb * Hh * Tt * HDd];

__device__ __forceinline__ uint32_t smem_u32(const void* p) {
    uint32_t a;
    asm("{ .reg .u64 t; cvta.to.shared.u64 t, %1; cvt.u32.u64 %0, t; }" : "=r"(a) : "l"(p));
    return a;
}

// ================= RoPE table ==============================================
__global__ void rope_table_kernel(const int* __restrict__ positions) {
    int idx = blockIdx.x * blockDim.x + threadIdx.x;
    if (idx >= Bb * Tt * 64) return;
    int j = idx & 63;
    int bt = idx >> 6;
    int pos = positions[bt];
    float inv_freq = exp2f(-(float)j * (13.287712379549449f / 64.0f));
    float ang = (float)pos * inv_freq;
    double da = (double)ang;
    g_cos[idx] = (float)cos(da);
    g_sin[idx] = (float)sin(da);
}

// ================= split-convert (elementwise) ==============================
__global__ void convert_split_kernel(const float* __restrict__ in,
                                     __nv_bfloat16* __restrict__ oh,
                                     __nv_bfloat16* __restrict__ ol, int n4) {
    int i = blockIdx.x * blockDim.x + threadIdx.x;
    if (i >= n4) return;
    float4 v = ((const float4*)in)[i];
    __nv_bfloat16 hx = __float2bfloat16(v.x);
    __nv_bfloat16 hy = __float2bfloat16(v.y);
    __nv_bfloat16 hz = __float2bfloat16(v.z);
    __nv_bfloat16 hw = __float2bfloat16(v.w);
    __nv_bfloat16 lx = __float2bfloat16(v.x - __bfloat162float(hx));
    __nv_bfloat16 ly = __float2bfloat16(v.y - __bfloat162float(hy));
    __nv_bfloat16 lz = __float2bfloat16(v.z - __bfloat162float(hz));
    __nv_bfloat16 lw = __float2bfloat16(v.w - __bfloat162float(hw));
    ((__nv_bfloat162*)oh)[2 * i + 0] = __nv_bfloat162(hx, hy);
    ((__nv_bfloat162*)oh)[2 * i + 1] = __nv_bfloat162(hz, hw);
    ((__nv_bfloat162*)ol)[2 * i + 0] = __nv_bfloat162(lx, ly);
    ((__nv_bfloat162*)ol)[2 * i + 1] = __nv_bfloat162(lz, lw);
}

// ================= transpose + split convert (both weights) =================
__global__ void transpose_split_kernel(const float* __restrict__ W0,
                                       const float* __restrict__ W1) {
    __shared__ float t[32][33];
    int z = blockIdx.z;
    int Ncols = z ? Dd : 3 * Dd;
    const float* W = z ? W1 : W0;
    __nv_bfloat16* Th = z ? g_woh : g_wqh;
    __nv_bfloat16* Tl = z ? g_wol : g_wql;
    int n0 = blockIdx.x * 32, k0 = blockIdx.y * 32;
    if (n0 >= Ncols) return;
    int tx = threadIdx.x, ty = threadIdx.y;
#pragma unroll
    for (int i = ty; i < 32; i += 8)
        t[i][tx] = W[(size_t)(k0 + i) * Ncols + n0 + tx];
    __syncthreads();
#pragma unroll
    for (int i = ty; i < 32; i += 8) {
        float v = t[tx][i];
        __nv_bfloat16 h = __float2bfloat16(v);
        __nv_bfloat16 l = __float2bfloat16(v - __bfloat162float(h));
        size_t o = (size_t)(n0 + i) * Dd + k0 + tx;
        Th[o] = h;
        Tl[o] = l;
    }
}

// ================= mma.sync bf16x3 GEMM (proven) ============================
#define BKP 40
#define TILE_E (128 * BKP)
#define STAGE_E (4 * TILE_E)
#define GEMM_SMEM (2 * STAGE_E * 2)

__device__ __forceinline__ void mma_bf16(float* d, const uint32_t* a, const uint32_t* b) {
    asm volatile(
        "mma.sync.aligned.m16n8k16.row.col.f32.bf16.bf16.f32 "
        "{%0,%1,%2,%3}, {%4,%5,%6,%7}, {%8,%9}, {%0,%1,%2,%3};"
        : "+f"(d[0]), "+f"(d[1]), "+f"(d[2]), "+f"(d[3])
        : "r"(a[0]), "r"(a[1]), "r"(a[2]), "r"(a[3]), "r"(b[0]), "r"(b[1]));
}

__global__ __launch_bounds__(256) void gemm_mma_kernel(
    const __nv_bfloat16* __restrict__ Ah, const __nv_bfloat16* __restrict__ Al,
    const __nv_bfloat16* __restrict__ Bh, const __nv_bfloat16* __restrict__ Bl,
    float* __restrict__ C, int M, int N, int K) {
    extern __shared__ __align__(128) __nv_bfloat16 smem[];
    const int tid = threadIdx.x;
    const int lane = tid & 31;
    const int wid = tid >> 5;
    const int g = lane >> 2;
    const int t2 = (lane & 3) * 2;
    const int wm = wid & 1, wn = wid >> 1;
    const int m0 = wm * 64, n0 = wn * 32;
    const int bm = blockIdx.y * 128;
    const int bn = blockIdx.x * 128;

    const __nv_bfloat16* srcs[4] = {Ah + (size_t)bm * K, Al + (size_t)bm * K,
                                    Bh + (size_t)bn * K, Bl + (size_t)bn * K};

    uint32_t smem_base = smem_u32(smem);

    float acc[4][4][4];
#pragma unroll
    for (int mi = 0; mi < 4; mi++)
#pragma unroll
        for (int ni = 0; ni < 4; ni++)
#pragma unroll
            for (int c = 0; c < 4; c++) acc[mi][ni][c] = 0.0f;

    const int nK = K >> 5;

    auto load_stage = [&](int s, int kb) {
        const int k0 = kb * 32;
#pragma unroll
        for (int i = 0; i < 8; i++) {
            int idx = i * 256 + tid;
            int tile = idx >> 9;
            int rem = idx & 511;
            int row = rem >> 2;
            int seg = rem & 3;
            const __nv_bfloat16* gp = srcs[tile] + (size_t)row * K + k0 + seg * 8;
            uint32_t sa = smem_base +
                (uint32_t)(s * STAGE_E + tile * TILE_E + row * BKP + seg * 8) * 2;
            asm volatile("cp.async.ca.shared.global [%0], [%1], 16;"
                         :: "r"(sa), "l"(gp));
        }
    };

    load_stage(0, 0);
    asm volatile("cp.async.commit_group;");

    for (int kb = 0; kb < nK; kb++) {
        const int cur = kb & 1;
        if (kb + 1 < nK) {
            load_stage(cur ^ 1, kb + 1);
            asm volatile("cp.async.commit_group;");
            asm volatile("cp.async.wait_group 1;");
        } else {
            asm volatile("cp.async.wait_group 0;");
        }
        __syncthreads();

        const __nv_bfloat16* sAh = smem + cur * STAGE_E;
        const __nv_bfloat16* sAl = sAh + TILE_E;
        const __nv_bfloat16* sBh = sAh + 2 * TILE_E;
        const __nv_bfloat16* sBl = sAh + 3 * TILE_E;

#pragma unroll
        for (int ks = 0; ks < 32; ks += 16) {
            uint32_t ah[4][4], al[4][4], bh[4][2], bl[4][2];
#pragma unroll
            for (int mi = 0; mi < 4; mi++) {
                int r = m0 + mi * 16 + g;
                ah[mi][0] = *(const uint32_t*)&sAh[r * BKP + ks + t2];
                ah[mi][1] = *(const uint32_t*)&sAh[(r + 8) * BKP + ks + t2];
                ah[mi][2] = *(const uint32_t*)&sAh[r * BKP + ks + t2 + 8];
                ah[mi][3] = *(const uint32_t*)&sAh[(r + 8) * BKP + ks + t2 + 8];
                al[mi][0] = *(const uint32_t*)&sAl[r * BKP + ks + t2];
                al[mi][1] = *(const uint32_t*)&sAl[(r + 8) * BKP + ks + t2];
                al[mi][2] = *(const uint32_t*)&sAl[r * BKP + ks + t2 + 8];
                al[mi][3] = *(const uint32_t*)&sAl[(r + 8) * BKP + ks + t2 + 8];
            }
#pragma unroll
            for (int ni = 0; ni < 4; ni++) {
                int r = n0 + ni * 8 + g;
                bh[ni][0] = *(const uint32_t*)&sBh[r * BKP + ks + t2];
                bh[ni][1] = *(const uint32_t*)&sBh[r * BKP + ks + t2 + 8];
                bl[ni][0] = *(const uint32_t*)&sBl[r * BKP + ks + t2];
                bl[ni][1] = *(const uint32_t*)&sBl[r * BKP + ks + t2 + 8];
            }
#pragma unroll
            for (int mi = 0; mi < 4; mi++)
#pragma unroll
                for (int ni = 0; ni < 4; ni++) {
                    mma_bf16(acc[mi][ni], ah[mi], bh[ni]);
                    mma_bf16(acc[mi][ni], ah[mi], bl[ni]);
                    mma_bf16(acc[mi][ni], al[mi], bh[ni]);
                }
        }
        __syncthreads();
    }

#pragma unroll
    for (int mi = 0; mi < 4; mi++) {
#pragma unroll
        for (int ni = 0; ni < 4; ni++) {
            int row = bm + m0 + mi * 16 + g;
            int col = bn + n0 + ni * 8 + t2;
            *(float2*)&C[(size_t)row * N + col] =
                make_float2(acc[mi][ni][0], acc[mi][ni][1]);
            *(float2*)&C[(size_t)(row + 8) * N + col] =
                make_float2(acc[mi][ni][2], acc[mi][ni][3]);
        }
    }
}

// ================= RoPE + RMSNorm -> bf16 hi/lo Q,K,V =======================
__global__ void rope_norm_kernel(const float* __restrict__ qw,
                                 const float* __restrict__ kw) {
    const int h = blockIdx.x, t = blockIdx.y, b = blockIdx.z;
    const int hd = threadIdx.x;
    __shared__ float sq[128], sk[128];
    __shared__ float red[8];

    const size_t row = (size_t)(b * Tt + t) * (3 * Dd);
    float qv = g_qkv[row + h * HDd + hd];
    float kv = g_qkv[row + Dd + h * HDd + hd];
    float vv = g_qkv[row + 2 * Dd + h * HDd + hd];
    sq[hd] = qv;
    sk[hd] = kv;
    __syncthreads();

    const int j = hd & 63;
    const int ci = (b * Tt + t) * 64 + j;
    const float c = g_cos[ci], s = g_sin[ci];
    float rq, rk;
    if (hd < 64) {
        rq = sq[hd] * c - sq[hd + 64] * s;
        rk = sk[hd] * c - sk[hd + 64] * s;
    } else {
        rq = sq[hd] * c + sq[hd - 64] * s;
        rk = sk[hd] * c + sk[hd - 64] * s;
    }
    float s2q = rq * rq, s2k = rk * rk;
#pragma unroll
    for (int m = 16; m >= 1; m >>= 1) {
        s2q += __shfl_xor_sync(0xffffffffu, s2q, m);
        s2k += __shfl_xor_sync(0xffffffffu, s2k, m);
    }
    const int w = hd >> 5;
    if ((hd & 31) == 0) { red[w] = s2q; red[4 + w] = s2k; }
    __syncthreads();
    float sumq = red[0] + red[1] + red[2] + red[3];
    float sumk = red[4] + red[5] + red[6] + red[7];
    float iq = rsqrtf(sumq * (1.0f / 128.0f) + 1e-6f);
    float ik = rsqrtf(sumk * (1.0f / 128.0f) + 1e-6f);

    const float qsc = 0.08838834764831845f;
    float qf = rq * iq * qw[hd] * qsc;
    float kf = rk * ik * kw[hd];

    const size_t o = (size_t)((b * Hh + h) * Tt + t) * HDd + hd;
    __nv_bfloat16 qh = __float2bfloat16(qf);
    __nv_bfloat16 kh = __float2bfloat16(kf);
    __nv_bfloat16 vh = __float2bfloat16(vv);
    g_qh[o] = qh;
    g_ql[o] = __float2bfloat16(qf - __bfloat162float(qh));
    g_kh[o] = kh;
    g_kl[o] = __float2bfloat16(kf - __bfloat162float(kh));
    g_vh[o] = vh;
    g_vl[o] = __float2bfloat16(vv - __bfloat162float(vh));
}

// ================= Tensor-core flash attention (causal, bf16x3) =============
// grid (T/128, H, B), 256 threads (8 warps x 16 q-rows). Single-buffered.
#define AP 136          // Q/K row pitch (elems)
#define PP 72           // P / Vt row pitch (elems)
#define Q_E (128 * AP)
#define K_E (64 * AP)
#define VT_E (128 * PP)
#define P_E (128 * PP)
#define OFF_QH 0
#define OFF_QL (Q_E)
#define OFF_KH (2 * Q_E)
#define OFF_KL (2 * Q_E + K_E)
#define OFF_VTH (2 * Q_E + 2 * K_E)
#define OFF_VTL (2 * Q_E + 2 * K_E + VT_E)
#define OFF_PH (2 * Q_E + 2 * K_E + 2 * VT_E)
#define OFF_PL (2 * Q_E + 2 * K_E + 2 * VT_E + P_E)
#define ATTN_SMEM ((2 * Q_E + 2 * K_E + 2 * VT_E + 2 * P_E) * 2)  // 178176 B

__global__ __launch_bounds__(256, 1) void attn_mma_kernel() {
    extern __shared__ __align__(128) __nv_bfloat16 sma[];
    const int tid = threadIdx.x;
    const int lane = tid & 31;
    const int w = tid >> 5;
    const int g = lane >> 2;
    const int t2 = (lane & 3) * 2;
    const int qb = blockIdx.x, h = blockIdx.y, b = blockIdx.z;
    const int qg0 = qb * 128;
    const size_t hb = (size_t)(b * Hh + h) * Tt * HDd;
    const uint32_t sbase = smem_u32(sma);

    // ---- load Q hi/lo tiles: 2 arrays x 128 rows x 16 segs = 4096 uint4 ----
    {
        const __nv_bfloat16* qs[2] = {g_qh + hb + (size_t)qg0 * HDd,
                                      g_ql + hb + (size_t)qg0 * HDd};
#pragma unroll
        for (int i = 0; i < 16; i++) {
            int idx = tid + i * 256;          // 0..4095
            int arr = idx >> 11;              // 0..1
            int rem = idx & 2047;
            int row = rem >> 4;               // 0..127
            int seg = rem & 15;               // 0..15
            uint4 v = *(const uint4*)(qs[arr] + (size_t)row * HDd + seg * 8);
            *(uint4*)(sma + arr * Q_E + row * AP + seg * 8) = v;
        }
    }

    float o[16][4];
#pragma unroll
    for (int ni = 0; ni < 16; ni++)
#pragma unroll
        for (int c = 0; c < 4; c++) o[ni][c] = 0.0f;
    float m_run[2] = {-1e30f, -1e30f}, l_run[2] = {0.0f, 0.0f};

    const int nkb = 2 * qb + 2;
    const int qwr = qg0 + w * 16;

    for (int kb = 0; kb < nkb; kb++) {
        const int kg0 = kb * 64;
        __syncthreads();   // (a) previous tile's compute done

        // ---- load K hi/lo: 2 arrays x 64 rows x 16 segs = 2048 uint4 ----
#pragma unroll
        for (int i = 0; i < 8; i++) {
            int idx = tid + i * 256;          // 0..2047
            int arr = idx >> 10;              // 0..1
            int rem = idx & 1023;
            int row = rem >> 4;               // 0..63
            int seg = rem & 15;               // 0..15
            const __nv_bfloat16* gp = (arr ? g_kl : g_kh) + hb +
                                      (size_t)(kg0 + row) * HDd + seg * 8;
            uint32_t sa = sbase + (uint32_t)((arr ? OFF_KL : OFF_KH) +
                                             row * AP + seg * 8) * 2;
            asm volatile("cp.async.ca.shared.global [%0], [%1], 16;"
                         :: "r"(sa), "l"(gp));
        }
        asm volatile("cp.async.commit_group;");

        // ---- load V hi/lo transposed: sVt[d][key] (2 x 16 dsegs x 64 keys) --
#pragma unroll
        for (int i = 0; i < 8; i++) {
            int idx = tid + i * 256;          // 0..2047
            int arr = idx >> 10, rem = idx & 1023;
            int dseg = rem >> 6, key = rem & 63;
            const __nv_bfloat16* gp = (arr ? g_vl : g_vh) + hb +
                                      (size_t)(kg0 + key) * HDd + dseg * 8;
            uint4 v = *(const uint4*)gp;
            const __nv_bfloat16* pv = (const __nv_bfloat16*)&v;
            __nv_bfloat16* dst = sma + (arr ? OFF_VTL : OFF_VTH);
#pragma unroll
            for (int j = 0; j < 8; j++)
                dst[(dseg * 8 + j) * PP + key] = pv[j];
        }
        asm volatile("cp.async.wait_group 0;");
        __syncthreads();   // (b) K, V visible (Q too on first pass)

        const bool active = (kg0 <= qwr + 15);
        if (active) {
            const __nv_bfloat16* sQh = sma + OFF_QH;
            const __nv_bfloat16* sQl = sma + OFF_QL;
            const __nv_bfloat16* sKh = sma + OFF_KH;
            const __nv_bfloat16* sKl = sma + OFF_KL;

            // ---- S = Q K^T (bf16x3) ----
            float s[8][4];
#pragma unroll
            for (int ni = 0; ni < 8; ni++)
#pragma unroll
                for (int c = 0; c < 4; c++) s[ni][c] = 0.0f;

#pragma unroll
            for (int kc = 0; kc < 8; kc++) {
                const int col = kc * 16 + t2;
                const int r0 = w * 16 + g;
                uint32_t ah[4], al[4];
                ah[0] = *(const uint32_t*)&sQh[r0 * AP + col];
                ah[1] = *(const uint32_t*)&sQh[(r0 + 8) * AP + col];
                ah[2] = *(const uint32_t*)&sQh[r0 * AP + col + 8];
                ah[3] = *(const uint32_t*)&sQh[(r0 + 8) * AP + col + 8];
                al[0] = *(const uint32_t*)&sQl[r0 * AP + col];
                al[1] = *(const uint32_t*)&sQl[(r0 + 8) * AP + col];
                al[2] = *(const uint32_t*)&sQl[r0 * AP + col + 8];
                al[3] = *(const uint32_t*)&sQl[(r0 + 8) * AP + col + 8];
#pragma unroll
                for (int ni = 0; ni < 8; ni++) {
                    const int kr = ni * 8 + g;
                    uint32_t bh[2], bl[2];
                    bh[0] = *(const uint32_t*)&sKh[kr * AP + col];
                    bh[1] = *(const uint32_t*)&sKh[kr * AP + col + 8];
                    bl[0] = *(const uint32_t*)&sKl[kr * AP + col];
                    bl[1] = *(const uint32_t*)&sKl[kr * AP + col + 8];
                    mma_bf16(s[ni], ah, bh);
                    mma_bf16(s[ni], ah, bl);
                    mma_bf16(s[ni], al, bh);
                }
            }

            // ---- causal mask ----
            if (kg0 + 63 > qwr) {
#pragma unroll
                for (int ni = 0; ni < 8; ni++)
#pragma unroll
                    for (int c = 0; c < 4; c++) {
                        int key = kg0 + ni * 8 + t2 + (c & 1);
                        int qr = qwr + g + ((c & 2) ? 8 : 0);
                        if (key > qr) s[ni][c] = -1e30f;
                    }
            }

            // ---- online softmax; store P hi/lo to smem (A-layout) ----
            __nv_bfloat16* sPh = sma + OFF_PH;
            __nv_bfloat16* sPl = sma + OFF_PL;
#pragma unroll
            for (int r = 0; r < 2; r++) {
                float mt = -1e30f;
#pragma unroll
                for (int ni = 0; ni < 8; ni++)
                    mt = fmaxf(mt, fmaxf(s[ni][2 * r], s[ni][2 * r + 1]));
                mt = fmaxf(mt, __shfl_xor_sync(0xffffffffu, mt, 1));
                mt = fmaxf(mt, __shfl_xor_sync(0xffffffffu, mt, 2));
                float mnew = fmaxf(m_run[r], mt);
                float corr = __expf(m_run[r] - mnew);
                m_run[r] = mnew;
                float psum = 0.0f;
                const int prow = w * 16 + g + r * 8;
#pragma unroll
                for (int ni = 0; ni < 8; ni++) {
                    float p0 = __expf(s[ni][2 * r] - mnew);
                    float p1 = __expf(s[ni][2 * r + 1] - mnew);
                    psum += p0 + p1;
                    __nv_bfloat162 h2 = __floats2bfloat162_rn(p0, p1);
                    float l0 = p0 - __bfloat162float(h2.x);
                    float l1 = p1 - __bfloat162float(h2.y);
                    __nv_bfloat162 l2 = __floats2bfloat162_rn(l0, l1);
                    *(uint32_t*)&sPh[prow * PP + ni * 8 + t2] = *(uint32_t*)&h2;
                    *(uint32_t*)&sPl[prow * PP + ni * 8 + t2] = *(uint32_t*)&l2;
                }
                psum += __shfl_xor_sync(0xffffffffu, psum, 1);
                psum += __shfl_xor_sync(0xffffffffu, psum, 2);
                l_run[r] = l_run[r] * corr + psum;
#pragma unroll
                for (int ni = 0; ni < 16; ni++) {
                    o[ni][2 * r] *= corr;
                    o[ni][2 * r + 1] *= corr;
                }
            }
        }
        __syncthreads();   // (c) P visible

        if (active) {
            const __nv_bfloat16* sPh = sma + OFF_PH;
            const __nv_bfloat16* sPl = sma + OFF_PL;
            const __nv_bfloat16* sVth = sma + OFF_VTH;
            const __nv_bfloat16* sVtl = sma + OFF_VTL;

            // ---- O += P Vt^T (bf16x3), gemm-style fragments ----
#pragma unroll
            for (int kc = 0; kc < 4; kc++) {
                const int col = kc * 16 + t2;
                const int pr = w * 16 + g;
                uint32_t ah[4], al[4];
                ah[0] = *(const uint32_t*)&sPh[pr * PP + col];
                ah[1] = *(const uint32_t*)&sPh[(pr + 8) * PP + col];
                ah[2] = *(const uint32_t*)&sPh[pr * PP + col + 8];
                ah[3] = *(const uint32_t*)&sPh[(pr + 8) * PP + col + 8];
                al[0] = *(const uint32_t*)&sPl[pr * PP + col];
                al[1] = *(const uint32_t*)&sPl[(pr + 8) * PP + col];
                al[2] = *(const uint32_t*)&sPl[pr * PP + col + 8];
                al[3] = *(const uint32_t*)&sPl[(pr + 8) * PP + col + 8];
#pragma unroll
                for (int ni = 0; ni < 16; ni++) {
                    const int vr = ni * 8 + g;
                    uint32_t bh[2], bl[2];
                    bh[0] = *(const uint32_t*)&sVth[vr * PP + col];
                    bh[1] = *(const uint32_t*)&sVth[vr * PP + col + 8];
                    bl[0] = *(const uint32_t*)&sVtl[vr * PP + col];
                    bl[1] = *(const uint32_t*)&sVtl[vr * PP + col + 8];
                    mma_bf16(o[ni], ah, bh);
                    mma_bf16(o[ni], ah, bl);
                    mma_bf16(o[ni], al, bh);
                }
            }
        }
    }

    // ---- epilogue: normalize, split hi/lo, write [B,T,D] ----
#pragma unroll
    for (int r = 0; r < 2; r++) {
        float inv = 1.0f / l_run[r];
        int t = qg0 + w * 16 + g + r * 8;
        size_t rowo = (size_t)(b * Tt + t) * Dd + h * HDd;
#pragma unroll
        for (int ni = 0; ni < 16; ni++) {
            float v0 = o[ni][2 * r] * inv;
            float v1 = o[ni][2 * r + 1] * inv;
            __nv_bfloat162 h2 = __floats2bfloat162_rn(v0, v1);
            float l0 = v0 - __bfloat162float(h2.x);
            float l1 = v1 - __bfloat162float(h2.y);
            __nv_bfloat162 l2 = __floats2bfloat162_rn(l0, l1);
            *(uint32_t*)&g_aoh[rowo + ni * 8 + t2] = *(uint32_t*)&h2;
            *(uint32_t*)&g_aol[rowo + ni * 8 + t2] = *(uint32_t*)&l2;
        }
    }
}

// ================= launch ===================================================
extern "C" void kernel_launch(void* const* d_in, const int* in_sizes, int n_in,
                              void* d_out, int out_size) {
    const float* x = (const float*)d_in[0];
    const int* positions = (const int*)d_in[2];
    const float* qkv_w = (const float*)d_in[3];
    const float* out_w = (const float*)d_in[4];
    const float* q_norm_w = (const float*)d_in[5];
    const float* k_norm_w = (const float*)d_in[6];
    float* out = (float*)d_out;
    (void)in_sizes; (void)n_in; (void)out_size;

    void *p_qkv, *p_xh, *p_xl, *p_aoh, *p_aol, *p_wqh, *p_wql, *p_woh, *p_wol;
    cudaGetSymbolAddress(&p_qkv, g_qkv);
    cudaGetSymbolAddress(&p_xh, g_xh);
    cudaGetSymbolAddress(&p_xl, g_xl);
    cudaGetSymbolAddress(&p_aoh, g_aoh);
    cudaGetSymbolAddress(&p_aol, g_aol);
    cudaGetSymbolAddress(&p_wqh, g_wqh);
    cudaGetSymbolAddress(&p_wql, g_wql);
    cudaGetSymbolAddress(&p_woh, g_woh);
    cudaGetSymbolAddress(&p_wol, g_wol);

    static int attr_set = 0;
    if (!attr_set) {
        cudaFuncSetAttribute(gemm_mma_kernel, cudaFuncAttributeMaxDynamicSharedMemorySize, GEMM_SMEM);
        cudaFuncSetAttribute(attn_mma_kernel, cudaFuncAttributeMaxDynamicSharedMemorySize, ATTN_SMEM);
        attr_set = 1;
    }

    const int M = Bb * Tt;

    rope_table_kernel<<<(Bb * Tt * 64 + 255) / 256, 256>>>(positions);
    convert_split_kernel<<<(M * Dd / 4 + 255) / 256, 256>>>(
        x, (__nv_bfloat16*)p_xh, (__nv_bfloat16*)p_xl, M * Dd / 4);
    transpose_split_kernel<<<dim3(3 * Dd / 32, Dd / 32, 2), dim3(32, 8)>>>(qkv_w, out_w);
    gemm_mma_kernel<<<dim3(3 * Dd / 128, M / 128), 256, GEMM_SMEM>>>(
        (const __nv_bfloat16*)p_xh, (const __nv_bfloat16*)p_xl,
        (const __nv_bfloat16*)p_wqh, (const __nv_bfloat16*)p_wql,
        (float*)p_qkv, M, 3 * Dd, Dd);
    rope_norm_kernel<<<dim3(Hh, Tt, Bb), 128>>>(q_norm_w, k_norm_w);
    attn_mma_kernel<<<dim3(Tt / 128, Hh, Bb), 256, ATTN_SMEM>>>();
    gemm_mma_kernel<<<dim3(Dd / 128, M / 128), 256, GEMM_SMEM>>>(
        (const __nv_bfloat16*)p_aoh, (const __nv_bfloat16*)p_aol,
        (const __nv_bfloat16*)p_woh, (const __nv_bfloat16*)p_wol,
        out, M, Dd, Dd);
}

// round 8
// speedup vs baseline: 2.6424x; 1.0478x over previous
#include <cuda_runtime.h>
#include <cuda_bf16.h>
#include <math.h>
#include <stdint.h>

#define Bb 2
#define Tt 2048
#define Dd 2048
#define Hh 16
#define HDd 128

// ================= scratch ==================================================
__device__ float g_qkv[(size_t)Bb * Tt * 3 * Dd];
__device__ float g_cos[(size_t)Bb * Tt * 64];
__device__ float g_sin[(size_t)Bb * Tt * 64];
__device__ __nv_bfloat16 g_xh[(size_t)Bb * Tt * Dd];
__device__ __nv_bfloat16 g_xl[(size_t)Bb * Tt * Dd];
__device__ __nv_bfloat16 g_aoh[(size_t)Bb * Tt * Dd];
__device__ __nv_bfloat16 g_aol[(size_t)Bb * Tt * Dd];
__device__ __nv_bfloat16 g_wqh[(size_t)3 * Dd * Dd];
__device__ __nv_bfloat16 g_wql[(size_t)3 * Dd * Dd];
__device__ __nv_bfloat16 g_woh[(size_t)Dd * Dd];
__device__ __nv_bfloat16 g_wol[(size_t)Dd * Dd];
__device__ __nv_bfloat16 g_qh[(size_t)Bb * Hh * Tt * HDd];
__device__ __nv_bfloat16 g_ql[(size_t)Bb * Hh * Tt * HDd];
__device__ __nv_bfloat16 g_kh[(size_t)Bb * Hh * Tt * HDd];
__device__ __nv_bfloat16 g_kl[(size_t)Bb * Hh * Tt * HDd];
__device__ __nv_bfloat16 g_vh[(size_t)Bb * Hh * Tt * HDd];
__device__ __nv_bfloat16 g_vl[(size_t)Bb * Hh * Tt * HDd];

__device__ __forceinline__ uint32_t smem_u32(const void* p) {
    uint32_t a;
    asm("{ .reg .u64 t; cvta.to.shared.u64 t, %1; cvt.u32.u64 %0, t; }" : "=r"(a) : "l"(p));
    return a;
}

// ================= RoPE table ==============================================
__global__ void rope_table_kernel(const int* __restrict__ positions) {
    int idx = blockIdx.x * blockDim.x + threadIdx.x;
    if (idx >= Bb * Tt * 64) return;
    int j = idx & 63;
    int bt = idx >> 6;
    int pos = positions[bt];
    float inv_freq = exp2f(-(float)j * (13.287712379549449f / 64.0f));
    float ang = (float)pos * inv_freq;
    double da = (double)ang;
    g_cos[idx] = (float)cos(da);
    g_sin[idx] = (float)sin(da);
}

// ================= split-convert (elementwise) ==============================
__global__ void convert_split_kernel(const float* __restrict__ in,
                                     __nv_bfloat16* __restrict__ oh,
                                     __nv_bfloat16* __restrict__ ol, int n4) {
    int i = blockIdx.x * blockDim.x + threadIdx.x;
    if (i >= n4) return;
    float4 v = ((const float4*)in)[i];
    __nv_bfloat16 hx = __float2bfloat16(v.x);
    __nv_bfloat16 hy = __float2bfloat16(v.y);
    __nv_bfloat16 hz = __float2bfloat16(v.z);
    __nv_bfloat16 hw = __float2bfloat16(v.w);
    __nv_bfloat16 lx = __float2bfloat16(v.x - __bfloat162float(hx));
    __nv_bfloat16 ly = __float2bfloat16(v.y - __bfloat162float(hy));
    __nv_bfloat16 lz = __float2bfloat16(v.z - __bfloat162float(hz));
    __nv_bfloat16 lw = __float2bfloat16(v.w - __bfloat162float(hw));
    ((__nv_bfloat162*)oh)[2 * i + 0] = __nv_bfloat162(hx, hy);
    ((__nv_bfloat162*)oh)[2 * i + 1] = __nv_bfloat162(hz, hw);
    ((__nv_bfloat162*)ol)[2 * i + 0] = __nv_bfloat162(lx, ly);
    ((__nv_bfloat162*)ol)[2 * i + 1] = __nv_bfloat162(lz, lw);
}

// ================= transpose + split convert (both weights) =================
__global__ void transpose_split_kernel(const float* __restrict__ W0,
                                       const float* __restrict__ W1) {
    __shared__ float t[32][33];
    int z = blockIdx.z;
    int Ncols = z ? Dd : 3 * Dd;
    const float* W = z ? W1 : W0;
    __nv_bfloat16* Th = z ? g_woh : g_wqh;
    __nv_bfloat16* Tl = z ? g_wol : g_wql;
    int n0 = blockIdx.x * 32, k0 = blockIdx.y * 32;
    if (n0 >= Ncols) return;
    int tx = threadIdx.x, ty = threadIdx.y;
#pragma unroll
    for (int i = ty; i < 32; i += 8)
        t[i][tx] = W[(size_t)(k0 + i) * Ncols + n0 + tx];
    __syncthreads();
#pragma unroll
    for (int i = ty; i < 32; i += 8) {
        float v = t[tx][i];
        __nv_bfloat16 h = __float2bfloat16(v);
        __nv_bfloat16 l = __float2bfloat16(v - __bfloat162float(h));
        size_t o = (size_t)(n0 + i) * Dd + k0 + tx;
        Th[o] = h;
        Tl[o] = l;
    }
}

// ================= mma.sync bf16x3 GEMM =====================================
// Tile 128x128, BK=32, 8 warps (2x4), warp tile 64x32. 2 CTAs/SM target.
#define BKP 40
#define TILE_E (128 * BKP)
#define STAGE_E (4 * TILE_E)
#define GEMM_SMEM (2 * STAGE_E * 2)

__device__ __forceinline__ void mma_bf16(float* d, const uint32_t* a, const uint32_t* b) {
    asm volatile(
        "mma.sync.aligned.m16n8k16.row.col.f32.bf16.bf16.f32 "
        "{%0,%1,%2,%3}, {%4,%5,%6,%7}, {%8,%9}, {%0,%1,%2,%3};"
        : "+f"(d[0]), "+f"(d[1]), "+f"(d[2]), "+f"(d[3])
        : "r"(a[0]), "r"(a[1]), "r"(a[2]), "r"(a[3]), "r"(b[0]), "r"(b[1]));
}

__global__ __launch_bounds__(256, 2) void gemm_mma_kernel(
    const __nv_bfloat16* __restrict__ Ah, const __nv_bfloat16* __restrict__ Al,
    const __nv_bfloat16* __restrict__ Bh, const __nv_bfloat16* __restrict__ Bl,
    float* __restrict__ C, int M, int N, int K) {
    extern __shared__ __align__(128) __nv_bfloat16 smem[];
    const int tid = threadIdx.x;
    const int lane = tid & 31;
    const int wid = tid >> 5;
    const int g = lane >> 2;
    const int t2 = (lane & 3) * 2;
    const int wm = wid & 1, wn = wid >> 1;
    const int m0 = wm * 64, n0 = wn * 32;
    const int bm = blockIdx.y * 128;
    const int bn = blockIdx.x * 128;

    const __nv_bfloat16* srcs[4] = {Ah + (size_t)bm * K, Al + (size_t)bm * K,
                                    Bh + (size_t)bn * K, Bl + (size_t)bn * K};

    uint32_t smem_base = smem_u32(smem);

    float acc[4][4][4];
#pragma unroll
    for (int mi = 0; mi < 4; mi++)
#pragma unroll
        for (int ni = 0; ni < 4; ni++)
#pragma unroll
            for (int c = 0; c < 4; c++) acc[mi][ni][c] = 0.0f;

    const int nK = K >> 5;

    auto load_stage = [&](int s, int kb) {
        const int k0 = kb * 32;
#pragma unroll
        for (int i = 0; i < 8; i++) {
            int idx = i * 256 + tid;
            int tile = idx >> 9;
            int rem = idx & 511;
            int row = rem >> 2;
            int seg = rem & 3;
            const __nv_bfloat16* gp = srcs[tile] + (size_t)row * K + k0 + seg * 8;
            uint32_t sa = smem_base +
                (uint32_t)(s * STAGE_E + tile * TILE_E + row * BKP + seg * 8) * 2;
            asm volatile("cp.async.ca.shared.global [%0], [%1], 16;"
                         :: "r"(sa), "l"(gp));
        }
    };

    load_stage(0, 0);
    asm volatile("cp.async.commit_group;");

    for (int kb = 0; kb < nK; kb++) {
        const int cur = kb & 1;
        if (kb + 1 < nK) {
            load_stage(cur ^ 1, kb + 1);
            asm volatile("cp.async.commit_group;");
            asm volatile("cp.async.wait_group 1;");
        } else {
            asm volatile("cp.async.wait_group 0;");
        }
        __syncthreads();

        const __nv_bfloat16* sAh = smem + cur * STAGE_E;
        const __nv_bfloat16* sAl = sAh + TILE_E;
        const __nv_bfloat16* sBh = sAh + 2 * TILE_E;
        const __nv_bfloat16* sBl = sAh + 3 * TILE_E;

#pragma unroll
        for (int ks = 0; ks < 32; ks += 16) {
            // B fragments for all 4 ni (16 regs), held across the mi loop
            uint32_t bh[4][2], bl[4][2];
#pragma unroll
            for (int ni = 0; ni < 4; ni++) {
                int r = n0 + ni * 8 + g;
                bh[ni][0] = *(const uint32_t*)&sBh[r * BKP + ks + t2];
                bh[ni][1] = *(const uint32_t*)&sBh[r * BKP + ks + t2 + 8];
                bl[ni][0] = *(const uint32_t*)&sBl[r * BKP + ks + t2];
                bl[ni][1] = *(const uint32_t*)&sBl[r * BKP + ks + t2 + 8];
            }
            // A fragments streamed per-mi (8 regs live at a time)
#pragma unroll
            for (int mi = 0; mi < 4; mi++) {
                int r = m0 + mi * 16 + g;
                uint32_t ah[4], al[4];
                ah[0] = *(const uint32_t*)&sAh[r * BKP + ks + t2];
                ah[1] = *(const uint32_t*)&sAh[(r + 8) * BKP + ks + t2];
                ah[2] = *(const uint32_t*)&sAh[r * BKP + ks + t2 + 8];
                ah[3] = *(const uint32_t*)&sAh[(r + 8) * BKP + ks + t2 + 8];
                al[0] = *(const uint32_t*)&sAl[r * BKP + ks + t2];
                al[1] = *(const uint32_t*)&sAl[(r + 8) * BKP + ks + t2];
                al[2] = *(const uint32_t*)&sAl[r * BKP + ks + t2 + 8];
                al[3] = *(const uint32_t*)&sAl[(r + 8) * BKP + ks + t2 + 8];
#pragma unroll
                for (int ni = 0; ni < 4; ni++) {
                    mma_bf16(acc[mi][ni], ah, bh[ni]);
                    mma_bf16(acc[mi][ni], ah, bl[ni]);
                    mma_bf16(acc[mi][ni], al, bh[ni]);
                }
            }
        }
        __syncthreads();
    }

#pragma unroll
    for (int mi = 0; mi < 4; mi++) {
#pragma unroll
        for (int ni = 0; ni < 4; ni++) {
            int row = bm + m0 + mi * 16 + g;
            int col = bn + n0 + ni * 8 + t2;
            *(float2*)&C[(size_t)row * N + col] =
                make_float2(acc[mi][ni][0], acc[mi][ni][1]);
            *(float2*)&C[(size_t)(row + 8) * N + col] =
                make_float2(acc[mi][ni][2], acc[mi][ni][3]);
        }
    }
}

// ================= RoPE + RMSNorm -> bf16 hi/lo Q,K,V =======================
__global__ void rope_norm_kernel(const float* __restrict__ qw,
                                 const float* __restrict__ kw) {
    const int h = blockIdx.x, t = blockIdx.y, b = blockIdx.z;
    const int hd = threadIdx.x;
    __shared__ float sq[128], sk[128];
    __shared__ float red[8];

    const size_t row = (size_t)(b * Tt + t) * (3 * Dd);
    float qv = g_qkv[row + h * HDd + hd];
    float kv = g_qkv[row + Dd + h * HDd + hd];
    float vv = g_qkv[row + 2 * Dd + h * HDd + hd];
    sq[hd] = qv;
    sk[hd] = kv;
    __syncthreads();

    const int j = hd & 63;
    const int ci = (b * Tt + t) * 64 + j;
    const float c = g_cos[ci], s = g_sin[ci];
    float rq, rk;
    if (hd < 64) {
        rq = sq[hd] * c - sq[hd + 64] * s;
        rk = sk[hd] * c - sk[hd + 64] * s;
    } else {
        rq = sq[hd] * c + sq[hd - 64] * s;
        rk = sk[hd] * c + sk[hd - 64] * s;
    }
    float s2q = rq * rq, s2k = rk * rk;
#pragma unroll
    for (int m = 16; m >= 1; m >>= 1) {
        s2q += __shfl_xor_sync(0xffffffffu, s2q, m);
        s2k += __shfl_xor_sync(0xffffffffu, s2k, m);
    }
    const int w = hd >> 5;
    if ((hd & 31) == 0) { red[w] = s2q; red[4 + w] = s2k; }
    __syncthreads();
    float sumq = red[0] + red[1] + red[2] + red[3];
    float sumk = red[4] + red[5] + red[6] + red[7];
    float iq = rsqrtf(sumq * (1.0f / 128.0f) + 1e-6f);
    float ik = rsqrtf(sumk * (1.0f / 128.0f) + 1e-6f);

    const float qsc = 0.08838834764831845f;
    float qf = rq * iq * qw[hd] * qsc;
    float kf = rk * ik * kw[hd];

    const size_t o = (size_t)((b * Hh + h) * Tt + t) * HDd + hd;
    __nv_bfloat16 qh = __float2bfloat16(qf);
    __nv_bfloat16 kh = __float2bfloat16(kf);
    __nv_bfloat16 vh = __float2bfloat16(vv);
    g_qh[o] = qh;
    g_ql[o] = __float2bfloat16(qf - __bfloat162float(qh));
    g_kh[o] = kh;
    g_kl[o] = __float2bfloat16(kf - __bfloat162float(kh));
    g_vh[o] = vh;
    g_vl[o] = __float2bfloat16(vv - __bfloat162float(vh));
}

// ================= Tensor-core flash attention (causal, bf16x3) =============
// grid (T/128, H, B), 256 threads (8 warps x 16 q-rows). Single-buffered.
#define AP 136
#define PP 72
#define Q_E (128 * AP)
#define K_E (64 * AP)
#define VT_E (128 * PP)
#define P_E (128 * PP)
#define OFF_QH 0
#define OFF_QL (Q_E)
#define OFF_KH (2 * Q_E)
#define OFF_KL (2 * Q_E + K_E)
#define OFF_VTH (2 * Q_E + 2 * K_E)
#define OFF_VTL (2 * Q_E + 2 * K_E + VT_E)
#define OFF_PH (2 * Q_E + 2 * K_E + 2 * VT_E)
#define OFF_PL (2 * Q_E + 2 * K_E + 2 * VT_E + P_E)
#define ATTN_SMEM ((2 * Q_E + 2 * K_E + 2 * VT_E + 2 * P_E) * 2)  // 178176 B

__global__ __launch_bounds__(256, 1) void attn_mma_kernel() {
    extern __shared__ __align__(128) __nv_bfloat16 sma[];
    const int tid = threadIdx.x;
    const int lane = tid & 31;
    const int w = tid >> 5;
    const int g = lane >> 2;
    const int t2 = (lane & 3) * 2;
    const int qb = blockIdx.x, h = blockIdx.y, b = blockIdx.z;
    const int qg0 = qb * 128;
    const size_t hb = (size_t)(b * Hh + h) * Tt * HDd;
    const uint32_t sbase = smem_u32(sma);

    // ---- load Q hi/lo tiles: 2 arrays x 128 rows x 16 segs ----
    {
        const __nv_bfloat16* qs[2] = {g_qh + hb + (size_t)qg0 * HDd,
                                      g_ql + hb + (size_t)qg0 * HDd};
#pragma unroll
        for (int i = 0; i < 16; i++) {
            int idx = tid + i * 256;
            int arr = idx >> 11;
            int rem = idx & 2047;
            int row = rem >> 4;
            int seg = rem & 15;
            uint4 v = *(const uint4*)(qs[arr] + (size_t)row * HDd + seg * 8);
            *(uint4*)(sma + arr * Q_E + row * AP + seg * 8) = v;
        }
    }

    float o[16][4];
#pragma unroll
    for (int ni = 0; ni < 16; ni++)
#pragma unroll
        for (int c = 0; c < 4; c++) o[ni][c] = 0.0f;
    float m_run[2] = {-1e30f, -1e30f}, l_run[2] = {0.0f, 0.0f};

    const int nkb = 2 * qb + 2;
    const int qwr = qg0 + w * 16;

    for (int kb = 0; kb < nkb; kb++) {
        const int kg0 = kb * 64;
        __syncthreads();   // (a)

        // ---- load K hi/lo: 2 x 64 rows x 16 segs ----
#pragma unroll
        for (int i = 0; i < 8; i++) {
            int idx = tid + i * 256;
            int arr = idx >> 10;
            int rem = idx & 1023;
            int row = rem >> 4;
            int seg = rem & 15;
            const __nv_bfloat16* gp = (arr ? g_kl : g_kh) + hb +
                                      (size_t)(kg0 + row) * HDd + seg * 8;
            uint32_t sa = sbase + (uint32_t)((arr ? OFF_KL : OFF_KH) +
                                             row * AP + seg * 8) * 2;
            asm volatile("cp.async.ca.shared.global [%0], [%1], 16;"
                         :: "r"(sa), "l"(gp));
        }
        asm volatile("cp.async.commit_group;");

        // ---- load V hi/lo transposed: sVt[d][key] ----
#pragma unroll
        for (int i = 0; i < 8; i++) {
            int idx = tid + i * 256;
            int arr = idx >> 10, rem = idx & 1023;
            int dseg = rem >> 6, key = rem & 63;
            const __nv_bfloat16* gp = (arr ? g_vl : g_vh) + hb +
                                      (size_t)(kg0 + key) * HDd + dseg * 8;
            uint4 v = *(const uint4*)gp;
            const __nv_bfloat16* pv = (const __nv_bfloat16*)&v;
            __nv_bfloat16* dst = sma + (arr ? OFF_VTL : OFF_VTH);
#pragma unroll
            for (int j = 0; j < 8; j++)
                dst[(dseg * 8 + j) * PP + key] = pv[j];
        }
        asm volatile("cp.async.wait_group 0;");
        __syncthreads();   // (b)

        const bool active = (kg0 <= qwr + 15);
        if (active) {
            const __nv_bfloat16* sQh = sma + OFF_QH;
            const __nv_bfloat16* sQl = sma + OFF_QL;
            const __nv_bfloat16* sKh = sma + OFF_KH;
            const __nv_bfloat16* sKl = sma + OFF_KL;

            float s[8][4];
#pragma unroll
            for (int ni = 0; ni < 8; ni++)
#pragma unroll
                for (int c = 0; c < 4; c++) s[ni][c] = 0.0f;

#pragma unroll
            for (int kc = 0; kc < 8; kc++) {
                const int col = kc * 16 + t2;
                const int r0 = w * 16 + g;
                uint32_t ah[4], al[4];
                ah[0] = *(const uint32_t*)&sQh[r0 * AP + col];
                ah[1] = *(const uint32_t*)&sQh[(r0 + 8) * AP + col];
                ah[2] = *(const uint32_t*)&sQh[r0 * AP + col + 8];
                ah[3] = *(const uint32_t*)&sQh[(r0 + 8) * AP + col + 8];
                al[0] = *(const uint32_t*)&sQl[r0 * AP + col];
                al[1] = *(const uint32_t*)&sQl[(r0 + 8) * AP + col];
                al[2] = *(const uint32_t*)&sQl[r0 * AP + col + 8];
                al[3] = *(const uint32_t*)&sQl[(r0 + 8) * AP + col + 8];
#pragma unroll
                for (int ni = 0; ni < 8; ni++) {
                    const int kr = ni * 8 + g;
                    uint32_t bh[2], bl[2];
                    bh[0] = *(const uint32_t*)&sKh[kr * AP + col];
                    bh[1] = *(const uint32_t*)&sKh[kr * AP + col + 8];
                    bl[0] = *(const uint32_t*)&sKl[kr * AP + col];
                    bl[1] = *(const uint32_t*)&sKl[kr * AP + col + 8];
                    mma_bf16(s[ni], ah, bh);
                    mma_bf16(s[ni], ah, bl);
                    mma_bf16(s[ni], al, bh);
                }
            }

            if (kg0 + 63 > qwr) {
#pragma unroll
                for (int ni = 0; ni < 8; ni++)
#pragma unroll
                    for (int c = 0; c < 4; c++) {
                        int key = kg0 + ni * 8 + t2 + (c & 1);
                        int qr = qwr + g + ((c & 2) ? 8 : 0);
                        if (key > qr) s[ni][c] = -1e30f;
                    }
            }

            __nv_bfloat16* sPh = sma + OFF_PH;
            __nv_bfloat16* sPl = sma + OFF_PL;
#pragma unroll
            for (int r = 0; r < 2; r++) {
                float mt = -1e30f;
#pragma unroll
                for (int ni = 0; ni < 8; ni++)
                    mt = fmaxf(mt, fmaxf(s[ni][2 * r], s[ni][2 * r + 1]));
                mt = fmaxf(mt, __shfl_xor_sync(0xffffffffu, mt, 1));
                mt = fmaxf(mt, __shfl_xor_sync(0xffffffffu, mt, 2));
                float mnew = fmaxf(m_run[r], mt);
                float corr = __expf(m_run[r] - mnew);
                m_run[r] = mnew;
                float psum = 0.0f;
                const int prow = w * 16 + g + r * 8;
#pragma unroll
                for (int ni = 0; ni < 8; ni++) {
                    float p0 = __expf(s[ni][2 * r] - mnew);
                    float p1 = __expf(s[ni][2 * r + 1] - mnew);
                    psum += p0 + p1;
                    __nv_bfloat162 h2 = __floats2bfloat162_rn(p0, p1);
                    float l0 = p0 - __bfloat162float(h2.x);
                    float l1 = p1 - __bfloat162float(h2.y);
                    __nv_bfloat162 l2 = __floats2bfloat162_rn(l0, l1);
                    *(uint32_t*)&sPh[prow * PP + ni * 8 + t2] = *(uint32_t*)&h2;
                    *(uint32_t*)&sPl[prow * PP + ni * 8 + t2] = *(uint32_t*)&l2;
                }
                psum += __shfl_xor_sync(0xffffffffu, psum, 1);
                psum += __shfl_xor_sync(0xffffffffu, psum, 2);
                l_run[r] = l_run[r] * corr + psum;
#pragma unroll
                for (int ni = 0; ni < 16; ni++) {
                    o[ni][2 * r] *= corr;
                    o[ni][2 * r + 1] *= corr;
                }
            }
        }
        __syncthreads();   // (c)

        if (active) {
            const __nv_bfloat16* sPh = sma + OFF_PH;
            const __nv_bfloat16* sPl = sma + OFF_PL;
            const __nv_bfloat16* sVth = sma + OFF_VTH;
            const __nv_bfloat16* sVtl = sma + OFF_VTL;

#pragma unroll
            for (int kc = 0; kc < 4; kc++) {
                const int col = kc * 16 + t2;
                const int pr = w * 16 + g;
                uint32_t ah[4], al[4];
                ah[0] = *(const uint32_t*)&sPh[pr * PP + col];
                ah[1] = *(const uint32_t*)&sPh[(pr + 8) * PP + col];
                ah[2] = *(const uint32_t*)&sPh[pr * PP + col + 8];
                ah[3] = *(const uint32_t*)&sPh[(pr + 8) * PP + col + 8];
                al[0] = *(const uint32_t*)&sPl[pr * PP + col];
                al[1] = *(const uint32_t*)&sPl[(pr + 8) * PP + col];
                al[2] = *(const uint32_t*)&sPl[pr * PP + col + 8];
                al[3] = *(const uint32_t*)&sPl[(pr + 8) * PP + col + 8];
#pragma unroll
                for (int ni = 0; ni < 16; ni++) {
                    const int vr = ni * 8 + g;
                    uint32_t bh[2], bl[2];
                    bh[0] = *(const uint32_t*)&sVth[vr * PP + col];
                    bh[1] = *(const uint32_t*)&sVth[vr * PP + col + 8];
                    bl[0] = *(const uint32_t*)&sVtl[vr * PP + col];
                    bl[1] = *(const uint32_t*)&sVtl[vr * PP + col + 8];
                    mma_bf16(o[ni], ah, bh);
                    mma_bf16(o[ni], ah, bl);
                    mma_bf16(o[ni], al, bh);
                }
            }
        }
    }

    // ---- epilogue ----
#pragma unroll
    for (int r = 0; r < 2; r++) {
        float inv = 1.0f / l_run[r];
        int t = qg0 + w * 16 + g + r * 8;
        size_t rowo = (size_t)(b * Tt + t) * Dd + h * HDd;
#pragma unroll
        for (int ni = 0; ni < 16; ni++) {
            float v0 = o[ni][2 * r] * inv;
            float v1 = o[ni][2 * r + 1] * inv;
            __nv_bfloat162 h2 = __floats2bfloat162_rn(v0, v1);
            float l0 = v0 - __bfloat162float(h2.x);
            float l1 = v1 - __bfloat162float(h2.y);
            __nv_bfloat162 l2 = __floats2bfloat162_rn(l0, l1);
            *(uint32_t*)&g_aoh[rowo + ni * 8 + t2] = *(uint32_t*)&h2;
            *(uint32_t*)&g_aol[rowo + ni * 8 + t2] = *(uint32_t*)&l2;
        }
    }
}

// ================= launch ===================================================
extern "C" void kernel_launch(void* const* d_in, const int* in_sizes, int n_in,
                              void* d_out, int out_size) {
    const float* x = (const float*)d_in[0];
    const int* positions = (const int*)d_in[2];
    const float* qkv_w = (const float*)d_in[3];
    const float* out_w = (const float*)d_in[4];
    const float* q_norm_w = (const float*)d_in[5];
    const float* k_norm_w = (const float*)d_in[6];
    float* out = (float*)d_out;
    (void)in_sizes; (void)n_in; (void)out_size;

    void *p_qkv, *p_xh, *p_xl, *p_aoh, *p_aol, *p_wqh, *p_wql, *p_woh, *p_wol;
    cudaGetSymbolAddress(&p_qkv, g_qkv);
    cudaGetSymbolAddress(&p_xh, g_xh);
    cudaGetSymbolAddress(&p_xl, g_xl);
    cudaGetSymbolAddress(&p_aoh, g_aoh);
    cudaGetSymbolAddress(&p_aol, g_aol);
    cudaGetSymbolAddress(&p_wqh, g_wqh);
    cudaGetSymbolAddress(&p_wql, g_wql);
    cudaGetSymbolAddress(&p_woh, g_woh);
    cudaGetSymbolAddress(&p_wol, g_wol);

    static int attr_set = 0;
    if (!attr_set) {
        cudaFuncSetAttribute(gemm_mma_kernel, cudaFuncAttributeMaxDynamicSharedMemorySize, GEMM_SMEM);
        cudaFuncSetAttribute(attn_mma_kernel, cudaFuncAttributeMaxDynamicSharedMemorySize, ATTN_SMEM);
        attr_set = 1;
    }

    const int M = Bb * Tt;

    rope_table_kernel<<<(Bb * Tt * 64 + 255) / 256, 256>>>(positions);
    convert_split_kernel<<<(M * Dd / 4 + 255) / 256, 256>>>(
        x, (__nv_bfloat16*)p_xh, (__nv_bfloat16*)p_xl, M * Dd / 4);
    transpose_split_kernel<<<dim3(3 * Dd / 32, Dd / 32, 2), dim3(32, 8)>>>(qkv_w, out_w);
    gemm_mma_kernel<<<dim3(3 * Dd / 128, M / 128), 256, GEMM_SMEM>>>(
        (const __nv_bfloat16*)p_xh, (const __nv_bfloat16*)p_xl,
        (const __nv_bfloat16*)p_wqh, (const __nv_bfloat16*)p_wql,
        (float*)p_qkv, M, 3 * Dd, Dd);
    rope_norm_kernel<<<dim3(Hh, Tt, Bb), 128>>>(q_norm_w, k_norm_w);
    attn_mma_kernel<<<dim3(Tt / 128, Hh, Bb), 256, ATTN_SMEM>>>();
    gemm_mma_kernel<<<dim3(Dd / 128, M / 128), 256, GEMM_SMEM>>>(
        (const __nv_bfloat16*)p_aoh, (const __nv_bfloat16*)p_aol,
        (const __nv_bfloat16*)p_woh, (const __nv_bfloat16*)p_wol,
        out, M, Dd, Dd);
}

// round 10
// speedup vs baseline: 2.8909x; 1.0940x over previous
#include <cuda_runtime.h>
#include <cuda_bf16.h>
#include <math.h>
#include <stdint.h>

#define Bb 2
#define Tt 2048
#define Dd 2048
#define Hh 16
#define HDd 128

// ================= scratch ==================================================
__device__ float g_qkv[(size_t)Bb * Tt * 3 * Dd];
__device__ float g_cos[(size_t)Bb * Tt * 64];
__device__ float g_sin[(size_t)Bb * Tt * 64];
__device__ __nv_bfloat16 g_xh[(size_t)Bb * Tt * Dd];
__device__ __nv_bfloat16 g_xl[(size_t)Bb * Tt * Dd];
__device__ __nv_bfloat16 g_aoh[(size_t)Bb * Tt * Dd];
__device__ __nv_bfloat16 g_aol[(size_t)Bb * Tt * Dd];
__device__ __nv_bfloat16 g_wqh[(size_t)3 * Dd * Dd];
__device__ __nv_bfloat16 g_wql[(size_t)3 * Dd * Dd];
__device__ __nv_bfloat16 g_woh[(size_t)Dd * Dd];
__device__ __nv_bfloat16 g_wol[(size_t)Dd * Dd];
__device__ __nv_bfloat16 g_qh[(size_t)Bb * Hh * Tt * HDd];
__device__ __nv_bfloat16 g_ql[(size_t)Bb * Hh * Tt * HDd];
__device__ __nv_bfloat16 g_kh[(size_t)Bb * Hh * Tt * HDd];
__device__ __nv_bfloat16 g_kl[(size_t)Bb * Hh * Tt * HDd];
__device__ __nv_bfloat16 g_vh[(size_t)Bb * Hh * Tt * HDd];
__device__ __nv_bfloat16 g_vl[(size_t)Bb * Hh * Tt * HDd];

__device__ __forceinline__ uint32_t smem_u32(const void* p) {
    uint32_t a;
    asm("{ .reg .u64 t; cvta.to.shared.u64 t, %1; cvt.u32.u64 %0, t; }" : "=r"(a) : "l"(p));
    return a;
}

__device__ __forceinline__ void ldsm_x4(uint32_t* r, uint32_t addr) {
    asm volatile("ldmatrix.sync.aligned.m8n8.x4.shared.b16 {%0,%1,%2,%3}, [%4];"
                 : "=r"(r[0]), "=r"(r[1]), "=r"(r[2]), "=r"(r[3]) : "r"(addr));
}

// ================= RoPE table ==============================================
__global__ void rope_table_kernel(const int* __restrict__ positions) {
    int idx = blockIdx.x * blockDim.x + threadIdx.x;
    if (idx >= Bb * Tt * 64) return;
    int j = idx & 63;
    int bt = idx >> 6;
    int pos = positions[bt];
    float inv_freq = exp2f(-(float)j * (13.287712379549449f / 64.0f));
    float ang = (float)pos * inv_freq;
    double da = (double)ang;
    g_cos[idx] = (float)cos(da);
    g_sin[idx] = (float)sin(da);
}

// ================= split-convert (elementwise) ==============================
__global__ void convert_split_kernel(const float* __restrict__ in,
                                     __nv_bfloat16* __restrict__ oh,
                                     __nv_bfloat16* __restrict__ ol, int n4) {
    int i = blockIdx.x * blockDim.x + threadIdx.x;
    if (i >= n4) return;
    float4 v = ((const float4*)in)[i];
    __nv_bfloat16 hx = __float2bfloat16(v.x);
    __nv_bfloat16 hy = __float2bfloat16(v.y);
    __nv_bfloat16 hz = __float2bfloat16(v.z);
    __nv_bfloat16 hw = __float2bfloat16(v.w);
    __nv_bfloat16 lx = __float2bfloat16(v.x - __bfloat162float(hx));
    __nv_bfloat16 ly = __float2bfloat16(v.y - __bfloat162float(hy));
    __nv_bfloat16 lz = __float2bfloat16(v.z - __bfloat162float(hz));
    __nv_bfloat16 lw = __float2bfloat16(v.w - __bfloat162float(hw));
    ((__nv_bfloat162*)oh)[2 * i + 0] = __nv_bfloat162(hx, hy);
    ((__nv_bfloat162*)oh)[2 * i + 1] = __nv_bfloat162(hz, hw);
    ((__nv_bfloat162*)ol)[2 * i + 0] = __nv_bfloat162(lx, ly);
    ((__nv_bfloat162*)ol)[2 * i + 1] = __nv_bfloat162(lz, lw);
}

// ================= transpose + split convert (both weights) =================
__global__ void transpose_split_kernel(const float* __restrict__ W0,
                                       const float* __restrict__ W1) {
    __shared__ float t[32][33];
    int z = blockIdx.z;
    int Ncols = z ? Dd : 3 * Dd;
    const float* W = z ? W1 : W0;
    __nv_bfloat16* Th = z ? g_woh : g_wqh;
    __nv_bfloat16* Tl = z ? g_wol : g_wql;
    int n0 = blockIdx.x * 32, k0 = blockIdx.y * 32;
    if (n0 >= Ncols) return;
    int tx = threadIdx.x, ty = threadIdx.y;
#pragma unroll
    for (int i = ty; i < 32; i += 8)
        t[i][tx] = W[(size_t)(k0 + i) * Ncols + n0 + tx];
    __syncthreads();
#pragma unroll
    for (int i = ty; i < 32; i += 8) {
        float v = t[tx][i];
        __nv_bfloat16 h = __float2bfloat16(v);
        __nv_bfloat16 l = __float2bfloat16(v - __bfloat162float(h));
        size_t o = (size_t)(n0 + i) * Dd + k0 + tx;
        Th[o] = h;
        Tl[o] = l;
    }
}

// ================= mma.sync bf16x3 GEMM (LDSM fragments) ====================
#define BKP 40
#define TILE_E (128 * BKP)
#define STAGE_E (4 * TILE_E)
#define GEMM_SMEM (2 * STAGE_E * 2)

__device__ __forceinline__ void mma_bf16(float* d, const uint32_t* a, const uint32_t* b) {
    asm volatile(
        "mma.sync.aligned.m16n8k16.row.col.f32.bf16.bf16.f32 "
        "{%0,%1,%2,%3}, {%4,%5,%6,%7}, {%8,%9}, {%0,%1,%2,%3};"
        : "+f"(d[0]), "+f"(d[1]), "+f"(d[2]), "+f"(d[3])
        : "r"(a[0]), "r"(a[1]), "r"(a[2]), "r"(a[3]), "r"(b[0]), "r"(b[1]));
}

__global__ __launch_bounds__(256, 2) void gemm_mma_kernel(
    const __nv_bfloat16* __restrict__ Ah, const __nv_bfloat16* __restrict__ Al,
    const __nv_bfloat16* __restrict__ Bh, const __nv_bfloat16* __restrict__ Bl,
    float* __restrict__ C, int M, int N, int K) {
    extern __shared__ __align__(128) __nv_bfloat16 smem[];
    const int tid = threadIdx.x;
    const int lane = tid & 31;
    const int wid = tid >> 5;
    const int g = lane >> 2;
    const int t2 = (lane & 3) * 2;
    const int wm = wid & 1, wn = wid >> 1;
    const int m0 = wm * 64, n0 = wn * 32;
    const int bm = blockIdx.y * 128;
    const int bn = blockIdx.x * 128;

    const __nv_bfloat16* srcs[4] = {Ah + (size_t)bm * K, Al + (size_t)bm * K,
                                    Bh + (size_t)bn * K, Bl + (size_t)bn * K};

    uint32_t smem_base = smem_u32(smem);

    // ldmatrix lane-address components
    const int aRow = lane & 15;                       // row within 16-row frag
    const int aCol = (lane >> 4) << 3;                // 0 or 8 (k offset)
    const int bRow = (lane & 7) + ((lane >> 4) << 3); // row within 16-n pair
    const int bCol = lane & 8;                        // 0 or 8 (k offset)

    float acc[4][4][4];
#pragma unroll
    for (int mi = 0; mi < 4; mi++)
#pragma unroll
        for (int ni = 0; ni < 4; ni++)
#pragma unroll
            for (int c = 0; c < 4; c++) acc[mi][ni][c] = 0.0f;

    const int nK = K >> 5;

    auto load_stage = [&](int s, int kb) {
        const int k0 = kb * 32;
#pragma unroll
        for (int i = 0; i < 8; i++) {
            int idx = i * 256 + tid;
            int tile = idx >> 9;
            int rem = idx & 511;
            int row = rem >> 2;
            int seg = rem & 3;
            const __nv_bfloat16* gp = srcs[tile] + (size_t)row * K + k0 + seg * 8;
            uint32_t sa = smem_base +
                (uint32_t)(s * STAGE_E + tile * TILE_E + row * BKP + seg * 8) * 2;
            asm volatile("cp.async.ca.shared.global [%0], [%1], 16;"
                         :: "r"(sa), "l"(gp));
        }
    };

    load_stage(0, 0);
    asm volatile("cp.async.commit_group;");

    for (int kb = 0; kb < nK; kb++) {
        const int cur = kb & 1;
        if (kb + 1 < nK) {
            load_stage(cur ^ 1, kb + 1);
            asm volatile("cp.async.commit_group;");
            asm volatile("cp.async.wait_group 1;");
        } else {
            asm volatile("cp.async.wait_group 0;");
        }
        __syncthreads();

        const uint32_t uAh = smem_base + (uint32_t)(cur * STAGE_E) * 2;
        const uint32_t uAl = uAh + (uint32_t)TILE_E * 2;
        const uint32_t uBh = uAh + (uint32_t)(2 * TILE_E) * 2;
        const uint32_t uBl = uAh + (uint32_t)(3 * TILE_E) * 2;

#pragma unroll
        for (int ks = 0; ks < 32; ks += 16) {
            // B fragments: 2 LDSM.x4 each for hi/lo -> b[4][2]
            uint32_t bh[4][2], bl[4][2];
#pragma unroll
            for (int np = 0; np < 2; np++) {
                uint32_t r4[4];
                uint32_t off = (uint32_t)((n0 + np * 16 + bRow) * BKP + ks + bCol) * 2;
                ldsm_x4(r4, uBh + off);
                bh[np * 2][0] = r4[0]; bh[np * 2][1] = r4[1];
                bh[np * 2 + 1][0] = r4[2]; bh[np * 2 + 1][1] = r4[3];
                ldsm_x4(r4, uBl + off);
                bl[np * 2][0] = r4[0]; bl[np * 2][1] = r4[1];
                bl[np * 2 + 1][0] = r4[2]; bl[np * 2 + 1][1] = r4[3];
            }
            // A fragments streamed per-mi: 1 LDSM.x4 hi + 1 lo
#pragma unroll
            for (int mi = 0; mi < 4; mi++) {
                uint32_t off = (uint32_t)((m0 + mi * 16 + aRow) * BKP + ks + aCol) * 2;
                uint32_t ah[4], al[4];
                ldsm_x4(ah, uAh + off);
                ldsm_x4(al, uAl + off);
#pragma unroll
                for (int ni = 0; ni < 4; ni++) {
                    mma_bf16(acc[mi][ni], ah, bh[ni]);
                    mma_bf16(acc[mi][ni], ah, bl[ni]);
                    mma_bf16(acc[mi][ni], al, bh[ni]);
                }
            }
        }
        __syncthreads();
    }

#pragma unroll
    for (int mi = 0; mi < 4; mi++) {
#pragma unroll
        for (int ni = 0; ni < 4; ni++) {
            int row = bm + m0 + mi * 16 + g;
            int col = bn + n0 + ni * 8 + t2;
            *(float2*)&C[(size_t)row * N + col] =
                make_float2(acc[mi][ni][0], acc[mi][ni][1]);
            *(float2*)&C[(size_t)(row + 8) * N + col] =
                make_float2(acc[mi][ni][2], acc[mi][ni][3]);
        }
    }
}

// ================= RoPE + RMSNorm -> bf16 hi/lo Q,K,V =======================
__global__ void rope_norm_kernel(const float* __restrict__ qw,
                                 const float* __restrict__ kw) {
    const int h = blockIdx.x, t = blockIdx.y, b = blockIdx.z;
    const int hd = threadIdx.x;
    __shared__ float sq[128], sk[128];
    __shared__ float red[8];

    const size_t row = (size_t)(b * Tt + t) * (3 * Dd);
    float qv = g_qkv[row + h * HDd + hd];
    float kv = g_qkv[row + Dd + h * HDd + hd];
    float vv = g_qkv[row + 2 * Dd + h * HDd + hd];
    sq[hd] = qv;
    sk[hd] = kv;
    __syncthreads();

    const int j = hd & 63;
    const int ci = (b * Tt + t) * 64 + j;
    const float c = g_cos[ci], s = g_sin[ci];
    float rq, rk;
    if (hd < 64) {
        rq = sq[hd] * c - sq[hd + 64] * s;
        rk = sk[hd] * c - sk[hd + 64] * s;
    } else {
        rq = sq[hd] * c + sq[hd - 64] * s;
        rk = sk[hd] * c + sk[hd - 64] * s;
    }
    float s2q = rq * rq, s2k = rk * rk;
#pragma unroll
    for (int m = 16; m >= 1; m >>= 1) {
        s2q += __shfl_xor_sync(0xffffffffu, s2q, m);
        s2k += __shfl_xor_sync(0xffffffffu, s2k, m);
    }
    const int w = hd >> 5;
    if ((hd & 31) == 0) { red[w] = s2q; red[4 + w] = s2k; }
    __syncthreads();
    float sumq = red[0] + red[1] + red[2] + red[3];
    float sumk = red[4] + red[5] + red[6] + red[7];
    float iq = rsqrtf(sumq * (1.0f / 128.0f) + 1e-6f);
    float ik = rsqrtf(sumk * (1.0f / 128.0f) + 1e-6f);

    const float qsc = 0.08838834764831845f;
    float qf = rq * iq * qw[hd] * qsc;
    float kf = rk * ik * kw[hd];

    const size_t o = (size_t)((b * Hh + h) * Tt + t) * HDd + hd;
    __nv_bfloat16 qh = __float2bfloat16(qf);
    __nv_bfloat16 kh = __float2bfloat16(kf);
    __nv_bfloat16 vh = __float2bfloat16(vv);
    g_qh[o] = qh;
    g_ql[o] = __float2bfloat16(qf - __bfloat162float(qh));
    g_kh[o] = kh;
    g_kl[o] = __float2bfloat16(kf - __bfloat162float(kh));
    g_vh[o] = vh;
    g_vl[o] = __float2bfloat16(vv - __bfloat162float(vh));
}

// ================= Tensor-core flash attention (causal, bf16x3) =============
#define AP 136
#define PP 72
#define Q_E (128 * AP)
#define K_E (64 * AP)
#define VT_E (128 * PP)
#define P_E (128 * PP)
#define OFF_QH 0
#define OFF_QL (Q_E)
#define OFF_KH (2 * Q_E)
#define OFF_KL (2 * Q_E + K_E)
#define OFF_VTH (2 * Q_E + 2 * K_E)
#define OFF_VTL (2 * Q_E + 2 * K_E + VT_E)
#define OFF_PH (2 * Q_E + 2 * K_E + 2 * VT_E)
#define OFF_PL (2 * Q_E + 2 * K_E + 2 * VT_E + P_E)
#define ATTN_SMEM ((2 * Q_E + 2 * K_E + 2 * VT_E + 2 * P_E) * 2)  // 178176 B

__global__ __launch_bounds__(256, 1) void attn_mma_kernel() {
    extern __shared__ __align__(128) __nv_bfloat16 sma[];
    const int tid = threadIdx.x;
    const int lane = tid & 31;
    const int w = tid >> 5;
    const int g = lane >> 2;
    const int t2 = (lane & 3) * 2;
    const int qb = blockIdx.x, h = blockIdx.y, b = blockIdx.z;
    const int qg0 = qb * 128;
    const size_t hb = (size_t)(b * Hh + h) * Tt * HDd;
    const uint32_t sbase = smem_u32(sma);

    {
        const __nv_bfloat16* qs[2] = {g_qh + hb + (size_t)qg0 * HDd,
                                      g_ql + hb + (size_t)qg0 * HDd};
#pragma unroll
        for (int i = 0; i < 16; i++) {
            int idx = tid + i * 256;
            int arr = idx >> 11;
            int rem = idx & 2047;
            int row = rem >> 4;
            int seg = rem & 15;
            uint4 v = *(const uint4*)(qs[arr] + (size_t)row * HDd + seg * 8);
            *(uint4*)(sma + arr * Q_E + row * AP + seg * 8) = v;
        }
    }

    float o[16][4];
#pragma unroll
    for (int ni = 0; ni < 16; ni++)
#pragma unroll
        for (int c = 0; c < 4; c++) o[ni][c] = 0.0f;
    float m_run[2] = {-1e30f, -1e30f}, l_run[2] = {0.0f, 0.0f};

    const int nkb = 2 * qb + 2;
    const int qwr = qg0 + w * 16;

    for (int kb = 0; kb < nkb; kb++) {
        const int kg0 = kb * 64;
        __syncthreads();   // (a)

#pragma unroll
        for (int i = 0; i < 8; i++) {
            int idx = tid + i * 256;
            int arr = idx >> 10;
            int rem = idx & 1023;
            int row = rem >> 4;
            int seg = rem & 15;
            const __nv_bfloat16* gp = (arr ? g_kl : g_kh) + hb +
                                      (size_t)(kg0 + row) * HDd + seg * 8;
            uint32_t sa = sbase + (uint32_t)((arr ? OFF_KL : OFF_KH) +
                                             row * AP + seg * 8) * 2;
            asm volatile("cp.async.ca.shared.global [%0], [%1], 16;"
                         :: "r"(sa), "l"(gp));
        }
        asm volatile("cp.async.commit_group;");

#pragma unroll
        for (int i = 0; i < 8; i++) {
            int idx = tid + i * 256;
            int arr = idx >> 10, rem = idx & 1023;
            int dseg = rem >> 6, key = rem & 63;
            const __nv_bfloat16* gp = (arr ? g_vl : g_vh) + hb +
                                      (size_t)(kg0 + key) * HDd + dseg * 8;
            uint4 v = *(const uint4*)gp;
            const __nv_bfloat16* pv = (const __nv_bfloat16*)&v;
            __nv_bfloat16* dst = sma + (arr ? OFF_VTL : OFF_VTH);
#pragma unroll
            for (int j = 0; j < 8; j++)
                dst[(dseg * 8 + j) * PP + key] = pv[j];
        }
        asm volatile("cp.async.wait_group 0;");
        __syncthreads();   // (b)

        const bool active = (kg0 <= qwr + 15);
        if (active) {
            const __nv_bfloat16* sQh = sma + OFF_QH;
            const __nv_bfloat16* sQl = sma + OFF_QL;
            const __nv_bfloat16* sKh = sma + OFF_KH;
            const __nv_bfloat16* sKl = sma + OFF_KL;

            float s[8][4];
#pragma unroll
            for (int ni = 0; ni < 8; ni++)
#pragma unroll
                for (int c = 0; c < 4; c++) s[ni][c] = 0.0f;

#pragma unroll
            for (int kc = 0; kc < 8; kc++) {
                const int col = kc * 16 + t2;
                const int r0 = w * 16 + g;
                uint32_t ah[4], al[4];
                ah[0] = *(const uint32_t*)&sQh[r0 * AP + col];
                ah[1] = *(const uint32_t*)&sQh[(r0 + 8) * AP + col];
                ah[2] = *(const uint32_t*)&sQh[r0 * AP + col + 8];
                ah[3] = *(const uint32_t*)&sQh[(r0 + 8) * AP + col + 8];
                al[0] = *(const uint32_t*)&sQl[r0 * AP + col];
                al[1] = *(const uint32_t*)&sQl[(r0 + 8) * AP + col];
                al[2] = *(const uint32_t*)&sQl[r0 * AP + col + 8];
                al[3] = *(const uint32_t*)&sQl[(r0 + 8) * AP + col + 8];
#pragma unroll
                for (int ni = 0; ni < 8; ni++) {
                    const int kr = ni * 8 + g;
                    uint32_t bh[2], bl[2];
                    bh[0] = *(const uint32_t*)&sKh[kr * AP + col];
                    bh[1] = *(const uint32_t*)&sKh[kr * AP + col + 8];
                    bl[0] = *(const uint32_t*)&sKl[kr * AP + col];
                    bl[1] = *(const uint32_t*)&sKl[kr * AP + col + 8];
                    mma_bf16(s[ni], ah, bh);
                    mma_bf16(s[ni], ah, bl);
                    mma_bf16(s[ni], al, bh);
                }
            }

            if (kg0 + 63 > qwr) {
#pragma unroll
                for (int ni = 0; ni < 8; ni++)
#pragma unroll
                    for (int c = 0; c < 4; c++) {
                        int key = kg0 + ni * 8 + t2 + (c & 1);
                        int qr = qwr + g + ((c & 2) ? 8 : 0);
                        if (key > qr) s[ni][c] = -1e30f;
                    }
            }

            __nv_bfloat16* sPh = sma + OFF_PH;
            __nv_bfloat16* sPl = sma + OFF_PL;
#pragma unroll
            for (int r = 0; r < 2; r++) {
                float mt = -1e30f;
#pragma unroll
                for (int ni = 0; ni < 8; ni++)
                    mt = fmaxf(mt, fmaxf(s[ni][2 * r], s[ni][2 * r + 1]));
                mt = fmaxf(mt, __shfl_xor_sync(0xffffffffu, mt, 1));
                mt = fmaxf(mt, __shfl_xor_sync(0xffffffffu, mt, 2));
                float mnew = fmaxf(m_run[r], mt);
                float corr = __expf(m_run[r] - mnew);
                m_run[r] = mnew;
                float psum = 0.0f;
                const int prow = w * 16 + g + r * 8;
#pragma unroll
                for (int ni = 0; ni < 8; ni++) {
                    float p0 = __expf(s[ni][2 * r] - mnew);
                    float p1 = __expf(s[ni][2 * r + 1] - mnew);
                    psum += p0 + p1;
                    __nv_bfloat162 h2 = __floats2bfloat162_rn(p0, p1);
                    float l0 = p0 - __bfloat162float(h2.x);
                    float l1 = p1 - __bfloat162float(h2.y);
                    __nv_bfloat162 l2 = __floats2bfloat162_rn(l0, l1);
                    *(uint32_t*)&sPh[prow * PP + ni * 8 + t2] = *(uint32_t*)&h2;
                    *(uint32_t*)&sPl[prow * PP + ni * 8 + t2] = *(uint32_t*)&l2;
                }
                psum += __shfl_xor_sync(0xffffffffu, psum, 1);
                psum += __shfl_xor_sync(0xffffffffu, psum, 2);
                l_run[r] = l_run[r] * corr + psum;
#pragma unroll
                for (int ni = 0; ni < 16; ni++) {
                    o[ni][2 * r] *= corr;
                    o[ni][2 * r + 1] *= corr;
                }
            }
        }
        __syncthreads();   // (c)

        if (active) {
            const __nv_bfloat16* sPh = sma + OFF_PH;
            const __nv_bfloat16* sPl = sma + OFF_PL;
            const __nv_bfloat16* sVth = sma + OFF_VTH;
            const __nv_bfloat16* sVtl = sma + OFF_VTL;

#pragma unroll
            for (int kc = 0; kc < 4; kc++) {
                const int col = kc * 16 + t2;
                const int pr = w * 16 + g;
                uint32_t ah[4], al[4];
                ah[0] = *(const uint32_t*)&sPh[pr * PP + col];
                ah[1] = *(const uint32_t*)&sPh[(pr + 8) * PP + col];
                ah[2] = *(const uint32_t*)&sPh[pr * PP + col + 8];
                ah[3] = *(const uint32_t*)&sPh[(pr + 8) * PP + col + 8];
                al[0] = *(const uint32_t*)&sPl[pr * PP + col];
                al[1] = *(const uint32_t*)&sPl[(pr + 8) * PP + col];
                al[2] = *(const uint32_t*)&sPl[pr * PP + col + 8];
                al[3] = *(const uint32_t*)&sPl[(pr + 8) * PP + col + 8];
#pragma unroll
                for (int ni = 0; ni < 16; ni++) {
                    const int vr = ni * 8 + g;
                    uint32_t bh[2], bl[2];
                    bh[0] = *(const uint32_t*)&sVth[vr * PP + col];
                    bh[1] = *(const uint32_t*)&sVth[vr * PP + col + 8];
                    bl[0] = *(const uint32_t*)&sVtl[vr * PP + col];
                    bl[1] = *(const uint32_t*)&sVtl[vr * PP + col + 8];
                    mma_bf16(o[ni], ah, bh);
                    mma_bf16(o[ni], ah, bl);
                    mma_bf16(o[ni], al, bh);
                }
            }
        }
    }

    // ---- epilogue ----
#pragma unroll
    for (int r = 0; r < 2; r++) {
        float inv = 1.0f / l_run[r];
        int t = qg0 + w * 16 + g + r * 8;
        size_t rowo = (size_t)(b * Tt + t) * Dd + h * HDd;
#pragma unroll
        for (int ni = 0; ni < 16; ni++) {
            float v0 = o[ni][2 * r] * inv;
            float v1 = o[ni][2 * r + 1] * inv;
            __nv_bfloat162 h2 = __floats2bfloat162_rn(v0, v1);
            float l0 = v0 - __bfloat162float(h2.x);
            float l1 = v1 - __bfloat162float(h2.y);
            __nv_bfloat162 l2 = __floats2bfloat162_rn(l0, l1);
            *(uint32_t*)&g_aoh[rowo + ni * 8 + t2] = *(uint32_t*)&h2;
            *(uint32_t*)&g_aol[rowo + ni * 8 + t2] = *(uint32_t*)&l2;
        }
    }
}

// ================= launch ===================================================
extern "C" void kernel_launch(void* const* d_in, const int* in_sizes, int n_in,
                              void* d_out, int out_size) {
    const float* x = (const float*)d_in[0];
    const int* positions = (const int*)d_in[2];
    const float* qkv_w = (const float*)d_in[3];
    const float* out_w = (const float*)d_in[4];
    const float* q_norm_w = (const float*)d_in[5];
    const float* k_norm_w = (const float*)d_in[6];
    float* out = (float*)d_out;
    (void)in_sizes; (void)n_in; (void)out_size;

    void *p_qkv, *p_xh, *p_xl, *p_aoh, *p_aol, *p_wqh, *p_wql, *p_woh, *p_wol;
    cudaGetSymbolAddress(&p_qkv, g_qkv);
    cudaGetSymbolAddress(&p_xh, g_xh);
    cudaGetSymbolAddress(&p_xl, g_xl);
    cudaGetSymbolAddress(&p_aoh, g_aoh);
    cudaGetSymbolAddress(&p_aol, g_aol);
    cudaGetSymbolAddress(&p_wqh, g_wqh);
    cudaGetSymbolAddress(&p_wql, g_wql);
    cudaGetSymbolAddress(&p_woh, g_woh);
    cudaGetSymbolAddress(&p_wol, g_wol);

    static int attr_set = 0;
    if (!attr_set) {
        cudaFuncSetAttribute(gemm_mma_kernel, cudaFuncAttributeMaxDynamicSharedMemorySize, GEMM_SMEM);
        cudaFuncSetAttribute(attn_mma_kernel, cudaFuncAttributeMaxDynamicSharedMemorySize, ATTN_SMEM);
        attr_set = 1;
    }

    const int M = Bb * Tt;

    rope_table_kernel<<<(Bb * Tt * 64 + 255) / 256, 256>>>(positions);
    convert_split_kernel<<<(M * Dd / 4 + 255) / 256, 256>>>(
        x, (__nv_bfloat16*)p_xh, (__nv_bfloat16*)p_xl, M * Dd / 4);
    transpose_split_kernel<<<dim3(3 * Dd / 32, Dd / 32, 2), dim3(32, 8)>>>(qkv_w, out_w);
    gemm_mma_kernel<<<dim3(3 * Dd / 128, M / 128), 256, GEMM_SMEM>>>(
        (const __nv_bfloat16*)p_xh, (const __nv_bfloat16*)p_xl,
        (const __nv_bfloat16*)p_wqh, (const __nv_bfloat16*)p_wql,
        (float*)p_qkv, M, 3 * Dd, Dd);
    rope_norm_kernel<<<dim3(Hh, Tt, Bb), 128>>>(q_norm_w, k_norm_w);
    attn_mma_kernel<<<dim3(Tt / 128, Hh, Bb), 256, ATTN_SMEM>>>();
    gemm_mma_kernel<<<dim3(Dd / 128, M / 128), 256, GEMM_SMEM>>>(
        (const __nv_bfloat16*)p_aoh, (const __nv_bfloat16*)p_aol,
        (const __nv_bfloat16*)p_woh, (const __nv_bfloat16*)p_wol,
        out, M, Dd, Dd);
}

// round 11
// speedup vs baseline: 2.9015x; 1.0037x over previous
#include <cuda_runtime.h>
#include <cuda_bf16.h>
#include <math.h>
#include <stdint.h>

#define Bb 2
#define Tt 2048
#define Dd 2048
#define Hh 16
#define HDd 128

// ================= scratch ==================================================
__device__ float g_qkv[(size_t)Bb * Tt * 3 * Dd];
__device__ float g_cos[(size_t)Bb * Tt * 64];
__device__ float g_sin[(size_t)Bb * Tt * 64];
__device__ __nv_bfloat16 g_xh[(size_t)Bb * Tt * Dd];
__device__ __nv_bfloat16 g_xl[(size_t)Bb * Tt * Dd];
__device__ __nv_bfloat16 g_aoh[(size_t)Bb * Tt * Dd];
__device__ __nv_bfloat16 g_aol[(size_t)Bb * Tt * Dd];
__device__ __nv_bfloat16 g_wqh[(size_t)3 * Dd * Dd];
__device__ __nv_bfloat16 g_wql[(size_t)3 * Dd * Dd];
__device__ __nv_bfloat16 g_woh[(size_t)Dd * Dd];
__device__ __nv_bfloat16 g_wol[(size_t)Dd * Dd];
__device__ __nv_bfloat16 g_qh[(size_t)Bb * Hh * Tt * HDd];
__device__ __nv_bfloat16 g_ql[(size_t)Bb * Hh * Tt * HDd];
__device__ __nv_bfloat16 g_kh[(size_t)Bb * Hh * Tt * HDd];
__device__ __nv_bfloat16 g_kl[(size_t)Bb * Hh * Tt * HDd];
__device__ __nv_bfloat16 g_vh[(size_t)Bb * Hh * Tt * HDd];
__device__ __nv_bfloat16 g_vl[(size_t)Bb * Hh * Tt * HDd];

__device__ __forceinline__ uint32_t smem_u32(const void* p) {
    uint32_t a;
    asm("{ .reg .u64 t; cvta.to.shared.u64 t, %1; cvt.u32.u64 %0, t; }" : "=r"(a) : "l"(p));
    return a;
}

__device__ __forceinline__ void ldsm_x4(uint32_t* r, uint32_t addr) {
    asm volatile("ldmatrix.sync.aligned.m8n8.x4.shared.b16 {%0,%1,%2,%3}, [%4];"
                 : "=r"(r[0]), "=r"(r[1]), "=r"(r[2]), "=r"(r[3]) : "r"(addr));
}

// ================= RoPE table ==============================================
__global__ void rope_table_kernel(const int* __restrict__ positions) {
    int idx = blockIdx.x * blockDim.x + threadIdx.x;
    if (idx >= Bb * Tt * 64) return;
    int j = idx & 63;
    int bt = idx >> 6;
    int pos = positions[bt];
    float inv_freq = exp2f(-(float)j * (13.287712379549449f / 64.0f));
    float ang = (float)pos * inv_freq;
    double da = (double)ang;
    g_cos[idx] = (float)cos(da);
    g_sin[idx] = (float)sin(da);
}

// ================= split-convert (elementwise) ==============================
__global__ void convert_split_kernel(const float* __restrict__ in,
                                     __nv_bfloat16* __restrict__ oh,
                                     __nv_bfloat16* __restrict__ ol, int n4) {
    int i = blockIdx.x * blockDim.x + threadIdx.x;
    if (i >= n4) return;
    float4 v = ((const float4*)in)[i];
    __nv_bfloat16 hx = __float2bfloat16(v.x);
    __nv_bfloat16 hy = __float2bfloat16(v.y);
    __nv_bfloat16 hz = __float2bfloat16(v.z);
    __nv_bfloat16 hw = __float2bfloat16(v.w);
    __nv_bfloat16 lx = __float2bfloat16(v.x - __bfloat162float(hx));
    __nv_bfloat16 ly = __float2bfloat16(v.y - __bfloat162float(hy));
    __nv_bfloat16 lz = __float2bfloat16(v.z - __bfloat162float(hz));
    __nv_bfloat16 lw = __float2bfloat16(v.w - __bfloat162float(hw));
    ((__nv_bfloat162*)oh)[2 * i + 0] = __nv_bfloat162(hx, hy);
    ((__nv_bfloat162*)oh)[2 * i + 1] = __nv_bfloat162(hz, hw);
    ((__nv_bfloat162*)ol)[2 * i + 0] = __nv_bfloat162(lx, ly);
    ((__nv_bfloat162*)ol)[2 * i + 1] = __nv_bfloat162(lz, lw);
}

// ================= transpose + split convert (both weights) =================
__global__ void transpose_split_kernel(const float* __restrict__ W0,
                                       const float* __restrict__ W1) {
    __shared__ float t[32][33];
    int z = blockIdx.z;
    int Ncols = z ? Dd : 3 * Dd;
    const float* W = z ? W1 : W0;
    __nv_bfloat16* Th = z ? g_woh : g_wqh;
    __nv_bfloat16* Tl = z ? g_wol : g_wql;
    int n0 = blockIdx.x * 32, k0 = blockIdx.y * 32;
    if (n0 >= Ncols) return;
    int tx = threadIdx.x, ty = threadIdx.y;
#pragma unroll
    for (int i = ty; i < 32; i += 8)
        t[i][tx] = W[(size_t)(k0 + i) * Ncols + n0 + tx];
    __syncthreads();
#pragma unroll
    for (int i = ty; i < 32; i += 8) {
        float v = t[tx][i];
        __nv_bfloat16 h = __float2bfloat16(v);
        __nv_bfloat16 l = __float2bfloat16(v - __bfloat162float(h));
        size_t o = (size_t)(n0 + i) * Dd + k0 + tx;
        Th[o] = h;
        Tl[o] = l;
    }
}

// ================= mma.sync bf16x3 GEMM (LDSM fragments) ====================
#define BKP 40
#define TILE_E (128 * BKP)
#define STAGE_E (4 * TILE_E)
#define GEMM_SMEM (2 * STAGE_E * 2)

__device__ __forceinline__ void mma_bf16(float* d, const uint32_t* a, const uint32_t* b) {
    asm volatile(
        "mma.sync.aligned.m16n8k16.row.col.f32.bf16.bf16.f32 "
        "{%0,%1,%2,%3}, {%4,%5,%6,%7}, {%8,%9}, {%0,%1,%2,%3};"
        : "+f"(d[0]), "+f"(d[1]), "+f"(d[2]), "+f"(d[3])
        : "r"(a[0]), "r"(a[1]), "r"(a[2]), "r"(a[3]), "r"(b[0]), "r"(b[1]));
}

__global__ __launch_bounds__(256, 2) void gemm_mma_kernel(
    const __nv_bfloat16* __restrict__ Ah, const __nv_bfloat16* __restrict__ Al,
    const __nv_bfloat16* __restrict__ Bh, const __nv_bfloat16* __restrict__ Bl,
    float* __restrict__ C, int M, int N, int K) {
    extern __shared__ __align__(128) __nv_bfloat16 smem[];
    const int tid = threadIdx.x;
    const int lane = tid & 31;
    const int wid = tid >> 5;
    const int g = lane >> 2;
    const int t2 = (lane & 3) * 2;
    const int wm = wid & 1, wn = wid >> 1;
    const int m0 = wm * 64, n0 = wn * 32;
    const int bm = blockIdx.y * 128;
    const int bn = blockIdx.x * 128;

    const __nv_bfloat16* srcs[4] = {Ah + (size_t)bm * K, Al + (size_t)bm * K,
                                    Bh + (size_t)bn * K, Bl + (size_t)bn * K};

    uint32_t smem_base = smem_u32(smem);

    const int aRow = lane & 15;
    const int aCol = (lane >> 4) << 3;
    const int bRow = (lane & 7) + ((lane >> 4) << 3);
    const int bCol = lane & 8;

    float acc[4][4][4];
#pragma unroll
    for (int mi = 0; mi < 4; mi++)
#pragma unroll
        for (int ni = 0; ni < 4; ni++)
#pragma unroll
            for (int c = 0; c < 4; c++) acc[mi][ni][c] = 0.0f;

    const int nK = K >> 5;

    auto load_stage = [&](int s, int kb) {
        const int k0 = kb * 32;
#pragma unroll
        for (int i = 0; i < 8; i++) {
            int idx = i * 256 + tid;
            int tile = idx >> 9;
            int rem = idx & 511;
            int row = rem >> 2;
            int seg = rem & 3;
            const __nv_bfloat16* gp = srcs[tile] + (size_t)row * K + k0 + seg * 8;
            uint32_t sa = smem_base +
                (uint32_t)(s * STAGE_E + tile * TILE_E + row * BKP + seg * 8) * 2;
            asm volatile("cp.async.ca.shared.global [%0], [%1], 16;"
                         :: "r"(sa), "l"(gp));
        }
    };

    load_stage(0, 0);
    asm volatile("cp.async.commit_group;");

    for (int kb = 0; kb < nK; kb++) {
        const int cur = kb & 1;
        if (kb + 1 < nK) {
            load_stage(cur ^ 1, kb + 1);
            asm volatile("cp.async.commit_group;");
            asm volatile("cp.async.wait_group 1;");
        } else {
            asm volatile("cp.async.wait_group 0;");
        }
        __syncthreads();

        const uint32_t uAh = smem_base + (uint32_t)(cur * STAGE_E) * 2;
        const uint32_t uAl = uAh + (uint32_t)TILE_E * 2;
        const uint32_t uBh = uAh + (uint32_t)(2 * TILE_E) * 2;
        const uint32_t uBl = uAh + (uint32_t)(3 * TILE_E) * 2;

#pragma unroll
        for (int ks = 0; ks < 32; ks += 16) {
            uint32_t bh[4][2], bl[4][2];
#pragma unroll
            for (int np = 0; np < 2; np++) {
                uint32_t r4[4];
                uint32_t off = (uint32_t)((n0 + np * 16 + bRow) * BKP + ks + bCol) * 2;
                ldsm_x4(r4, uBh + off);
                bh[np * 2][0] = r4[0]; bh[np * 2][1] = r4[1];
                bh[np * 2 + 1][0] = r4[2]; bh[np * 2 + 1][1] = r4[3];
                ldsm_x4(r4, uBl + off);
                bl[np * 2][0] = r4[0]; bl[np * 2][1] = r4[1];
                bl[np * 2 + 1][0] = r4[2]; bl[np * 2 + 1][1] = r4[3];
            }
#pragma unroll
            for (int mi = 0; mi < 4; mi++) {
                uint32_t off = (uint32_t)((m0 + mi * 16 + aRow) * BKP + ks + aCol) * 2;
                uint32_t ah[4], al[4];
                ldsm_x4(ah, uAh + off);
                ldsm_x4(al, uAl + off);
#pragma unroll
                for (int ni = 0; ni < 4; ni++) {
                    mma_bf16(acc[mi][ni], ah, bh[ni]);
                    mma_bf16(acc[mi][ni], ah, bl[ni]);
                    mma_bf16(acc[mi][ni], al, bh[ni]);
                }
            }
        }
        __syncthreads();
    }

#pragma unroll
    for (int mi = 0; mi < 4; mi++) {
#pragma unroll
        for (int ni = 0; ni < 4; ni++) {
            int row = bm + m0 + mi * 16 + g;
            int col = bn + n0 + ni * 8 + t2;
            *(float2*)&C[(size_t)row * N + col] =
                make_float2(acc[mi][ni][0], acc[mi][ni][1]);
            *(float2*)&C[(size_t)(row + 8) * N + col] =
                make_float2(acc[mi][ni][2], acc[mi][ni][3]);
        }
    }
}

// ================= RoPE + RMSNorm -> bf16 hi/lo Q,K,V =======================
__global__ void rope_norm_kernel(const float* __restrict__ qw,
                                 const float* __restrict__ kw) {
    const int h = blockIdx.x, t = blockIdx.y, b = blockIdx.z;
    const int hd = threadIdx.x;
    __shared__ float sq[128], sk[128];
    __shared__ float red[8];

    const size_t row = (size_t)(b * Tt + t) * (3 * Dd);
    float qv = g_qkv[row + h * HDd + hd];
    float kv = g_qkv[row + Dd + h * HDd + hd];
    float vv = g_qkv[row + 2 * Dd + h * HDd + hd];
    sq[hd] = qv;
    sk[hd] = kv;
    __syncthreads();

    const int j = hd & 63;
    const int ci = (b * Tt + t) * 64 + j;
    const float c = g_cos[ci], s = g_sin[ci];
    float rq, rk;
    if (hd < 64) {
        rq = sq[hd] * c - sq[hd + 64] * s;
        rk = sk[hd] * c - sk[hd + 64] * s;
    } else {
        rq = sq[hd] * c + sq[hd - 64] * s;
        rk = sk[hd] * c + sk[hd - 64] * s;
    }
    float s2q = rq * rq, s2k = rk * rk;
#pragma unroll
    for (int m = 16; m >= 1; m >>= 1) {
        s2q += __shfl_xor_sync(0xffffffffu, s2q, m);
        s2k += __shfl_xor_sync(0xffffffffu, s2k, m);
    }
    const int w = hd >> 5;
    if ((hd & 31) == 0) { red[w] = s2q; red[4 + w] = s2k; }
    __syncthreads();
    float sumq = red[0] + red[1] + red[2] + red[3];
    float sumk = red[4] + red[5] + red[6] + red[7];
    float iq = rsqrtf(sumq * (1.0f / 128.0f) + 1e-6f);
    float ik = rsqrtf(sumk * (1.0f / 128.0f) + 1e-6f);

    const float qsc = 0.08838834764831845f;
    float qf = rq * iq * qw[hd] * qsc;
    float kf = rk * ik * kw[hd];

    const size_t o = (size_t)((b * Hh + h) * Tt + t) * HDd + hd;
    __nv_bfloat16 qh = __float2bfloat16(qf);
    __nv_bfloat16 kh = __float2bfloat16(kf);
    __nv_bfloat16 vh = __float2bfloat16(vv);
    g_qh[o] = qh;
    g_ql[o] = __float2bfloat16(qf - __bfloat162float(qh));
    g_kh[o] = kh;
    g_kl[o] = __float2bfloat16(kf - __bfloat162float(kh));
    g_vh[o] = vh;
    g_vl[o] = __float2bfloat16(vv - __bfloat162float(vh));
}

// ================= Tensor-core flash attention (causal, bf16x3, LDSM) =======
#define AP 136
#define PP 72
#define Q_E (128 * AP)
#define K_E (64 * AP)
#define VT_E (128 * PP)
#define P_E (128 * PP)
#define OFF_QH 0
#define OFF_QL (Q_E)
#define OFF_KH (2 * Q_E)
#define OFF_KL (2 * Q_E + K_E)
#define OFF_VTH (2 * Q_E + 2 * K_E)
#define OFF_VTL (2 * Q_E + 2 * K_E + VT_E)
#define OFF_PH (2 * Q_E + 2 * K_E + 2 * VT_E)
#define OFF_PL (2 * Q_E + 2 * K_E + 2 * VT_E + P_E)
#define ATTN_SMEM ((2 * Q_E + 2 * K_E + 2 * VT_E + 2 * P_E) * 2)  // 178176 B

__global__ __launch_bounds__(256, 1) void attn_mma_kernel() {
    extern __shared__ __align__(128) __nv_bfloat16 sma[];
    const int tid = threadIdx.x;
    const int lane = tid & 31;
    const int w = tid >> 5;
    const int g = lane >> 2;
    const int t2 = (lane & 3) * 2;
    const int qb = blockIdx.x, h = blockIdx.y, b = blockIdx.z;
    const int qg0 = qb * 128;
    const size_t hb = (size_t)(b * Hh + h) * Tt * HDd;
    const uint32_t sbase = smem_u32(sma);

    // ldmatrix lane-address components (same recipe as gemm)
    const int aRow = lane & 15;
    const int aCol = (lane >> 4) << 3;
    const int bRow = (lane & 7) + ((lane >> 4) << 3);
    const int bCol = lane & 8;

    {
        const __nv_bfloat16* qs[2] = {g_qh + hb + (size_t)qg0 * HDd,
                                      g_ql + hb + (size_t)qg0 * HDd};
#pragma unroll
        for (int i = 0; i < 16; i++) {
            int idx = tid + i * 256;
            int arr = idx >> 11;
            int rem = idx & 2047;
            int row = rem >> 4;
            int seg = rem & 15;
            uint4 v = *(const uint4*)(qs[arr] + (size_t)row * HDd + seg * 8);
            *(uint4*)(sma + arr * Q_E + row * AP + seg * 8) = v;
        }
    }

    float o[16][4];
#pragma unroll
    for (int ni = 0; ni < 16; ni++)
#pragma unroll
        for (int c = 0; c < 4; c++) o[ni][c] = 0.0f;
    float m_run[2] = {-1e30f, -1e30f}, l_run[2] = {0.0f, 0.0f};

    const int nkb = 2 * qb + 2;
    const int qwr = qg0 + w * 16;

    const uint32_t uQh = sbase + (uint32_t)OFF_QH * 2;
    const uint32_t uQl = sbase + (uint32_t)OFF_QL * 2;
    const uint32_t uKh = sbase + (uint32_t)OFF_KH * 2;
    const uint32_t uKl = sbase + (uint32_t)OFF_KL * 2;
    const uint32_t uVth = sbase + (uint32_t)OFF_VTH * 2;
    const uint32_t uVtl = sbase + (uint32_t)OFF_VTL * 2;
    const uint32_t uPh = sbase + (uint32_t)OFF_PH * 2;
    const uint32_t uPl = sbase + (uint32_t)OFF_PL * 2;

    for (int kb = 0; kb < nkb; kb++) {
        const int kg0 = kb * 64;
        __syncthreads();   // (a)

#pragma unroll
        for (int i = 0; i < 8; i++) {
            int idx = tid + i * 256;
            int arr = idx >> 10;
            int rem = idx & 1023;
            int row = rem >> 4;
            int seg = rem & 15;
            const __nv_bfloat16* gp = (arr ? g_kl : g_kh) + hb +
                                      (size_t)(kg0 + row) * HDd + seg * 8;
            uint32_t sa = sbase + (uint32_t)((arr ? OFF_KL : OFF_KH) +
                                             row * AP + seg * 8) * 2;
            asm volatile("cp.async.ca.shared.global [%0], [%1], 16;"
                         :: "r"(sa), "l"(gp));
        }
        asm volatile("cp.async.commit_group;");

#pragma unroll
        for (int i = 0; i < 8; i++) {
            int idx = tid + i * 256;
            int arr = idx >> 10, rem = idx & 1023;
            int dseg = rem >> 6, key = rem & 63;
            const __nv_bfloat16* gp = (arr ? g_vl : g_vh) + hb +
                                      (size_t)(kg0 + key) * HDd + dseg * 8;
            uint4 v = *(const uint4*)gp;
            const __nv_bfloat16* pv = (const __nv_bfloat16*)&v;
            __nv_bfloat16* dst = sma + (arr ? OFF_VTL : OFF_VTH);
#pragma unroll
            for (int j = 0; j < 8; j++)
                dst[(dseg * 8 + j) * PP + key] = pv[j];
        }
        asm volatile("cp.async.wait_group 0;");
        __syncthreads();   // (b)

        const bool active = (kg0 <= qwr + 15);
        if (active) {
            // ---- S = Q K^T (bf16x3), LDSM fragments ----
            float s[8][4];
#pragma unroll
            for (int ni = 0; ni < 8; ni++)
#pragma unroll
                for (int c = 0; c < 4; c++) s[ni][c] = 0.0f;

#pragma unroll
            for (int kc = 0; kc < 8; kc++) {
                const int colb = kc * 16;
                uint32_t offA = (uint32_t)((w * 16 + aRow) * AP + colb + aCol) * 2;
                uint32_t ah[4], al[4];
                ldsm_x4(ah, uQh + offA);
                ldsm_x4(al, uQl + offA);
#pragma unroll
                for (int np = 0; np < 4; np++) {
                    uint32_t offB = (uint32_t)((np * 16 + bRow) * AP + colb + bCol) * 2;
                    uint32_t r4[4];
                    uint32_t bhA[2], bhB[2], blA[2], blB[2];
                    ldsm_x4(r4, uKh + offB);
                    bhA[0] = r4[0]; bhA[1] = r4[1]; bhB[0] = r4[2]; bhB[1] = r4[3];
                    ldsm_x4(r4, uKl + offB);
                    blA[0] = r4[0]; blA[1] = r4[1]; blB[0] = r4[2]; blB[1] = r4[3];
                    mma_bf16(s[np * 2], ah, bhA);
                    mma_bf16(s[np * 2], ah, blA);
                    mma_bf16(s[np * 2], al, bhA);
                    mma_bf16(s[np * 2 + 1], ah, bhB);
                    mma_bf16(s[np * 2 + 1], ah, blB);
                    mma_bf16(s[np * 2 + 1], al, bhB);
                }
            }

            if (kg0 + 63 > qwr) {
#pragma unroll
                for (int ni = 0; ni < 8; ni++)
#pragma unroll
                    for (int c = 0; c < 4; c++) {
                        int key = kg0 + ni * 8 + t2 + (c & 1);
                        int qr = qwr + g + ((c & 2) ? 8 : 0);
                        if (key > qr) s[ni][c] = -1e30f;
                    }
            }

            __nv_bfloat16* sPh = sma + OFF_PH;
            __nv_bfloat16* sPl = sma + OFF_PL;
#pragma unroll
            for (int r = 0; r < 2; r++) {
                float mt = -1e30f;
#pragma unroll
                for (int ni = 0; ni < 8; ni++)
                    mt = fmaxf(mt, fmaxf(s[ni][2 * r], s[ni][2 * r + 1]));
                mt = fmaxf(mt, __shfl_xor_sync(0xffffffffu, mt, 1));
                mt = fmaxf(mt, __shfl_xor_sync(0xffffffffu, mt, 2));
                float mnew = fmaxf(m_run[r], mt);
                float corr = __expf(m_run[r] - mnew);
                m_run[r] = mnew;
                float psum = 0.0f;
                const int prow = w * 16 + g + r * 8;
#pragma unroll
                for (int ni = 0; ni < 8; ni++) {
                    float p0 = __expf(s[ni][2 * r] - mnew);
                    float p1 = __expf(s[ni][2 * r + 1] - mnew);
                    psum += p0 + p1;
                    __nv_bfloat162 h2 = __floats2bfloat162_rn(p0, p1);
                    float l0 = p0 - __bfloat162float(h2.x);
                    float l1 = p1 - __bfloat162float(h2.y);
                    __nv_bfloat162 l2 = __floats2bfloat162_rn(l0, l1);
                    *(uint32_t*)&sPh[prow * PP + ni * 8 + t2] = *(uint32_t*)&h2;
                    *(uint32_t*)&sPl[prow * PP + ni * 8 + t2] = *(uint32_t*)&l2;
                }
                psum += __shfl_xor_sync(0xffffffffu, psum, 1);
                psum += __shfl_xor_sync(0xffffffffu, psum, 2);
                l_run[r] = l_run[r] * corr + psum;
#pragma unroll
                for (int ni = 0; ni < 16; ni++) {
                    o[ni][2 * r] *= corr;
                    o[ni][2 * r + 1] *= corr;
                }
            }
        }
        __syncthreads();   // (c)

        if (active) {
            // ---- O += P Vt^T (bf16x3), LDSM fragments ----
#pragma unroll
            for (int kc = 0; kc < 4; kc++) {
                const int colb = kc * 16;
                uint32_t offA = (uint32_t)((w * 16 + aRow) * PP + colb + aCol) * 2;
                uint32_t ah[4], al[4];
                ldsm_x4(ah, uPh + offA);
                ldsm_x4(al, uPl + offA);
#pragma unroll
                for (int np = 0; np < 8; np++) {
                    uint32_t offB = (uint32_t)((np * 16 + bRow) * PP + colb + bCol) * 2;
                    uint32_t r4[4];
                    uint32_t bhA[2], bhB[2], blA[2], blB[2];
                    ldsm_x4(r4, uVth + offB);
                    bhA[0] = r4[0]; bhA[1] = r4[1]; bhB[0] = r4[2]; bhB[1] = r4[3];
                    ldsm_x4(r4, uVtl + offB);
                    blA[0] = r4[0]; blA[1] = r4[1]; blB[0] = r4[2]; blB[1] = r4[3];
                    mma_bf16(o[np * 2], ah, bhA);
                    mma_bf16(o[np * 2], ah, blA);
                    mma_bf16(o[np * 2], al, bhA);
                    mma_bf16(o[np * 2 + 1], ah, bhB);
                    mma_bf16(o[np * 2 + 1], ah, blB);
                    mma_bf16(o[np * 2 + 1], al, bhB);
                }
            }
        }
    }

    // ---- epilogue ----
#pragma unroll
    for (int r = 0; r < 2; r++) {
        float inv = 1.0f / l_run[r];
        int t = qg0 + w * 16 + g + r * 8;
        size_t rowo = (size_t)(b * Tt + t) * Dd + h * HDd;
#pragma unroll
        for (int ni = 0; ni < 16; ni++) {
            float v0 = o[ni][2 * r] * inv;
            float v1 = o[ni][2 * r + 1] * inv;
            __nv_bfloat162 h2 = __floats2bfloat162_rn(v0, v1);
            float l0 = v0 - __bfloat162float(h2.x);
            float l1 = v1 - __bfloat162float(h2.y);
            __nv_bfloat162 l2 = __floats2bfloat162_rn(l0, l1);
            *(uint32_t*)&g_aoh[rowo + ni * 8 + t2] = *(uint32_t*)&h2;
            *(uint32_t*)&g_aol[rowo + ni * 8 + t2] = *(uint32_t*)&l2;
        }
    }
}

// ================= launch ===================================================
extern "C" void kernel_launch(void* const* d_in, const int* in_sizes, int n_in,
                              void* d_out, int out_size) {
    const float* x = (const float*)d_in[0];
    const int* positions = (const int*)d_in[2];
    const float* qkv_w = (const float*)d_in[3];
    const float* out_w = (const float*)d_in[4];
    const float* q_norm_w = (const float*)d_in[5];
    const float* k_norm_w = (const float*)d_in[6];
    float* out = (float*)d_out;
    (void)in_sizes; (void)n_in; (void)out_size;

    void *p_qkv, *p_xh, *p_xl, *p_aoh, *p_aol, *p_wqh, *p_wql, *p_woh, *p_wol;
    cudaGetSymbolAddress(&p_qkv, g_qkv);
    cudaGetSymbolAddress(&p_xh, g_xh);
    cudaGetSymbolAddress(&p_xl, g_xl);
    cudaGetSymbolAddress(&p_aoh, g_aoh);
    cudaGetSymbolAddress(&p_aol, g_aol);
    cudaGetSymbolAddress(&p_wqh, g_wqh);
    cudaGetSymbolAddress(&p_wql, g_wql);
    cudaGetSymbolAddress(&p_woh, g_woh);
    cudaGetSymbolAddress(&p_wol, g_wol);

    static int attr_set = 0;
    if (!attr_set) {
        cudaFuncSetAttribute(gemm_mma_kernel, cudaFuncAttributeMaxDynamicSharedMemorySize, GEMM_SMEM);
        cudaFuncSetAttribute(attn_mma_kernel, cudaFuncAttributeMaxDynamicSharedMemorySize, ATTN_SMEM);
        attr_set = 1;
    }

    const int M = Bb * Tt;

    rope_table_kernel<<<(Bb * Tt * 64 + 255) / 256, 256>>>(positions);
    convert_split_kernel<<<(M * Dd / 4 + 255) / 256, 256>>>(
        x, (__nv_bfloat16*)p_xh, (__nv_bfloat16*)p_xl, M * Dd / 4);
    transpose_split_kernel<<<dim3(3 * Dd / 32, Dd / 32, 2), dim3(32, 8)>>>(qkv_w, out_w);
    gemm_mma_kernel<<<dim3(3 * Dd / 128, M / 128), 256, GEMM_SMEM>>>(
        (const __nv_bfloat16*)p_xh, (const __nv_bfloat16*)p_xl,
        (const __nv_bfloat16*)p_wqh, (const __nv_bfloat16*)p_wql,
        (float*)p_qkv, M, 3 * Dd, Dd);
    rope_norm_kernel<<<dim3(Hh, Tt, Bb), 128>>>(q_norm_w, k_norm_w);
    attn_mma_kernel<<<dim3(Tt / 128, Hh, Bb), 256, ATTN_SMEM>>>();
    gemm_mma_kernel<<<dim3(Dd / 128, M / 128), 256, GEMM_SMEM>>>(
        (const __nv_bfloat16*)p_aoh, (const __nv_bfloat16*)p_aol,
        (const __nv_bfloat16*)p_woh, (const __nv_bfloat16*)p_wol,
        out, M, Dd, Dd);
}

// round 12
// speedup vs baseline: 2.9420x; 1.0139x over previous
#include <cuda_runtime.h>
#include <cuda_bf16.h>
#include <math.h>
#include <stdint.h>

#define Bb 2
#define Tt 2048
#define Dd 2048
#define Hh 16
#define HDd 128

// ================= scratch ==================================================
__device__ float g_qkv[(size_t)Bb * Tt * 3 * Dd];
__device__ float g_cos[(size_t)Bb * Tt * 64];
__device__ float g_sin[(size_t)Bb * Tt * 64];
__device__ __nv_bfloat16 g_xh[(size_t)Bb * Tt * Dd];
__device__ __nv_bfloat16 g_xl[(size_t)Bb * Tt * Dd];
__device__ __nv_bfloat16 g_aoh[(size_t)Bb * Tt * Dd];
__device__ __nv_bfloat16 g_aol[(size_t)Bb * Tt * Dd];
__device__ __nv_bfloat16 g_wqh[(size_t)3 * Dd * Dd];
__device__ __nv_bfloat16 g_wql[(size_t)3 * Dd * Dd];
__device__ __nv_bfloat16 g_woh[(size_t)Dd * Dd];
__device__ __nv_bfloat16 g_wol[(size_t)Dd * Dd];
__device__ __nv_bfloat16 g_qh[(size_t)Bb * Hh * Tt * HDd];
__device__ __nv_bfloat16 g_ql[(size_t)Bb * Hh * Tt * HDd];
__device__ __nv_bfloat16 g_kh[(size_t)Bb * Hh * Tt * HDd];
__device__ __nv_bfloat16 g_kl[(size_t)Bb * Hh * Tt * HDd];
__device__ __nv_bfloat16 g_vh[(size_t)Bb * Hh * Tt * HDd];
__device__ __nv_bfloat16 g_vl[(size_t)Bb * Hh * Tt * HDd];

__device__ __forceinline__ uint32_t smem_u32(const void* p) {
    uint32_t a;
    asm("{ .reg .u64 t; cvta.to.shared.u64 t, %1; cvt.u32.u64 %0, t; }" : "=r"(a) : "l"(p));
    return a;
}

__device__ __forceinline__ void ldsm_x4(uint32_t* r, uint32_t addr) {
    asm volatile("ldmatrix.sync.aligned.m8n8.x4.shared.b16 {%0,%1,%2,%3}, [%4];"
                 : "=r"(r[0]), "=r"(r[1]), "=r"(r[2]), "=r"(r[3]) : "r"(addr));
}

// ================= RoPE table ==============================================
__global__ void rope_table_kernel(const int* __restrict__ positions) {
    int idx = blockIdx.x * blockDim.x + threadIdx.x;
    if (idx >= Bb * Tt * 64) return;
    int j = idx & 63;
    int bt = idx >> 6;
    int pos = positions[bt];
    float inv_freq = exp2f(-(float)j * (13.287712379549449f / 64.0f));
    float ang = (float)pos * inv_freq;
    float s, c;
    sincosf(ang, &s, &c);
    g_cos[idx] = c;
    g_sin[idx] = s;
}

// ================= split-convert (elementwise) ==============================
__global__ void convert_split_kernel(const float* __restrict__ in,
                                     __nv_bfloat16* __restrict__ oh,
                                     __nv_bfloat16* __restrict__ ol, int n4) {
    int i = blockIdx.x * blockDim.x + threadIdx.x;
    if (i >= n4) return;
    float4 v = ((const float4*)in)[i];
    __nv_bfloat16 hx = __float2bfloat16(v.x);
    __nv_bfloat16 hy = __float2bfloat16(v.y);
    __nv_bfloat16 hz = __float2bfloat16(v.z);
    __nv_bfloat16 hw = __float2bfloat16(v.w);
    __nv_bfloat16 lx = __float2bfloat16(v.x - __bfloat162float(hx));
    __nv_bfloat16 ly = __float2bfloat16(v.y - __bfloat162float(hy));
    __nv_bfloat16 lz = __float2bfloat16(v.z - __bfloat162float(hz));
    __nv_bfloat16 lw = __float2bfloat16(v.w - __bfloat162float(hw));
    ((__nv_bfloat162*)oh)[2 * i + 0] = __nv_bfloat162(hx, hy);
    ((__nv_bfloat162*)oh)[2 * i + 1] = __nv_bfloat162(hz, hw);
    ((__nv_bfloat162*)ol)[2 * i + 0] = __nv_bfloat162(lx, ly);
    ((__nv_bfloat162*)ol)[2 * i + 1] = __nv_bfloat162(lz, lw);
}

// ================= transpose + split convert (both weights) =================
__global__ void transpose_split_kernel(const float* __restrict__ W0,
                                       const float* __restrict__ W1) {
    __shared__ float t[32][33];
    int z = blockIdx.z;
    int Ncols = z ? Dd : 3 * Dd;
    const float* W = z ? W1 : W0;
    __nv_bfloat16* Th = z ? g_woh : g_wqh;
    __nv_bfloat16* Tl = z ? g_wol : g_wql;
    int n0 = blockIdx.x * 32, k0 = blockIdx.y * 32;
    if (n0 >= Ncols) return;
    int tx = threadIdx.x, ty = threadIdx.y;
#pragma unroll
    for (int i = ty; i < 32; i += 8)
        t[i][tx] = W[(size_t)(k0 + i) * Ncols + n0 + tx];
    __syncthreads();
#pragma unroll
    for (int i = ty; i < 32; i += 8) {
        float v = t[tx][i];
        __nv_bfloat16 h = __float2bfloat16(v);
        __nv_bfloat16 l = __float2bfloat16(v - __bfloat162float(h));
        size_t o = (size_t)(n0 + i) * Dd + k0 + tx;
        Th[o] = h;
        Tl[o] = l;
    }
}

// ================= mma.sync bf16x3 GEMM (LDSM, pass-major mma) ==============
#define BKP 40
#define TILE_E (128 * BKP)
#define STAGE_E (4 * TILE_E)
#define GEMM_SMEM (2 * STAGE_E * 2)

__device__ __forceinline__ void mma_bf16(float* d, const uint32_t* a, const uint32_t* b) {
    asm volatile(
        "mma.sync.aligned.m16n8k16.row.col.f32.bf16.bf16.f32 "
        "{%0,%1,%2,%3}, {%4,%5,%6,%7}, {%8,%9}, {%0,%1,%2,%3};"
        : "+f"(d[0]), "+f"(d[1]), "+f"(d[2]), "+f"(d[3])
        : "r"(a[0]), "r"(a[1]), "r"(a[2]), "r"(a[3]), "r"(b[0]), "r"(b[1]));
}

__global__ __launch_bounds__(256, 2) void gemm_mma_kernel(
    const __nv_bfloat16* __restrict__ Ah, const __nv_bfloat16* __restrict__ Al,
    const __nv_bfloat16* __restrict__ Bh, const __nv_bfloat16* __restrict__ Bl,
    float* __restrict__ C, int M, int N, int K) {
    extern __shared__ __align__(128) __nv_bfloat16 smem[];
    const int tid = threadIdx.x;
    const int lane = tid & 31;
    const int wid = tid >> 5;
    const int g = lane >> 2;
    const int t2 = (lane & 3) * 2;
    const int wm = wid & 1, wn = wid >> 1;
    const int m0 = wm * 64, n0 = wn * 32;
    const int bm = blockIdx.y * 128;
    const int bn = blockIdx.x * 128;

    const __nv_bfloat16* srcs[4] = {Ah + (size_t)bm * K, Al + (size_t)bm * K,
                                    Bh + (size_t)bn * K, Bl + (size_t)bn * K};

    uint32_t smem_base = smem_u32(smem);

    const int aRow = lane & 15;
    const int aCol = (lane >> 4) << 3;
    const int bRow = (lane & 7) + ((lane >> 4) << 3);
    const int bCol = lane & 8;

    float acc[4][4][4];
#pragma unroll
    for (int mi = 0; mi < 4; mi++)
#pragma unroll
        for (int ni = 0; ni < 4; ni++)
#pragma unroll
            for (int c = 0; c < 4; c++) acc[mi][ni][c] = 0.0f;

    const int nK = K >> 5;

    auto load_stage = [&](int s, int kb) {
        const int k0 = kb * 32;
#pragma unroll
        for (int i = 0; i < 8; i++) {
            int idx = i * 256 + tid;
            int tile = idx >> 9;
            int rem = idx & 511;
            int row = rem >> 2;
            int seg = rem & 3;
            const __nv_bfloat16* gp = srcs[tile] + (size_t)row * K + k0 + seg * 8;
            uint32_t sa = smem_base +
                (uint32_t)(s * STAGE_E + tile * TILE_E + row * BKP + seg * 8) * 2;
            asm volatile("cp.async.ca.shared.global [%0], [%1], 16;"
                         :: "r"(sa), "l"(gp));
        }
    };

    load_stage(0, 0);
    asm volatile("cp.async.commit_group;");

    for (int kb = 0; kb < nK; kb++) {
        const int cur = kb & 1;
        if (kb + 1 < nK) {
            load_stage(cur ^ 1, kb + 1);
            asm volatile("cp.async.commit_group;");
            asm volatile("cp.async.wait_group 1;");
        } else {
            asm volatile("cp.async.wait_group 0;");
        }
        __syncthreads();

        const uint32_t uAh = smem_base + (uint32_t)(cur * STAGE_E) * 2;
        const uint32_t uAl = uAh + (uint32_t)TILE_E * 2;
        const uint32_t uBh = uAh + (uint32_t)(2 * TILE_E) * 2;
        const uint32_t uBl = uAh + (uint32_t)(3 * TILE_E) * 2;

#pragma unroll
        for (int ks = 0; ks < 32; ks += 16) {
            uint32_t bh[4][2], bl[4][2];
#pragma unroll
            for (int np = 0; np < 2; np++) {
                uint32_t r4[4];
                uint32_t off = (uint32_t)((n0 + np * 16 + bRow) * BKP + ks + bCol) * 2;
                ldsm_x4(r4, uBh + off);
                bh[np * 2][0] = r4[0]; bh[np * 2][1] = r4[1];
                bh[np * 2 + 1][0] = r4[2]; bh[np * 2 + 1][1] = r4[3];
                ldsm_x4(r4, uBl + off);
                bl[np * 2][0] = r4[0]; bl[np * 2][1] = r4[1];
                bl[np * 2 + 1][0] = r4[2]; bl[np * 2 + 1][1] = r4[3];
            }
#pragma unroll
            for (int mi = 0; mi < 4; mi++) {
                uint32_t off = (uint32_t)((m0 + mi * 16 + aRow) * BKP + ks + aCol) * 2;
                uint32_t ah[4], al[4];
                ldsm_x4(ah, uAh + off);
                ldsm_x4(al, uAl + off);
                // pass-major: 4 independent mma between revisits of any acc
#pragma unroll
                for (int ni = 0; ni < 4; ni++) mma_bf16(acc[mi][ni], ah, bh[ni]);
#pragma unroll
                for (int ni = 0; ni < 4; ni++) mma_bf16(acc[mi][ni], ah, bl[ni]);
#pragma unroll
                for (int ni = 0; ni < 4; ni++) mma_bf16(acc[mi][ni], al, bh[ni]);
            }
        }
        __syncthreads();
    }

#pragma unroll
    for (int mi = 0; mi < 4; mi++) {
#pragma unroll
        for (int ni = 0; ni < 4; ni++) {
            int row = bm + m0 + mi * 16 + g;
            int col = bn + n0 + ni * 8 + t2;
            *(float2*)&C[(size_t)row * N + col] =
                make_float2(acc[mi][ni][0], acc[mi][ni][1]);
            *(float2*)&C[(size_t)(row + 8) * N + col] =
                make_float2(acc[mi][ni][2], acc[mi][ni][3]);
        }
    }
}

// ================= RoPE + RMSNorm -> bf16 hi/lo Q,K,V =======================
__global__ void rope_norm_kernel(const float* __restrict__ qw,
                                 const float* __restrict__ kw) {
    const int h = blockIdx.x, t = blockIdx.y, b = blockIdx.z;
    const int hd = threadIdx.x;
    __shared__ float sq[128], sk[128];
    __shared__ float red[8];

    const size_t row = (size_t)(b * Tt + t) * (3 * Dd);
    float qv = g_qkv[row + h * HDd + hd];
    float kv = g_qkv[row + Dd + h * HDd + hd];
    float vv = g_qkv[row + 2 * Dd + h * HDd + hd];
    sq[hd] = qv;
    sk[hd] = kv;
    __syncthreads();

    const int j = hd & 63;
    const int ci = (b * Tt + t) * 64 + j;
    const float c = g_cos[ci], s = g_sin[ci];
    float rq, rk;
    if (hd < 64) {
        rq = sq[hd] * c - sq[hd + 64] * s;
        rk = sk[hd] * c - sk[hd + 64] * s;
    } else {
        rq = sq[hd] * c + sq[hd - 64] * s;
        rk = sk[hd] * c + sk[hd - 64] * s;
    }
    float s2q = rq * rq, s2k = rk * rk;
#pragma unroll
    for (int m = 16; m >= 1; m >>= 1) {
        s2q += __shfl_xor_sync(0xffffffffu, s2q, m);
        s2k += __shfl_xor_sync(0xffffffffu, s2k, m);
    }
    const int w = hd >> 5;
    if ((hd & 31) == 0) { red[w] = s2q; red[4 + w] = s2k; }
    __syncthreads();
    float sumq = red[0] + red[1] + red[2] + red[3];
    float sumk = red[4] + red[5] + red[6] + red[7];
    float iq = rsqrtf(sumq * (1.0f / 128.0f) + 1e-6f);
    float ik = rsqrtf(sumk * (1.0f / 128.0f) + 1e-6f);

    const float qsc = 0.08838834764831845f;
    float qf = rq * iq * qw[hd] * qsc;
    float kf = rk * ik * kw[hd];

    const size_t o = (size_t)((b * Hh + h) * Tt + t) * HDd + hd;
    __nv_bfloat16 qh = __float2bfloat16(qf);
    __nv_bfloat16 kh = __float2bfloat16(kf);
    __nv_bfloat16 vh = __float2bfloat16(vv);
    g_qh[o] = qh;
    g_ql[o] = __float2bfloat16(qf - __bfloat162float(qh));
    g_kh[o] = kh;
    g_kl[o] = __float2bfloat16(kf - __bfloat162float(kh));
    g_vh[o] = vh;
    g_vl[o] = __float2bfloat16(vv - __bfloat162float(vh));
}

// ================= Tensor-core flash attention (pass-major mma) =============
#define AP 136
#define PP 72
#define Q_E (128 * AP)
#define K_E (64 * AP)
#define VT_E (128 * PP)
#define P_E (128 * PP)
#define OFF_QH 0
#define OFF_QL (Q_E)
#define OFF_KH (2 * Q_E)
#define OFF_KL (2 * Q_E + K_E)
#define OFF_VTH (2 * Q_E + 2 * K_E)
#define OFF_VTL (2 * Q_E + 2 * K_E + VT_E)
#define OFF_PH (2 * Q_E + 2 * K_E + 2 * VT_E)
#define OFF_PL (2 * Q_E + 2 * K_E + 2 * VT_E + P_E)
#define ATTN_SMEM ((2 * Q_E + 2 * K_E + 2 * VT_E + 2 * P_E) * 2)  // 178176 B

__global__ __launch_bounds__(256, 1) void attn_mma_kernel() {
    extern __shared__ __align__(128) __nv_bfloat16 sma[];
    const int tid = threadIdx.x;
    const int lane = tid & 31;
    const int w = tid >> 5;
    const int g = lane >> 2;
    const int t2 = (lane & 3) * 2;
    const int qb = blockIdx.x, h = blockIdx.y, b = blockIdx.z;
    const int qg0 = qb * 128;
    const size_t hb = (size_t)(b * Hh + h) * Tt * HDd;
    const uint32_t sbase = smem_u32(sma);

    const int aRow = lane & 15;
    const int aCol = (lane >> 4) << 3;
    const int bRow = (lane & 7) + ((lane >> 4) << 3);
    const int bCol = lane & 8;

    {
        const __nv_bfloat16* qs[2] = {g_qh + hb + (size_t)qg0 * HDd,
                                      g_ql + hb + (size_t)qg0 * HDd};
#pragma unroll
        for (int i = 0; i < 16; i++) {
            int idx = tid + i * 256;
            int arr = idx >> 11;
            int rem = idx & 2047;
            int row = rem >> 4;
            int seg = rem & 15;
            uint4 v = *(const uint4*)(qs[arr] + (size_t)row * HDd + seg * 8);
            *(uint4*)(sma + arr * Q_E + row * AP + seg * 8) = v;
        }
    }

    float o[16][4];
#pragma unroll
    for (int ni = 0; ni < 16; ni++)
#pragma unroll
        for (int c = 0; c < 4; c++) o[ni][c] = 0.0f;
    float m_run[2] = {-1e30f, -1e30f}, l_run[2] = {0.0f, 0.0f};

    const int nkb = 2 * qb + 2;
    const int qwr = qg0 + w * 16;

    const uint32_t uQh = sbase + (uint32_t)OFF_QH * 2;
    const uint32_t uQl = sbase + (uint32_t)OFF_QL * 2;
    const uint32_t uKh = sbase + (uint32_t)OFF_KH * 2;
    const uint32_t uKl = sbase + (uint32_t)OFF_KL * 2;
    const uint32_t uVth = sbase + (uint32_t)OFF_VTH * 2;
    const uint32_t uVtl = sbase + (uint32_t)OFF_VTL * 2;
    const uint32_t uPh = sbase + (uint32_t)OFF_PH * 2;
    const uint32_t uPl = sbase + (uint32_t)OFF_PL * 2;

    for (int kb = 0; kb < nkb; kb++) {
        const int kg0 = kb * 64;
        __syncthreads();   // (a)

#pragma unroll
        for (int i = 0; i < 8; i++) {
            int idx = tid + i * 256;
            int arr = idx >> 10;
            int rem = idx & 1023;
            int row = rem >> 4;
            int seg = rem & 15;
            const __nv_bfloat16* gp = (arr ? g_kl : g_kh) + hb +
                                      (size_t)(kg0 + row) * HDd + seg * 8;
            uint32_t sa = sbase + (uint32_t)((arr ? OFF_KL : OFF_KH) +
                                             row * AP + seg * 8) * 2;
            asm volatile("cp.async.ca.shared.global [%0], [%1], 16;"
                         :: "r"(sa), "l"(gp));
        }
        asm volatile("cp.async.commit_group;");

#pragma unroll
        for (int i = 0; i < 8; i++) {
            int idx = tid + i * 256;
            int arr = idx >> 10, rem = idx & 1023;
            int dseg = rem >> 6, key = rem & 63;
            const __nv_bfloat16* gp = (arr ? g_vl : g_vh) + hb +
                                      (size_t)(kg0 + key) * HDd + dseg * 8;
            uint4 v = *(const uint4*)gp;
            const __nv_bfloat16* pv = (const __nv_bfloat16*)&v;
            __nv_bfloat16* dst = sma + (arr ? OFF_VTL : OFF_VTH);
#pragma unroll
            for (int j = 0; j < 8; j++)
                dst[(dseg * 8 + j) * PP + key] = pv[j];
        }
        asm volatile("cp.async.wait_group 0;");
        __syncthreads();   // (b)

        const bool active = (kg0 <= qwr + 15);
        if (active) {
            // ---- S = Q K^T (bf16x3), hoisted K frags + pass-major mma ----
            float s[8][4];
#pragma unroll
            for (int ni = 0; ni < 8; ni++)
#pragma unroll
                for (int c = 0; c < 4; c++) s[ni][c] = 0.0f;

#pragma unroll
            for (int kc = 0; kc < 8; kc++) {
                const int colb = kc * 16;
                uint32_t offA = (uint32_t)((w * 16 + aRow) * AP + colb + aCol) * 2;
                uint32_t ah[4], al[4];
                ldsm_x4(ah, uQh + offA);
                ldsm_x4(al, uQl + offA);
                uint32_t kbh[8][2], kbl[8][2];
#pragma unroll
                for (int np = 0; np < 4; np++) {
                    uint32_t offB = (uint32_t)((np * 16 + bRow) * AP + colb + bCol) * 2;
                    uint32_t r4[4];
                    ldsm_x4(r4, uKh + offB);
                    kbh[np * 2][0] = r4[0]; kbh[np * 2][1] = r4[1];
                    kbh[np * 2 + 1][0] = r4[2]; kbh[np * 2 + 1][1] = r4[3];
                    ldsm_x4(r4, uKl + offB);
                    kbl[np * 2][0] = r4[0]; kbl[np * 2][1] = r4[1];
                    kbl[np * 2 + 1][0] = r4[2]; kbl[np * 2 + 1][1] = r4[3];
                }
#pragma unroll
                for (int ni = 0; ni < 8; ni++) mma_bf16(s[ni], ah, kbh[ni]);
#pragma unroll
                for (int ni = 0; ni < 8; ni++) mma_bf16(s[ni], ah, kbl[ni]);
#pragma unroll
                for (int ni = 0; ni < 8; ni++) mma_bf16(s[ni], al, kbh[ni]);
            }

            if (kg0 + 63 > qwr) {
#pragma unroll
                for (int ni = 0; ni < 8; ni++)
#pragma unroll
                    for (int c = 0; c < 4; c++) {
                        int key = kg0 + ni * 8 + t2 + (c & 1);
                        int qr = qwr + g + ((c & 2) ? 8 : 0);
                        if (key > qr) s[ni][c] = -1e30f;
                    }
            }

            __nv_bfloat16* sPh = sma + OFF_PH;
            __nv_bfloat16* sPl = sma + OFF_PL;
#pragma unroll
            for (int r = 0; r < 2; r++) {
                float mt = -1e30f;
#pragma unroll
                for (int ni = 0; ni < 8; ni++)
                    mt = fmaxf(mt, fmaxf(s[ni][2 * r], s[ni][2 * r + 1]));
                mt = fmaxf(mt, __shfl_xor_sync(0xffffffffu, mt, 1));
                mt = fmaxf(mt, __shfl_xor_sync(0xffffffffu, mt, 2));
                float mnew = fmaxf(m_run[r], mt);
                float corr = __expf(m_run[r] - mnew);
                m_run[r] = mnew;
                float psum = 0.0f;
                const int prow = w * 16 + g + r * 8;
#pragma unroll
                for (int ni = 0; ni < 8; ni++) {
                    float p0 = __expf(s[ni][2 * r] - mnew);
                    float p1 = __expf(s[ni][2 * r + 1] - mnew);
                    psum += p0 + p1;
                    __nv_bfloat162 h2 = __floats2bfloat162_rn(p0, p1);
                    float l0 = p0 - __bfloat162float(h2.x);
                    float l1 = p1 - __bfloat162float(h2.y);
                    __nv_bfloat162 l2 = __floats2bfloat162_rn(l0, l1);
                    *(uint32_t*)&sPh[prow * PP + ni * 8 + t2] = *(uint32_t*)&h2;
                    *(uint32_t*)&sPl[prow * PP + ni * 8 + t2] = *(uint32_t*)&l2;
                }
                psum += __shfl_xor_sync(0xffffffffu, psum, 1);
                psum += __shfl_xor_sync(0xffffffffu, psum, 2);
                l_run[r] = l_run[r] * corr + psum;
#pragma unroll
                for (int ni = 0; ni < 16; ni++) {
                    o[ni][2 * r] *= corr;
                    o[ni][2 * r + 1] *= corr;
                }
            }
        }
        __syncthreads();   // (c)

        if (active) {
            // ---- O += P Vt^T (bf16x3), hoisted V frags + pass-major mma ----
#pragma unroll
            for (int kc = 0; kc < 4; kc++) {
                const int colb = kc * 16;
                uint32_t offA = (uint32_t)((w * 16 + aRow) * PP + colb + aCol) * 2;
                uint32_t ah[4], al[4];
                ldsm_x4(ah, uPh + offA);
                ldsm_x4(al, uPl + offA);
#pragma unroll
                for (int half = 0; half < 2; half++) {
                    uint32_t vbh[8][2], vbl[8][2];
#pragma unroll
                    for (int np = 0; np < 4; np++) {
                        uint32_t offB = (uint32_t)(((half * 4 + np) * 16 + bRow) * PP +
                                                   colb + bCol) * 2;
                        uint32_t r4[4];
                        ldsm_x4(r4, uVth + offB);
                        vbh[np * 2][0] = r4[0]; vbh[np * 2][1] = r4[1];
                        vbh[np * 2 + 1][0] = r4[2]; vbh[np * 2 + 1][1] = r4[3];
                        ldsm_x4(r4, uVtl + offB);
                        vbl[np * 2][0] = r4[0]; vbl[np * 2][1] = r4[1];
                        vbl[np * 2 + 1][0] = r4[2]; vbl[np * 2 + 1][1] = r4[3];
                    }
                    float (*oh)[4] = &o[half * 8];
#pragma unroll
                    for (int ni = 0; ni < 8; ni++) mma_bf16(oh[ni], ah, vbh[ni]);
#pragma unroll
                    for (int ni = 0; ni < 8; ni++) mma_bf16(oh[ni], ah, vbl[ni]);
#pragma unroll
                    for (int ni = 0; ni < 8; ni++) mma_bf16(oh[ni], al, vbh[ni]);
                }
            }
        }
    }

    // ---- epilogue ----
#pragma unroll
    for (int r = 0; r < 2; r++) {
        float inv = 1.0f / l_run[r];
        int t = qg0 + w * 16 + g + r * 8;
        size_t rowo = (size_t)(b * Tt + t) * Dd + h * HDd;
#pragma unroll
        for (int ni = 0; ni < 16; ni++) {
            float v0 = o[ni][2 * r] * inv;
            float v1 = o[ni][2 * r + 1] * inv;
            __nv_bfloat162 h2 = __floats2bfloat162_rn(v0, v1);
            float l0 = v0 - __bfloat162float(h2.x);
            float l1 = v1 - __bfloat162float(h2.y);
            __nv_bfloat162 l2 = __floats2bfloat162_rn(l0, l1);
            *(uint32_t*)&g_aoh[rowo + ni * 8 + t2] = *(uint32_t*)&h2;
            *(uint32_t*)&g_aol[rowo + ni * 8 + t2] = *(uint32_t*)&l2;
        }
    }
}

// ================= launch ===================================================
extern "C" void kernel_launch(void* const* d_in, const int* in_sizes, int n_in,
                              void* d_out, int out_size) {
    const float* x = (const float*)d_in[0];
    const int* positions = (const int*)d_in[2];
    const float* qkv_w = (const float*)d_in[3];
    const float* out_w = (const float*)d_in[4];
    const float* q_norm_w = (const float*)d_in[5];
    const float* k_norm_w = (const float*)d_in[6];
    float* out = (float*)d_out;
    (void)in_sizes; (void)n_in; (void)out_size;

    void *p_qkv, *p_xh, *p_xl, *p_aoh, *p_aol, *p_wqh, *p_wql, *p_woh, *p_wol;
    cudaGetSymbolAddress(&p_qkv, g_qkv);
    cudaGetSymbolAddress(&p_xh, g_xh);
    cudaGetSymbolAddress(&p_xl, g_xl);
    cudaGetSymbolAddress(&p_aoh, g_aoh);
    cudaGetSymbolAddress(&p_aol, g_aol);
    cudaGetSymbolAddress(&p_wqh, g_wqh);
    cudaGetSymbolAddress(&p_wql, g_wql);
    cudaGetSymbolAddress(&p_woh, g_woh);
    cudaGetSymbolAddress(&p_wol, g_wol);

    static int attr_set = 0;
    if (!attr_set) {
        cudaFuncSetAttribute(gemm_mma_kernel, cudaFuncAttributeMaxDynamicSharedMemorySize, GEMM_SMEM);
        cudaFuncSetAttribute(attn_mma_kernel, cudaFuncAttributeMaxDynamicSharedMemorySize, ATTN_SMEM);
        attr_set = 1;
    }

    const int M = Bb * Tt;

    rope_table_kernel<<<(Bb * Tt * 64 + 255) / 256, 256>>>(positions);
    convert_split_kernel<<<(M * Dd / 4 + 255) / 256, 256>>>(
        x, (__nv_bfloat16*)p_xh, (__nv_bfloat16*)p_xl, M * Dd / 4);
    transpose_split_kernel<<<dim3(3 * Dd / 32, Dd / 32, 2), dim3(32, 8)>>>(qkv_w, out_w);
    gemm_mma_kernel<<<dim3(3 * Dd / 128, M / 128), 256, GEMM_SMEM>>>(
        (const __nv_bfloat16*)p_xh, (const __nv_bfloat16*)p_xl,
        (const __nv_bfloat16*)p_wqh, (const __nv_bfloat16*)p_wql,
        (float*)p_qkv, M, 3 * Dd, Dd);
    rope_norm_kernel<<<dim3(Hh, Tt, Bb), 128>>>(q_norm_w, k_norm_w);
    attn_mma_kernel<<<dim3(Tt / 128, Hh, Bb), 256, ATTN_SMEM>>>();
    gemm_mma_kernel<<<dim3(Dd / 128, M / 128), 256, GEMM_SMEM>>>(
        (const __nv_bfloat16*)p_aoh, (const __nv_bfloat16*)p_aol,
        (const __nv_bfloat16*)p_woh, (const __nv_bfloat16*)p_wol,
        out, M, Dd, Dd);
}

// round 13
// speedup vs baseline: 3.1273x; 1.0630x over previous
#include <cuda_runtime.h>
#include <cuda_bf16.h>
#include <math.h>
#include <stdint.h>

#define Bb 2
#define Tt 2048
#define Dd 2048
#define Hh 16
#define HDd 128

// ================= scratch ==================================================
__device__ float g_qkv[(size_t)Bb * Tt * 3 * Dd];
__device__ float g_cos[(size_t)Bb * Tt * 64];
__device__ float g_sin[(size_t)Bb * Tt * 64];
__device__ __nv_bfloat16 g_xh[(size_t)Bb * Tt * Dd];
__device__ __nv_bfloat16 g_xl[(size_t)Bb * Tt * Dd];
__device__ __nv_bfloat16 g_aoh[(size_t)Bb * Tt * Dd];
__device__ __nv_bfloat16 g_aol[(size_t)Bb * Tt * Dd];
__device__ __nv_bfloat16 g_wqh[(size_t)3 * Dd * Dd];
__device__ __nv_bfloat16 g_wql[(size_t)3 * Dd * Dd];
__device__ __nv_bfloat16 g_woh[(size_t)Dd * Dd];
__device__ __nv_bfloat16 g_wol[(size_t)Dd * Dd];
__device__ __nv_bfloat16 g_qh[(size_t)Bb * Hh * Tt * HDd];
__device__ __nv_bfloat16 g_ql[(size_t)Bb * Hh * Tt * HDd];
__device__ __nv_bfloat16 g_kh[(size_t)Bb * Hh * Tt * HDd];
__device__ __nv_bfloat16 g_kl[(size_t)Bb * Hh * Tt * HDd];
__device__ __nv_bfloat16 g_vh[(size_t)Bb * Hh * Tt * HDd];
__device__ __nv_bfloat16 g_vl[(size_t)Bb * Hh * Tt * HDd];

__device__ __forceinline__ uint32_t smem_u32(const void* p) {
    uint32_t a;
    asm("{ .reg .u64 t; cvta.to.shared.u64 t, %1; cvt.u32.u64 %0, t; }" : "=r"(a) : "l"(p));
    return a;
}

__device__ __forceinline__ void ldsm_x4(uint32_t* r, uint32_t addr) {
    asm volatile("ldmatrix.sync.aligned.m8n8.x4.shared.b16 {%0,%1,%2,%3}, [%4];"
                 : "=r"(r[0]), "=r"(r[1]), "=r"(r[2]), "=r"(r[3]) : "r"(addr));
}

__device__ __forceinline__ void ldsm_x4_trans(uint32_t* r, uint32_t addr) {
    asm volatile("ldmatrix.sync.aligned.m8n8.x4.trans.shared.b16 {%0,%1,%2,%3}, [%4];"
                 : "=r"(r[0]), "=r"(r[1]), "=r"(r[2]), "=r"(r[3]) : "r"(addr));
}

// ================= RoPE table ==============================================
__global__ void rope_table_kernel(const int* __restrict__ positions) {
    int idx = blockIdx.x * blockDim.x + threadIdx.x;
    if (idx >= Bb * Tt * 64) return;
    int j = idx & 63;
    int bt = idx >> 6;
    int pos = positions[bt];
    float inv_freq = exp2f(-(float)j * (13.287712379549449f / 64.0f));
    float ang = (float)pos * inv_freq;
    float s, c;
    sincosf(ang, &s, &c);
    g_cos[idx] = c;
    g_sin[idx] = s;
}

// ================= split-convert (elementwise) ==============================
__global__ void convert_split_kernel(const float* __restrict__ in,
                                     __nv_bfloat16* __restrict__ oh,
                                     __nv_bfloat16* __restrict__ ol, int n4) {
    int i = blockIdx.x * blockDim.x + threadIdx.x;
    if (i >= n4) return;
    float4 v = ((const float4*)in)[i];
    __nv_bfloat16 hx = __float2bfloat16(v.x);
    __nv_bfloat16 hy = __float2bfloat16(v.y);
    __nv_bfloat16 hz = __float2bfloat16(v.z);
    __nv_bfloat16 hw = __float2bfloat16(v.w);
    __nv_bfloat16 lx = __float2bfloat16(v.x - __bfloat162float(hx));
    __nv_bfloat16 ly = __float2bfloat16(v.y - __bfloat162float(hy));
    __nv_bfloat16 lz = __float2bfloat16(v.z - __bfloat162float(hz));
    __nv_bfloat16 lw = __float2bfloat16(v.w - __bfloat162float(hw));
    ((__nv_bfloat162*)oh)[2 * i + 0] = __nv_bfloat162(hx, hy);
    ((__nv_bfloat162*)oh)[2 * i + 1] = __nv_bfloat162(hz, hw);
    ((__nv_bfloat162*)ol)[2 * i + 0] = __nv_bfloat162(lx, ly);
    ((__nv_bfloat162*)ol)[2 * i + 1] = __nv_bfloat162(lz, lw);
}

// ================= transpose + split convert (both weights) =================
__global__ void transpose_split_kernel(const float* __restrict__ W0,
                                       const float* __restrict__ W1) {
    __shared__ float t[32][33];
    int z = blockIdx.z;
    int Ncols = z ? Dd : 3 * Dd;
    const float* W = z ? W1 : W0;
    __nv_bfloat16* Th = z ? g_woh : g_wqh;
    __nv_bfloat16* Tl = z ? g_wol : g_wql;
    int n0 = blockIdx.x * 32, k0 = blockIdx.y * 32;
    if (n0 >= Ncols) return;
    int tx = threadIdx.x, ty = threadIdx.y;
#pragma unroll
    for (int i = ty; i < 32; i += 8)
        t[i][tx] = W[(size_t)(k0 + i) * Ncols + n0 + tx];
    __syncthreads();
#pragma unroll
    for (int i = ty; i < 32; i += 8) {
        float v = t[tx][i];
        __nv_bfloat16 h = __float2bfloat16(v);
        __nv_bfloat16 l = __float2bfloat16(v - __bfloat162float(h));
        size_t o = (size_t)(n0 + i) * Dd + k0 + tx;
        Th[o] = h;
        Tl[o] = l;
    }
}

// ================= mma.sync bf16x3 GEMM (LDSM, unchanged) ===================
#define BKP 40
#define TILE_E (128 * BKP)
#define STAGE_E (4 * TILE_E)
#define GEMM_SMEM (2 * STAGE_E * 2)

__device__ __forceinline__ void mma_bf16(float* d, const uint32_t* a, const uint32_t* b) {
    asm volatile(
        "mma.sync.aligned.m16n8k16.row.col.f32.bf16.bf16.f32 "
        "{%0,%1,%2,%3}, {%4,%5,%6,%7}, {%8,%9}, {%0,%1,%2,%3};"
        : "+f"(d[0]), "+f"(d[1]), "+f"(d[2]), "+f"(d[3])
        : "r"(a[0]), "r"(a[1]), "r"(a[2]), "r"(a[3]), "r"(b[0]), "r"(b[1]));
}

__global__ __launch_bounds__(256, 2) void gemm_mma_kernel(
    const __nv_bfloat16* __restrict__ Ah, const __nv_bfloat16* __restrict__ Al,
    const __nv_bfloat16* __restrict__ Bh, const __nv_bfloat16* __restrict__ Bl,
    float* __restrict__ C, int M, int N, int K) {
    extern __shared__ __align__(128) __nv_bfloat16 smem[];
    const int tid = threadIdx.x;
    const int lane = tid & 31;
    const int wid = tid >> 5;
    const int g = lane >> 2;
    const int t2 = (lane & 3) * 2;
    const int wm = wid & 1, wn = wid >> 1;
    const int m0 = wm * 64, n0 = wn * 32;
    const int bm = blockIdx.y * 128;
    const int bn = blockIdx.x * 128;

    const __nv_bfloat16* srcs[4] = {Ah + (size_t)bm * K, Al + (size_t)bm * K,
                                    Bh + (size_t)bn * K, Bl + (size_t)bn * K};

    uint32_t smem_base = smem_u32(smem);

    const int aRow = lane & 15;
    const int aCol = (lane >> 4) << 3;
    const int bRow = (lane & 7) + ((lane >> 4) << 3);
    const int bCol = lane & 8;

    float acc[4][4][4];
#pragma unroll
    for (int mi = 0; mi < 4; mi++)
#pragma unroll
        for (int ni = 0; ni < 4; ni++)
#pragma unroll
            for (int c = 0; c < 4; c++) acc[mi][ni][c] = 0.0f;

    const int nK = K >> 5;

    auto load_stage = [&](int s, int kb) {
        const int k0 = kb * 32;
#pragma unroll
        for (int i = 0; i < 8; i++) {
            int idx = i * 256 + tid;
            int tile = idx >> 9;
            int rem = idx & 511;
            int row = rem >> 2;
            int seg = rem & 3;
            const __nv_bfloat16* gp = srcs[tile] + (size_t)row * K + k0 + seg * 8;
            uint32_t sa = smem_base +
                (uint32_t)(s * STAGE_E + tile * TILE_E + row * BKP + seg * 8) * 2;
            asm volatile("cp.async.ca.shared.global [%0], [%1], 16;"
                         :: "r"(sa), "l"(gp));
        }
    };

    load_stage(0, 0);
    asm volatile("cp.async.commit_group;");

    for (int kb = 0; kb < nK; kb++) {
        const int cur = kb & 1;
        if (kb + 1 < nK) {
            load_stage(cur ^ 1, kb + 1);
            asm volatile("cp.async.commit_group;");
            asm volatile("cp.async.wait_group 1;");
        } else {
            asm volatile("cp.async.wait_group 0;");
        }
        __syncthreads();

        const uint32_t uAh = smem_base + (uint32_t)(cur * STAGE_E) * 2;
        const uint32_t uAl = uAh + (uint32_t)TILE_E * 2;
        const uint32_t uBh = uAh + (uint32_t)(2 * TILE_E) * 2;
        const uint32_t uBl = uAh + (uint32_t)(3 * TILE_E) * 2;

#pragma unroll
        for (int ks = 0; ks < 32; ks += 16) {
            uint32_t bh[4][2], bl[4][2];
#pragma unroll
            for (int np = 0; np < 2; np++) {
                uint32_t r4[4];
                uint32_t off = (uint32_t)((n0 + np * 16 + bRow) * BKP + ks + bCol) * 2;
                ldsm_x4(r4, uBh + off);
                bh[np * 2][0] = r4[0]; bh[np * 2][1] = r4[1];
                bh[np * 2 + 1][0] = r4[2]; bh[np * 2 + 1][1] = r4[3];
                ldsm_x4(r4, uBl + off);
                bl[np * 2][0] = r4[0]; bl[np * 2][1] = r4[1];
                bl[np * 2 + 1][0] = r4[2]; bl[np * 2 + 1][1] = r4[3];
            }
#pragma unroll
            for (int mi = 0; mi < 4; mi++) {
                uint32_t off = (uint32_t)((m0 + mi * 16 + aRow) * BKP + ks + aCol) * 2;
                uint32_t ah[4], al[4];
                ldsm_x4(ah, uAh + off);
                ldsm_x4(al, uAl + off);
#pragma unroll
                for (int ni = 0; ni < 4; ni++) mma_bf16(acc[mi][ni], ah, bh[ni]);
#pragma unroll
                for (int ni = 0; ni < 4; ni++) mma_bf16(acc[mi][ni], ah, bl[ni]);
#pragma unroll
                for (int ni = 0; ni < 4; ni++) mma_bf16(acc[mi][ni], al, bh[ni]);
            }
        }
        __syncthreads();
    }

#pragma unroll
    for (int mi = 0; mi < 4; mi++) {
#pragma unroll
        for (int ni = 0; ni < 4; ni++) {
            int row = bm + m0 + mi * 16 + g;
            int col = bn + n0 + ni * 8 + t2;
            *(float2*)&C[(size_t)row * N + col] =
                make_float2(acc[mi][ni][0], acc[mi][ni][1]);
            *(float2*)&C[(size_t)(row + 8) * N + col] =
                make_float2(acc[mi][ni][2], acc[mi][ni][3]);
        }
    }
}

// ================= RoPE + RMSNorm -> bf16 hi/lo Q,K,V =======================
__global__ void rope_norm_kernel(const float* __restrict__ qw,
                                 const float* __restrict__ kw) {
    const int h = blockIdx.x, t = blockIdx.y, b = blockIdx.z;
    const int hd = threadIdx.x;
    __shared__ float sq[128], sk[128];
    __shared__ float red[8];

    const size_t row = (size_t)(b * Tt + t) * (3 * Dd);
    float qv = g_qkv[row + h * HDd + hd];
    float kv = g_qkv[row + Dd + h * HDd + hd];
    float vv = g_qkv[row + 2 * Dd + h * HDd + hd];
    sq[hd] = qv;
    sk[hd] = kv;
    __syncthreads();

    const int j = hd & 63;
    const int ci = (b * Tt + t) * 64 + j;
    const float c = g_cos[ci], s = g_sin[ci];
    float rq, rk;
    if (hd < 64) {
        rq = sq[hd] * c - sq[hd + 64] * s;
        rk = sk[hd] * c - sk[hd + 64] * s;
    } else {
        rq = sq[hd] * c + sq[hd - 64] * s;
        rk = sk[hd] * c + sk[hd - 64] * s;
    }
    float s2q = rq * rq, s2k = rk * rk;
#pragma unroll
    for (int m = 16; m >= 1; m >>= 1) {
        s2q += __shfl_xor_sync(0xffffffffu, s2q, m);
        s2k += __shfl_xor_sync(0xffffffffu, s2k, m);
    }
    const int w = hd >> 5;
    if ((hd & 31) == 0) { red[w] = s2q; red[4 + w] = s2k; }
    __syncthreads();
    float sumq = red[0] + red[1] + red[2] + red[3];
    float sumk = red[4] + red[5] + red[6] + red[7];
    float iq = rsqrtf(sumq * (1.0f / 128.0f) + 1e-6f);
    float ik = rsqrtf(sumk * (1.0f / 128.0f) + 1e-6f);

    const float qsc = 0.08838834764831845f;
    float qf = rq * iq * qw[hd] * qsc;
    float kf = rk * ik * kw[hd];

    const size_t o = (size_t)((b * Hh + h) * Tt + t) * HDd + hd;
    __nv_bfloat16 qh = __float2bfloat16(qf);
    __nv_bfloat16 kh = __float2bfloat16(kf);
    __nv_bfloat16 vh = __float2bfloat16(vv);
    g_qh[o] = qh;
    g_ql[o] = __float2bfloat16(qf - __bfloat162float(qh));
    g_kh[o] = kh;
    g_kl[o] = __float2bfloat16(kf - __bfloat162float(kh));
    g_vh[o] = vh;
    g_vl[o] = __float2bfloat16(vv - __bfloat162float(vh));
}

// ================= Tensor-core flash attention (cp.async V + ldsm.trans) ====
#define AP 136
#define PP 72
#define Q_E (128 * AP)
#define K_E (64 * AP)
#define P_E (128 * PP)
#define OFF_QH 0
#define OFF_QL (Q_E)
#define OFF_KH (2 * Q_E)
#define OFF_KL (2 * Q_E + K_E)
#define OFF_VH (2 * Q_E + 2 * K_E)
#define OFF_VL (2 * Q_E + 3 * K_E)
#define OFF_PH (2 * Q_E + 4 * K_E)
#define OFF_PL (2 * Q_E + 4 * K_E + P_E)
#define ATTN_SMEM ((2 * Q_E + 4 * K_E + 2 * P_E) * 2)  // 176128 B

__global__ __launch_bounds__(256, 1) void attn_mma_kernel() {
    extern __shared__ __align__(128) __nv_bfloat16 sma[];
    const int tid = threadIdx.x;
    const int lane = tid & 31;
    const int w = tid >> 5;
    const int g = lane >> 2;
    const int t2 = (lane & 3) * 2;
    const int qb = blockIdx.x, h = blockIdx.y, b = blockIdx.z;
    const int qg0 = qb * 128;
    const size_t hb = (size_t)(b * Hh + h) * Tt * HDd;
    const uint32_t sbase = smem_u32(sma);

    const int aRow = lane & 15;
    const int aCol = (lane >> 4) << 3;
    const int bRow = (lane & 7) + ((lane >> 4) << 3);
    const int bCol = lane & 8;

    {
        const __nv_bfloat16* qs[2] = {g_qh + hb + (size_t)qg0 * HDd,
                                      g_ql + hb + (size_t)qg0 * HDd};
#pragma unroll
        for (int i = 0; i < 16; i++) {
            int idx = tid + i * 256;
            int arr = idx >> 11;
            int rem = idx & 2047;
            int row = rem >> 4;
            int seg = rem & 15;
            uint4 v = *(const uint4*)(qs[arr] + (size_t)row * HDd + seg * 8);
            *(uint4*)(sma + arr * Q_E + row * AP + seg * 8) = v;
        }
    }

    float o[16][4];
#pragma unroll
    for (int ni = 0; ni < 16; ni++)
#pragma unroll
        for (int c = 0; c < 4; c++) o[ni][c] = 0.0f;
    float m_run[2] = {-1e30f, -1e30f}, l_run[2] = {0.0f, 0.0f};

    const int nkb = 2 * qb + 2;
    const int qwr = qg0 + w * 16;

    const uint32_t uQh = sbase + (uint32_t)OFF_QH * 2;
    const uint32_t uQl = sbase + (uint32_t)OFF_QL * 2;
    const uint32_t uKh = sbase + (uint32_t)OFF_KH * 2;
    const uint32_t uKl = sbase + (uint32_t)OFF_KL * 2;
    const uint32_t uVh = sbase + (uint32_t)OFF_VH * 2;
    const uint32_t uVl = sbase + (uint32_t)OFF_VL * 2;
    const uint32_t uPh = sbase + (uint32_t)OFF_PH * 2;
    const uint32_t uPl = sbase + (uint32_t)OFF_PL * 2;

    // K/V smem dest offsets + global sources by array index
    const uint32_t dsts[4] = {OFF_KH, OFF_KL, OFF_VH, OFF_VL};

    for (int kb = 0; kb < nkb; kb++) {
        const int kg0 = kb * 64;
        __syncthreads();   // (a) previous tile's compute done

        // ---- load K+V hi/lo row-major: 4 arrays x 64 rows x 16 segs ----
#pragma unroll
        for (int i = 0; i < 16; i++) {
            int idx = tid + i * 256;          // 0..4095
            int arr = idx >> 10;              // 0..3
            int rem = idx & 1023;
            int row = rem >> 4;               // 0..63
            int seg = rem & 15;               // 0..15
            const __nv_bfloat16* src =
                (arr == 0 ? g_kh : arr == 1 ? g_kl : arr == 2 ? g_vh : g_vl);
            const __nv_bfloat16* gp = src + hb + (size_t)(kg0 + row) * HDd + seg * 8;
            uint32_t sa = sbase + (uint32_t)(dsts[arr] + row * AP + seg * 8) * 2;
            asm volatile("cp.async.ca.shared.global [%0], [%1], 16;"
                         :: "r"(sa), "l"(gp));
        }
        asm volatile("cp.async.commit_group;");
        asm volatile("cp.async.wait_group 0;");
        __syncthreads();   // (b) K,V visible (Q too on first pass)

        const bool active = (kg0 <= qwr + 15);
        if (active) {
            // ---- S = Q K^T (bf16x3), hoisted K frags ----
            float s[8][4];
#pragma unroll
            for (int ni = 0; ni < 8; ni++)
#pragma unroll
                for (int c = 0; c < 4; c++) s[ni][c] = 0.0f;

#pragma unroll
            for (int kc = 0; kc < 8; kc++) {
                const int colb = kc * 16;
                uint32_t offA = (uint32_t)((w * 16 + aRow) * AP + colb + aCol) * 2;
                uint32_t ah[4], al[4];
                ldsm_x4(ah, uQh + offA);
                ldsm_x4(al, uQl + offA);
                uint32_t kbh[8][2], kbl[8][2];
#pragma unroll
                for (int np = 0; np < 4; np++) {
                    uint32_t offB = (uint32_t)((np * 16 + bRow) * AP + colb + bCol) * 2;
                    uint32_t r4[4];
                    ldsm_x4(r4, uKh + offB);
                    kbh[np * 2][0] = r4[0]; kbh[np * 2][1] = r4[1];
                    kbh[np * 2 + 1][0] = r4[2]; kbh[np * 2 + 1][1] = r4[3];
                    ldsm_x4(r4, uKl + offB);
                    kbl[np * 2][0] = r4[0]; kbl[np * 2][1] = r4[1];
                    kbl[np * 2 + 1][0] = r4[2]; kbl[np * 2 + 1][1] = r4[3];
                }
#pragma unroll
                for (int ni = 0; ni < 8; ni++) mma_bf16(s[ni], ah, kbh[ni]);
#pragma unroll
                for (int ni = 0; ni < 8; ni++) mma_bf16(s[ni], ah, kbl[ni]);
#pragma unroll
                for (int ni = 0; ni < 8; ni++) mma_bf16(s[ni], al, kbh[ni]);
            }

            if (kg0 + 63 > qwr) {
#pragma unroll
                for (int ni = 0; ni < 8; ni++)
#pragma unroll
                    for (int c = 0; c < 4; c++) {
                        int key = kg0 + ni * 8 + t2 + (c & 1);
                        int qr = qwr + g + ((c & 2) ? 8 : 0);
                        if (key > qr) s[ni][c] = -1e30f;
                    }
            }

            __nv_bfloat16* sPh = sma + OFF_PH;
            __nv_bfloat16* sPl = sma + OFF_PL;
#pragma unroll
            for (int r = 0; r < 2; r++) {
                float mt = -1e30f;
#pragma unroll
                for (int ni = 0; ni < 8; ni++)
                    mt = fmaxf(mt, fmaxf(s[ni][2 * r], s[ni][2 * r + 1]));
                mt = fmaxf(mt, __shfl_xor_sync(0xffffffffu, mt, 1));
                mt = fmaxf(mt, __shfl_xor_sync(0xffffffffu, mt, 2));
                float mnew = fmaxf(m_run[r], mt);
                float corr = __expf(m_run[r] - mnew);
                m_run[r] = mnew;
                float psum = 0.0f;
                const int prow = w * 16 + g + r * 8;
#pragma unroll
                for (int ni = 0; ni < 8; ni++) {
                    float p0 = __expf(s[ni][2 * r] - mnew);
                    float p1 = __expf(s[ni][2 * r + 1] - mnew);
                    psum += p0 + p1;
                    __nv_bfloat162 h2 = __floats2bfloat162_rn(p0, p1);
                    float l0 = p0 - __bfloat162float(h2.x);
                    float l1 = p1 - __bfloat162float(h2.y);
                    __nv_bfloat162 l2 = __floats2bfloat162_rn(l0, l1);
                    *(uint32_t*)&sPh[prow * PP + ni * 8 + t2] = *(uint32_t*)&h2;
                    *(uint32_t*)&sPl[prow * PP + ni * 8 + t2] = *(uint32_t*)&l2;
                }
                psum += __shfl_xor_sync(0xffffffffu, psum, 1);
                psum += __shfl_xor_sync(0xffffffffu, psum, 2);
                l_run[r] = l_run[r] * corr + psum;
#pragma unroll
                for (int ni = 0; ni < 16; ni++) {
                    o[ni][2 * r] *= corr;
                    o[ni][2 * r + 1] *= corr;
                }
            }
            __syncwarp();   // P rows are warp-private: warp-level visibility only

            // ---- O += P V (bf16x3); V fragments via ldmatrix.trans ----
#pragma unroll
            for (int kc = 0; kc < 4; kc++) {
                const int colb = kc * 16;
                uint32_t offA = (uint32_t)((w * 16 + aRow) * PP + colb + aCol) * 2;
                uint32_t ah[4], al[4];
                ldsm_x4(ah, uPh + offA);
                ldsm_x4(al, uPl + offA);
#pragma unroll
                for (int np = 0; np < 8; np++) {
                    // trans load: rows = key (kc*16 + lane&15), cols = d (np*16 + (lane>>4)*8)
                    uint32_t offV = (uint32_t)((kc * 16 + aRow) * AP + np * 16 + aCol) * 2;
                    uint32_t r4[4];
                    uint32_t bhA[2], bhB[2], blA[2], blB[2];
                    ldsm_x4_trans(r4, uVh + offV);
                    bhA[0] = r4[0]; bhA[1] = r4[1]; bhB[0] = r4[2]; bhB[1] = r4[3];
                    ldsm_x4_trans(r4, uVl + offV);
                    blA[0] = r4[0]; blA[1] = r4[1]; blB[0] = r4[2]; blB[1] = r4[3];
                    mma_bf16(o[np * 2], ah, bhA);
                    mma_bf16(o[np * 2], ah, blA);
                    mma_bf16(o[np * 2], al, bhA);
                    mma_bf16(o[np * 2 + 1], ah, bhB);
                    mma_bf16(o[np * 2 + 1], ah, blB);
                    mma_bf16(o[np * 2 + 1], al, bhB);
                }
            }
        }
    }

    // ---- epilogue ----
#pragma unroll
    for (int r = 0; r < 2; r++) {
        float inv = 1.0f / l_run[r];
        int t = qg0 + w * 16 + g + r * 8;
        size_t rowo = (size_t)(b * Tt + t) * Dd + h * HDd;
#pragma unroll
        for (int ni = 0; ni < 16; ni++) {
            float v0 = o[ni][2 * r] * inv;
            float v1 = o[ni][2 * r + 1] * inv;
            __nv_bfloat162 h2 = __floats2bfloat162_rn(v0, v1);
            float l0 = v0 - __bfloat162float(h2.x);
            float l1 = v1 - __bfloat162float(h2.y);
            __nv_bfloat162 l2 = __floats2bfloat162_rn(l0, l1);
            *(uint32_t*)&g_aoh[rowo + ni * 8 + t2] = *(uint32_t*)&h2;
            *(uint32_t*)&g_aol[rowo + ni * 8 + t2] = *(uint32_t*)&l2;
        }
    }
}

// ================= launch ===================================================
extern "C" void kernel_launch(void* const* d_in, const int* in_sizes, int n_in,
                              void* d_out, int out_size) {
    const float* x = (const float*)d_in[0];
    const int* positions = (const int*)d_in[2];
    const float* qkv_w = (const float*)d_in[3];
    const float* out_w = (const float*)d_in[4];
    const float* q_norm_w = (const float*)d_in[5];
    const float* k_norm_w = (const float*)d_in[6];
    float* out = (float*)d_out;
    (void)in_sizes; (void)n_in; (void)out_size;

    void *p_qkv, *p_xh, *p_xl, *p_aoh, *p_aol, *p_wqh, *p_wql, *p_woh, *p_wol;
    cudaGetSymbolAddress(&p_qkv, g_qkv);
    cudaGetSymbolAddress(&p_xh, g_xh);
    cudaGetSymbolAddress(&p_xl, g_xl);
    cudaGetSymbolAddress(&p_aoh, g_aoh);
    cudaGetSymbolAddress(&p_aol, g_aol);
    cudaGetSymbolAddress(&p_wqh, g_wqh);
    cudaGetSymbolAddress(&p_wql, g_wql);
    cudaGetSymbolAddress(&p_woh, g_woh);
    cudaGetSymbolAddress(&p_wol, g_wol);

    static int attr_set = 0;
    if (!attr_set) {
        cudaFuncSetAttribute(gemm_mma_kernel, cudaFuncAttributeMaxDynamicSharedMemorySize, GEMM_SMEM);
        cudaFuncSetAttribute(attn_mma_kernel, cudaFuncAttributeMaxDynamicSharedMemorySize, ATTN_SMEM);
        attr_set = 1;
    }

    const int M = Bb * Tt;

    rope_table_kernel<<<(Bb * Tt * 64 + 255) / 256, 256>>>(positions);
    convert_split_kernel<<<(M * Dd / 4 + 255) / 256, 256>>>(
        x, (__nv_bfloat16*)p_xh, (__nv_bfloat16*)p_xl, M * Dd / 4);
    transpose_split_kernel<<<dim3(3 * Dd / 32, Dd / 32, 2), dim3(32, 8)>>>(qkv_w, out_w);
    gemm_mma_kernel<<<dim3(3 * Dd / 128, M / 128), 256, GEMM_SMEM>>>(
        (const __nv_bfloat16*)p_xh, (const __nv_bfloat16*)p_xl,
        (const __nv_bfloat16*)p_wqh, (const __nv_bfloat16*)p_wql,
        (float*)p_qkv, M, 3 * Dd, Dd);
    rope_norm_kernel<<<dim3(Hh, Tt, Bb), 128>>>(q_norm_w, k_norm_w);
    attn_mma_kernel<<<dim3(Tt / 128, Hh, Bb), 256, ATTN_SMEM>>>();
    gemm_mma_kernel<<<dim3(Dd / 128, M / 128), 256, GEMM_SMEM>>>(
        (const __nv_bfloat16*)p_aoh, (const __nv_bfloat16*)p_aol,
        (const __nv_bfloat16*)p_woh, (const __nv_bfloat16*)p_wol,
        out, M, Dd, Dd);
}

// round 15
// speedup vs baseline: 4.1317x; 1.3212x over previous
#include <cuda_runtime.h>
#include <cuda_fp16.h>
#include <math.h>
#include <stdint.h>

#define Bb 2
#define Tt 2048
#define Dd 2048
#define Hh 16
#define HDd 128

// ================= scratch ==================================================
__device__ float g_qkv[(size_t)Bb * Tt * 3 * Dd];
__device__ float g_cos[(size_t)Bb * Tt * 64];
__device__ float g_sin[(size_t)Bb * Tt * 64];
__device__ __half g_xh[(size_t)Bb * Tt * Dd];
__device__ __half g_xl[(size_t)Bb * Tt * Dd];
__device__ __half g_aoh[(size_t)Bb * Tt * Dd];
__device__ __half g_aol[(size_t)Bb * Tt * Dd];
__device__ __half g_wq[(size_t)3 * Dd * Dd];    // qkv_w^T fp16 single
__device__ __half g_wo[(size_t)Dd * Dd];        // out_w^T fp16 single
__device__ __half g_qh[(size_t)Bb * Hh * Tt * HDd];
__device__ __half g_ql[(size_t)Bb * Hh * Tt * HDd];
__device__ __half g_kh[(size_t)Bb * Hh * Tt * HDd];
__device__ __half g_kl[(size_t)Bb * Hh * Tt * HDd];
__device__ __half g_v[(size_t)Bb * Hh * Tt * HDd];   // V fp16 single

__device__ __forceinline__ uint32_t smem_u32(const void* p) {
    uint32_t a;
    asm("{ .reg .u64 t; cvta.to.shared.u64 t, %1; cvt.u32.u64 %0, t; }" : "=r"(a) : "l"(p));
    return a;
}

__device__ __forceinline__ void ldsm_x4(uint32_t* r, uint32_t addr) {
    asm volatile("ldmatrix.sync.aligned.m8n8.x4.shared.b16 {%0,%1,%2,%3}, [%4];"
                 : "=r"(r[0]), "=r"(r[1]), "=r"(r[2]), "=r"(r[3]) : "r"(addr));
}

__device__ __forceinline__ void ldsm_x4_trans(uint32_t* r, uint32_t addr) {
    asm volatile("ldmatrix.sync.aligned.m8n8.x4.trans.shared.b16 {%0,%1,%2,%3}, [%4];"
                 : "=r"(r[0]), "=r"(r[1]), "=r"(r[2]), "=r"(r[3]) : "r"(addr));
}

__device__ __forceinline__ void mma_f16(float* d, const uint32_t* a, const uint32_t* b) {
    asm volatile(
        "mma.sync.aligned.m16n8k16.row.col.f32.f16.f16.f32 "
        "{%0,%1,%2,%3}, {%4,%5,%6,%7}, {%8,%9}, {%0,%1,%2,%3};"
        : "+f"(d[0]), "+f"(d[1]), "+f"(d[2]), "+f"(d[3])
        : "r"(a[0]), "r"(a[1]), "r"(a[2]), "r"(a[3]), "r"(b[0]), "r"(b[1]));
}

// ================= RoPE table ==============================================
__global__ void rope_table_kernel(const int* __restrict__ positions) {
    int idx = blockIdx.x * blockDim.x + threadIdx.x;
    if (idx >= Bb * Tt * 64) return;
    int j = idx & 63;
    int bt = idx >> 6;
    int pos = positions[bt];
    float inv_freq = exp2f(-(float)j * (13.287712379549449f / 64.0f));
    float ang = (float)pos * inv_freq;
    float s, c;
    sincosf(ang, &s, &c);
    g_cos[idx] = c;
    g_sin[idx] = s;
}

// ================= split-convert to fp16 hi/lo ==============================
__global__ void convert_split_kernel(const float* __restrict__ in,
                                     __half* __restrict__ oh,
                                     __half* __restrict__ ol, int n4) {
    int i = blockIdx.x * blockDim.x + threadIdx.x;
    if (i >= n4) return;
    float4 v = ((const float4*)in)[i];
    __half hx = __float2half_rn(v.x);
    __half hy = __float2half_rn(v.y);
    __half hz = __float2half_rn(v.z);
    __half hw = __float2half_rn(v.w);
    __half lx = __float2half_rn(v.x - __half2float(hx));
    __half ly = __float2half_rn(v.y - __half2float(hy));
    __half lz = __float2half_rn(v.z - __half2float(hz));
    __half lw = __float2half_rn(v.w - __half2float(hw));
    ((__half2*)oh)[2 * i + 0] = __halves2half2(hx, hy);
    ((__half2*)oh)[2 * i + 1] = __halves2half2(hz, hw);
    ((__half2*)ol)[2 * i + 0] = __halves2half2(lx, ly);
    ((__half2*)ol)[2 * i + 1] = __halves2half2(lz, lw);
}

// ================= transpose + convert weights to single fp16 ===============
__global__ void transpose_kernel(const float* __restrict__ W0,
                                 const float* __restrict__ W1) {
    __shared__ float t[32][33];
    int z = blockIdx.z;
    int Ncols = z ? Dd : 3 * Dd;
    const float* W = z ? W1 : W0;
    __half* Th = z ? g_wo : g_wq;
    int n0 = blockIdx.x * 32, k0 = blockIdx.y * 32;
    if (n0 >= Ncols) return;
    int tx = threadIdx.x, ty = threadIdx.y;
#pragma unroll
    for (int i = ty; i < 32; i += 8)
        t[i][tx] = W[(size_t)(k0 + i) * Ncols + n0 + tx];
    __syncthreads();
#pragma unroll
    for (int i = ty; i < 32; i += 8) {
        size_t o = (size_t)(n0 + i) * Dd + k0 + tx;
        Th[o] = __float2half_rn(t[tx][i]);
    }
}

// ================= fp16 2-pass GEMM: C = (Ah+Al) @ B^T ======================
// tile 128x128, BK=32, 8 warps, warp tile 64x32. 3 smem tiles/stage.
#define BKP 40
#define TILE_E (128 * BKP)
#define STAGE_E (3 * TILE_E)
#define GEMM_SMEM (2 * STAGE_E * 2)   // 61440 B

__global__ __launch_bounds__(256, 2) void gemm_mma_kernel(
    const __half* __restrict__ Ah, const __half* __restrict__ Al,
    const __half* __restrict__ B,
    float* __restrict__ C, int M, int N, int K) {
    extern __shared__ __align__(128) __half smem[];
    const int tid = threadIdx.x;
    const int lane = tid & 31;
    const int wid = tid >> 5;
    const int g = lane >> 2;
    const int t2 = (lane & 3) * 2;
    const int wm = wid & 1, wn = wid >> 1;
    const int m0 = wm * 64, n0 = wn * 32;
    const int bm = blockIdx.y * 128;
    const int bn = blockIdx.x * 128;

    const __half* srcs[3] = {Ah + (size_t)bm * K, Al + (size_t)bm * K,
                             B + (size_t)bn * K};

    uint32_t smem_base = smem_u32(smem);

    const int aRow = lane & 15;
    const int aCol = (lane >> 4) << 3;
    const int bRow = (lane & 7) + ((lane >> 4) << 3);
    const int bCol = lane & 8;

    float acc[4][4][4];
#pragma unroll
    for (int mi = 0; mi < 4; mi++)
#pragma unroll
        for (int ni = 0; ni < 4; ni++)
#pragma unroll
            for (int c = 0; c < 4; c++) acc[mi][ni][c] = 0.0f;

    const int nK = K >> 5;

    auto load_stage = [&](int s, int kb) {
        const int k0 = kb * 32;
#pragma unroll
        for (int i = 0; i < 6; i++) {
            int idx = i * 256 + tid;          // 0..1535
            int tile = idx >> 9;              // 0..2
            int rem = idx & 511;
            int row = rem >> 2;
            int seg = rem & 3;
            const __half* gp = srcs[tile] + (size_t)row * K + k0 + seg * 8;
            uint32_t sa = smem_base +
                (uint32_t)(s * STAGE_E + tile * TILE_E + row * BKP + seg * 8) * 2;
            asm volatile("cp.async.ca.shared.global [%0], [%1], 16;"
                         :: "r"(sa), "l"(gp));
        }
    };

    load_stage(0, 0);
    asm volatile("cp.async.commit_group;");

    for (int kb = 0; kb < nK; kb++) {
        const int cur = kb & 1;
        if (kb + 1 < nK) {
            load_stage(cur ^ 1, kb + 1);
            asm volatile("cp.async.commit_group;");
            asm volatile("cp.async.wait_group 1;");
        } else {
            asm volatile("cp.async.wait_group 0;");
        }
        __syncthreads();

        const uint32_t uAh = smem_base + (uint32_t)(cur * STAGE_E) * 2;
        const uint32_t uAl = uAh + (uint32_t)TILE_E * 2;
        const uint32_t uB  = uAh + (uint32_t)(2 * TILE_E) * 2;

#pragma unroll
        for (int ks = 0; ks < 32; ks += 16) {
            uint32_t bb[4][2];
#pragma unroll
            for (int np = 0; np < 2; np++) {
                uint32_t r4[4];
                uint32_t off = (uint32_t)((n0 + np * 16 + bRow) * BKP + ks + bCol) * 2;
                ldsm_x4(r4, uB + off);
                bb[np * 2][0] = r4[0]; bb[np * 2][1] = r4[1];
                bb[np * 2 + 1][0] = r4[2]; bb[np * 2 + 1][1] = r4[3];
            }
#pragma unroll
            for (int mi = 0; mi < 4; mi++) {
                uint32_t off = (uint32_t)((m0 + mi * 16 + aRow) * BKP + ks + aCol) * 2;
                uint32_t ah[4], al[4];
                ldsm_x4(ah, uAh + off);
                ldsm_x4(al, uAl + off);
#pragma unroll
                for (int ni = 0; ni < 4; ni++) mma_f16(acc[mi][ni], ah, bb[ni]);
#pragma unroll
                for (int ni = 0; ni < 4; ni++) mma_f16(acc[mi][ni], al, bb[ni]);
            }
        }
        __syncthreads();
    }

#pragma unroll
    for (int mi = 0; mi < 4; mi++) {
#pragma unroll
        for (int ni = 0; ni < 4; ni++) {
            int row = bm + m0 + mi * 16 + g;
            int col = bn + n0 + ni * 8 + t2;
            *(float2*)&C[(size_t)row * N + col] =
                make_float2(acc[mi][ni][0], acc[mi][ni][1]);
            *(float2*)&C[(size_t)(row + 8) * N + col] =
                make_float2(acc[mi][ni][2], acc[mi][ni][3]);
        }
    }
}

// ================= RoPE + RMSNorm -> fp16 Q(h/l), K(h/l), V(single) =========
__global__ void rope_norm_kernel(const float* __restrict__ qw,
                                 const float* __restrict__ kw) {
    const int h = blockIdx.x, t = blockIdx.y, b = blockIdx.z;
    const int hd = threadIdx.x;
    __shared__ float sq[128], sk[128];
    __shared__ float red[8];

    const size_t row = (size_t)(b * Tt + t) * (3 * Dd);
    float qv = g_qkv[row + h * HDd + hd];
    float kv = g_qkv[row + Dd + h * HDd + hd];
    float vv = g_qkv[row + 2 * Dd + h * HDd + hd];
    sq[hd] = qv;
    sk[hd] = kv;
    __syncthreads();

    const int j = hd & 63;
    const int ci = (b * Tt + t) * 64 + j;
    const float c = g_cos[ci], s = g_sin[ci];
    float rq, rk;
    if (hd < 64) {
        rq = sq[hd] * c - sq[hd + 64] * s;
        rk = sk[hd] * c - sk[hd + 64] * s;
    } else {
        rq = sq[hd] * c + sq[hd - 64] * s;
        rk = sk[hd] * c + sk[hd - 64] * s;
    }
    float s2q = rq * rq, s2k = rk * rk;
#pragma unroll
    for (int m = 16; m >= 1; m >>= 1) {
        s2q += __shfl_xor_sync(0xffffffffu, s2q, m);
        s2k += __shfl_xor_sync(0xffffffffu, s2k, m);
    }
    const int w = hd >> 5;
    if ((hd & 31) == 0) { red[w] = s2q; red[4 + w] = s2k; }
    __syncthreads();
    float sumq = red[0] + red[1] + red[2] + red[3];
    float sumk = red[4] + red[5] + red[6] + red[7];
    float iq = rsqrtf(sumq * (1.0f / 128.0f) + 1e-6f);
    float ik = rsqrtf(sumk * (1.0f / 128.0f) + 1e-6f);

    const float qsc = 0.08838834764831845f;
    float qf = rq * iq * qw[hd] * qsc;
    float kf = rk * ik * kw[hd];

    const size_t o = (size_t)((b * Hh + h) * Tt + t) * HDd + hd;
    __half qh = __float2half_rn(qf);
    __half kh = __float2half_rn(kf);
    g_qh[o] = qh;
    g_ql[o] = __float2half_rn(qf - __half2float(qh));
    g_kh[o] = kh;
    g_kl[o] = __float2half_rn(kf - __half2float(kh));
    g_v[o] = __float2half_rn(vv);
}

// ================= Tensor-core flash attention (fp16) =======================
// S: 3-pass (Q h/l x K h/l). P·V: 2-pass (P h/l x V single).
#define AP 136
#define PP 72
#define Q_E (128 * AP)
#define K_E (64 * AP)
#define P_E (128 * PP)
#define OFF_QH 0
#define OFF_QL (Q_E)
#define OFF_KH (2 * Q_E)
#define OFF_KL (2 * Q_E + K_E)
#define OFF_V  (2 * Q_E + 2 * K_E)
#define OFF_PH (2 * Q_E + 3 * K_E)
#define OFF_PL (2 * Q_E + 3 * K_E + P_E)
#define ATTN_SMEM ((2 * Q_E + 3 * K_E + 2 * P_E) * 2)   // 158720 B

__global__ __launch_bounds__(256, 1) void attn_mma_kernel() {
    extern __shared__ __align__(128) __half sma[];
    const int tid = threadIdx.x;
    const int lane = tid & 31;
    const int w = tid >> 5;
    const int g = lane >> 2;
    const int t2 = (lane & 3) * 2;
    const int qb = blockIdx.x, h = blockIdx.y, b = blockIdx.z;
    const int qg0 = qb * 128;
    const size_t hb = (size_t)(b * Hh + h) * Tt * HDd;
    const uint32_t sbase = smem_u32(sma);

    const int aRow = lane & 15;
    const int aCol = (lane >> 4) << 3;
    const int bRow = (lane & 7) + ((lane >> 4) << 3);
    const int bCol = lane & 8;

    {
        const __half* qs[2] = {g_qh + hb + (size_t)qg0 * HDd,
                               g_ql + hb + (size_t)qg0 * HDd};
#pragma unroll
        for (int i = 0; i < 16; i++) {
            int idx = tid + i * 256;
            int arr = idx >> 11;
            int rem = idx & 2047;
            int row = rem >> 4;
            int seg = rem & 15;
            uint4 v = *(const uint4*)(qs[arr] + (size_t)row * HDd + seg * 8);
            *(uint4*)(sma + arr * Q_E + row * AP + seg * 8) = v;
        }
    }

    float o[16][4];
#pragma unroll
    for (int ni = 0; ni < 16; ni++)
#pragma unroll
        for (int c = 0; c < 4; c++) o[ni][c] = 0.0f;
    float m_run[2] = {-1e30f, -1e30f}, l_run[2] = {0.0f, 0.0f};

    const int nkb = 2 * qb + 2;
    const int qwr = qg0 + w * 16;

    const uint32_t uQh = sbase + (uint32_t)OFF_QH * 2;
    const uint32_t uQl = sbase + (uint32_t)OFF_QL * 2;
    const uint32_t uKh = sbase + (uint32_t)OFF_KH * 2;
    const uint32_t uKl = sbase + (uint32_t)OFF_KL * 2;
    const uint32_t uV  = sbase + (uint32_t)OFF_V * 2;
    const uint32_t uPh = sbase + (uint32_t)OFF_PH * 2;
    const uint32_t uPl = sbase + (uint32_t)OFF_PL * 2;

    const uint32_t dsts[3] = {OFF_KH, OFF_KL, OFF_V};

    for (int kb = 0; kb < nkb; kb++) {
        const int kg0 = kb * 64;
        __syncthreads();   // (a) previous tile compute done

        // ---- load Kh, Kl, V row-major: 3 arrays x 64 rows x 16 segs ----
#pragma unroll
        for (int i = 0; i < 12; i++) {
            int idx = tid + i * 256;          // 0..3071
            int arr = idx >> 10;              // 0..2
            int rem = idx & 1023;
            int row = rem >> 4;
            int seg = rem & 15;
            const __half* src = (arr == 0 ? g_kh : arr == 1 ? g_kl : g_v);
            const __half* gp = src + hb + (size_t)(kg0 + row) * HDd + seg * 8;
            uint32_t sa = sbase + (uint32_t)(dsts[arr] + row * AP + seg * 8) * 2;
            asm volatile("cp.async.ca.shared.global [%0], [%1], 16;"
                         :: "r"(sa), "l"(gp));
        }
        asm volatile("cp.async.commit_group;");
        asm volatile("cp.async.wait_group 0;");
        __syncthreads();   // (b)

        const bool active = (kg0 <= qwr + 15);
        if (active) {
            // ---- S = Q K^T, 3-pass fp16 ----
            float s[8][4];
#pragma unroll
            for (int ni = 0; ni < 8; ni++)
#pragma unroll
                for (int c = 0; c < 4; c++) s[ni][c] = 0.0f;

#pragma unroll
            for (int kc = 0; kc < 8; kc++) {
                const int colb = kc * 16;
                uint32_t offA = (uint32_t)((w * 16 + aRow) * AP + colb + aCol) * 2;
                uint32_t ah[4], al[4];
                ldsm_x4(ah, uQh + offA);
                ldsm_x4(al, uQl + offA);
                uint32_t kbh[8][2], kbl[8][2];
#pragma unroll
                for (int np = 0; np < 4; np++) {
                    uint32_t offB = (uint32_t)((np * 16 + bRow) * AP + colb + bCol) * 2;
                    uint32_t r4[4];
                    ldsm_x4(r4, uKh + offB);
                    kbh[np * 2][0] = r4[0]; kbh[np * 2][1] = r4[1];
                    kbh[np * 2 + 1][0] = r4[2]; kbh[np * 2 + 1][1] = r4[3];
                    ldsm_x4(r4, uKl + offB);
                    kbl[np * 2][0] = r4[0]; kbl[np * 2][1] = r4[1];
                    kbl[np * 2 + 1][0] = r4[2]; kbl[np * 2 + 1][1] = r4[3];
                }
#pragma unroll
                for (int ni = 0; ni < 8; ni++) mma_f16(s[ni], ah, kbh[ni]);
#pragma unroll
                for (int ni = 0; ni < 8; ni++) mma_f16(s[ni], ah, kbl[ni]);
#pragma unroll
                for (int ni = 0; ni < 8; ni++) mma_f16(s[ni], al, kbh[ni]);
            }

            if (kg0 + 63 > qwr) {
#pragma unroll
                for (int ni = 0; ni < 8; ni++)
#pragma unroll
                    for (int c = 0; c < 4; c++) {
                        int key = kg0 + ni * 8 + t2 + (c & 1);
                        int qr = qwr + g + ((c & 2) ? 8 : 0);
                        if (key > qr) s[ni][c] = -1e30f;
                    }
            }

            __half* sPh = sma + OFF_PH;
            __half* sPl = sma + OFF_PL;
#pragma unroll
            for (int r = 0; r < 2; r++) {
                float mt = -1e30f;
#pragma unroll
                for (int ni = 0; ni < 8; ni++)
                    mt = fmaxf(mt, fmaxf(s[ni][2 * r], s[ni][2 * r + 1]));
                mt = fmaxf(mt, __shfl_xor_sync(0xffffffffu, mt, 1));
                mt = fmaxf(mt, __shfl_xor_sync(0xffffffffu, mt, 2));
                float mnew = fmaxf(m_run[r], mt);
                float corr = __expf(m_run[r] - mnew);
                m_run[r] = mnew;
                float psum = 0.0f;
                const int prow = w * 16 + g + r * 8;
#pragma unroll
                for (int ni = 0; ni < 8; ni++) {
                    float p0 = __expf(s[ni][2 * r] - mnew);
                    float p1 = __expf(s[ni][2 * r + 1] - mnew);
                    psum += p0 + p1;
                    __half2 h2 = __floats2half2_rn(p0, p1);
                    float l0 = p0 - __half2float(__low2half(h2));
                    float l1 = p1 - __half2float(__high2half(h2));
                    __half2 l2 = __floats2half2_rn(l0, l1);
                    *(uint32_t*)&sPh[prow * PP + ni * 8 + t2] = *(uint32_t*)&h2;
                    *(uint32_t*)&sPl[prow * PP + ni * 8 + t2] = *(uint32_t*)&l2;
                }
                psum += __shfl_xor_sync(0xffffffffu, psum, 1);
                psum += __shfl_xor_sync(0xffffffffu, psum, 2);
                l_run[r] = l_run[r] * corr + psum;
#pragma unroll
                for (int ni = 0; ni < 16; ni++) {
                    o[ni][2 * r] *= corr;
                    o[ni][2 * r + 1] *= corr;
                }
            }
            __syncwarp();   // P rows warp-private

            // ---- O += P V, 2-pass (V single fp16 via ldsm.trans) ----
#pragma unroll
            for (int kc = 0; kc < 4; kc++) {
                const int colb = kc * 16;
                uint32_t offA = (uint32_t)((w * 16 + aRow) * PP + colb + aCol) * 2;
                uint32_t ah[4], al[4];
                ldsm_x4(ah, uPh + offA);
                ldsm_x4(al, uPl + offA);
#pragma unroll
                for (int np = 0; np < 8; np++) {
                    uint32_t offV = (uint32_t)((kc * 16 + aRow) * AP + np * 16 + aCol) * 2;
                    uint32_t r4[4];
                    uint32_t bA[2], bB[2];
                    ldsm_x4_trans(r4, uV + offV);
                    bA[0] = r4[0]; bA[1] = r4[1]; bB[0] = r4[2]; bB[1] = r4[3];
                    mma_f16(o[np * 2], ah, bA);
                    mma_f16(o[np * 2], al, bA);
                    mma_f16(o[np * 2 + 1], ah, bB);
                    mma_f16(o[np * 2 + 1], al, bB);
                }
            }
        }
    }

    // ---- epilogue: normalize, split fp16 hi/lo, write [B,T,D] ----
#pragma unroll
    for (int r = 0; r < 2; r++) {
        float inv = 1.0f / l_run[r];
        int t = qg0 + w * 16 + g + r * 8;
        size_t rowo = (size_t)(b * Tt + t) * Dd + h * HDd;
#pragma unroll
        for (int ni = 0; ni < 16; ni++) {
            float v0 = o[ni][2 * r] * inv;
            float v1 = o[ni][2 * r + 1] * inv;
            __half2 h2 = __floats2half2_rn(v0, v1);
            float l0 = v0 - __half2float(__low2half(h2));
            float l1 = v1 - __half2float(__high2half(h2));
            __half2 l2 = __floats2half2_rn(l0, l1);
            *(uint32_t*)&g_aoh[rowo + ni * 8 + t2] = *(uint32_t*)&h2;
            *(uint32_t*)&g_aol[rowo + ni * 8 + t2] = *(uint32_t*)&l2;
        }
    }
}

// ================= launch ===================================================
extern "C" void kernel_launch(void* const* d_in, const int* in_sizes, int n_in,
                              void* d_out, int out_size) {
    const float* x = (const float*)d_in[0];
    const int* positions = (const int*)d_in[2];
    const float* qkv_w = (const float*)d_in[3];
    const float* out_w = (const float*)d_in[4];
    const float* q_norm_w = (const float*)d_in[5];
    const float* k_norm_w = (const float*)d_in[6];
    float* out = (float*)d_out;
    (void)in_sizes; (void)n_in; (void)out_size;

    void *p_qkv, *p_xh, *p_xl, *p_aoh, *p_aol, *p_wq, *p_wo;
    cudaGetSymbolAddress(&p_qkv, g_qkv);
    cudaGetSymbolAddress(&p_xh, g_xh);
    cudaGetSymbolAddress(&p_xl, g_xl);
    cudaGetSymbolAddress(&p_aoh, g_aoh);
    cudaGetSymbolAddress(&p_aol, g_aol);
    cudaGetSymbolAddress(&p_wq, g_wq);
    cudaGetSymbolAddress(&p_wo, g_wo);

    static int attr_set = 0;
    if (!attr_set) {
        cudaFuncSetAttribute(gemm_mma_kernel, cudaFuncAttributeMaxDynamicSharedMemorySize, GEMM_SMEM);
        cudaFuncSetAttribute(attn_mma_kernel, cudaFuncAttributeMaxDynamicSharedMemorySize, ATTN_SMEM);
        attr_set = 1;
    }

    const int M = Bb * Tt;

    rope_table_kernel<<<(Bb * Tt * 64 + 255) / 256, 256>>>(positions);
    convert_split_kernel<<<(M * Dd / 4 + 255) / 256, 256>>>(
        x, (__half*)p_xh, (__half*)p_xl, M * Dd / 4);
    transpose_kernel<<<dim3(3 * Dd / 32, Dd / 32, 2), dim3(32, 8)>>>(qkv_w, out_w);
    gemm_mma_kernel<<<dim3(3 * Dd / 128, M / 128), 256, GEMM_SMEM>>>(
        (const __half*)p_xh, (const __half*)p_xl, (const __half*)p_wq,
        (float*)p_qkv, M, 3 * Dd, Dd);
    rope_norm_kernel<<<dim3(Hh, Tt, Bb), 128>>>(q_norm_w, k_norm_w);
    attn_mma_kernel<<<dim3(Tt / 128, Hh, Bb), 256, ATTN_SMEM>>>();
    gemm_mma_kernel<<<dim3(Dd / 128, M / 128), 256, GEMM_SMEM>>>(
        (const __half*)p_aoh, (const __half*)p_aol, (const __half*)p_wo,
        out, M, Dd, Dd);
}

// round 16
// speedup vs baseline: 4.1741x; 1.0103x over previous
#include <cuda_runtime.h>
#include <cuda_fp16.h>
#include <math.h>
#include <stdint.h>

#define Bb 2
#define Tt 2048
#define Dd 2048
#define Hh 16
#define HDd 128

// ================= scratch ==================================================
__device__ float g_qkv[(size_t)Bb * Tt * 3 * Dd];
__device__ float g_cos[(size_t)Bb * Tt * 64];
__device__ float g_sin[(size_t)Bb * Tt * 64];
__device__ __half g_xh[(size_t)Bb * Tt * Dd];
__device__ __half g_xl[(size_t)Bb * Tt * Dd];
__device__ __half g_aoh[(size_t)Bb * Tt * Dd];
__device__ __half g_aol[(size_t)Bb * Tt * Dd];
__device__ __half g_wq[(size_t)3 * Dd * Dd];
__device__ __half g_wo[(size_t)Dd * Dd];
__device__ __half g_qh[(size_t)Bb * Hh * Tt * HDd];
__device__ __half g_ql[(size_t)Bb * Hh * Tt * HDd];
__device__ __half g_kh[(size_t)Bb * Hh * Tt * HDd];
__device__ __half g_kl[(size_t)Bb * Hh * Tt * HDd];
__device__ __half g_v[(size_t)Bb * Hh * Tt * HDd];

__device__ __forceinline__ uint32_t smem_u32(const void* p) {
    uint32_t a;
    asm("{ .reg .u64 t; cvta.to.shared.u64 t, %1; cvt.u32.u64 %0, t; }" : "=r"(a) : "l"(p));
    return a;
}

__device__ __forceinline__ void ldsm_x4(uint32_t* r, uint32_t addr) {
    asm volatile("ldmatrix.sync.aligned.m8n8.x4.shared.b16 {%0,%1,%2,%3}, [%4];"
                 : "=r"(r[0]), "=r"(r[1]), "=r"(r[2]), "=r"(r[3]) : "r"(addr));
}

__device__ __forceinline__ void ldsm_x4_trans(uint32_t* r, uint32_t addr) {
    asm volatile("ldmatrix.sync.aligned.m8n8.x4.trans.shared.b16 {%0,%1,%2,%3}, [%4];"
                 : "=r"(r[0]), "=r"(r[1]), "=r"(r[2]), "=r"(r[3]) : "r"(addr));
}

__device__ __forceinline__ void mma_f16(float* d, const uint32_t* a, const uint32_t* b) {
    asm volatile(
        "mma.sync.aligned.m16n8k16.row.col.f32.f16.f16.f32 "
        "{%0,%1,%2,%3}, {%4,%5,%6,%7}, {%8,%9}, {%0,%1,%2,%3};"
        : "+f"(d[0]), "+f"(d[1]), "+f"(d[2]), "+f"(d[3])
        : "r"(a[0]), "r"(a[1]), "r"(a[2]), "r"(a[3]), "r"(b[0]), "r"(b[1]));
}

// ================= RoPE table ==============================================
__global__ void rope_table_kernel(const int* __restrict__ positions) {
    int idx = blockIdx.x * blockDim.x + threadIdx.x;
    if (idx >= Bb * Tt * 64) return;
    int j = idx & 63;
    int bt = idx >> 6;
    int pos = positions[bt];
    float inv_freq = exp2f(-(float)j * (13.287712379549449f / 64.0f));
    float ang = (float)pos * inv_freq;
    float s, c;
    sincosf(ang, &s, &c);
    g_cos[idx] = c;
    g_sin[idx] = s;
}

// ================= split-convert to fp16 hi/lo ==============================
__global__ void convert_split_kernel(const float* __restrict__ in,
                                     __half* __restrict__ oh,
                                     __half* __restrict__ ol, int n4) {
    int i = blockIdx.x * blockDim.x + threadIdx.x;
    if (i >= n4) return;
    float4 v = ((const float4*)in)[i];
    __half hx = __float2half_rn(v.x);
    __half hy = __float2half_rn(v.y);
    __half hz = __float2half_rn(v.z);
    __half hw = __float2half_rn(v.w);
    __half lx = __float2half_rn(v.x - __half2float(hx));
    __half ly = __float2half_rn(v.y - __half2float(hy));
    __half lz = __float2half_rn(v.z - __half2float(hz));
    __half lw = __float2half_rn(v.w - __half2float(hw));
    ((__half2*)oh)[2 * i + 0] = __halves2half2(hx, hy);
    ((__half2*)oh)[2 * i + 1] = __halves2half2(hz, hw);
    ((__half2*)ol)[2 * i + 0] = __halves2half2(lx, ly);
    ((__half2*)ol)[2 * i + 1] = __halves2half2(lz, lw);
}

// ================= transpose + convert weights to single fp16 ===============
__global__ void transpose_kernel(const float* __restrict__ W0,
                                 const float* __restrict__ W1) {
    __shared__ float t[32][33];
    int z = blockIdx.z;
    int Ncols = z ? Dd : 3 * Dd;
    const float* W = z ? W1 : W0;
    __half* Th = z ? g_wo : g_wq;
    int n0 = blockIdx.x * 32, k0 = blockIdx.y * 32;
    if (n0 >= Ncols) return;
    int tx = threadIdx.x, ty = threadIdx.y;
#pragma unroll
    for (int i = ty; i < 32; i += 8)
        t[i][tx] = W[(size_t)(k0 + i) * Ncols + n0 + tx];
    __syncthreads();
#pragma unroll
    for (int i = ty; i < 32; i += 8) {
        size_t o = (size_t)(n0 + i) * Dd + k0 + tx;
        Th[o] = __float2half_rn(t[tx][i]);
    }
}

// ================= fp16 2-pass GEMM (unchanged) =============================
#define BKP 40
#define TILE_E (128 * BKP)
#define STAGE_E (3 * TILE_E)
#define GEMM_SMEM (2 * STAGE_E * 2)

__global__ __launch_bounds__(256, 2) void gemm_mma_kernel(
    const __half* __restrict__ Ah, const __half* __restrict__ Al,
    const __half* __restrict__ B,
    float* __restrict__ C, int M, int N, int K) {
    extern __shared__ __align__(128) __half smem[];
    const int tid = threadIdx.x;
    const int lane = tid & 31;
    const int wid = tid >> 5;
    const int g = lane >> 2;
    const int t2 = (lane & 3) * 2;
    const int wm = wid & 1, wn = wid >> 1;
    const int m0 = wm * 64, n0 = wn * 32;
    const int bm = blockIdx.y * 128;
    const int bn = blockIdx.x * 128;

    const __half* srcs[3] = {Ah + (size_t)bm * K, Al + (size_t)bm * K,
                             B + (size_t)bn * K};

    uint32_t smem_base = smem_u32(smem);

    const int aRow = lane & 15;
    const int aCol = (lane >> 4) << 3;
    const int bRow = (lane & 7) + ((lane >> 4) << 3);
    const int bCol = lane & 8;

    float acc[4][4][4];
#pragma unroll
    for (int mi = 0; mi < 4; mi++)
#pragma unroll
        for (int ni = 0; ni < 4; ni++)
#pragma unroll
            for (int c = 0; c < 4; c++) acc[mi][ni][c] = 0.0f;

    const int nK = K >> 5;

    auto load_stage = [&](int s, int kb) {
        const int k0 = kb * 32;
#pragma unroll
        for (int i = 0; i < 6; i++) {
            int idx = i * 256 + tid;
            int tile = idx >> 9;
            int rem = idx & 511;
            int row = rem >> 2;
            int seg = rem & 3;
            const __half* gp = srcs[tile] + (size_t)row * K + k0 + seg * 8;
            uint32_t sa = smem_base +
                (uint32_t)(s * STAGE_E + tile * TILE_E + row * BKP + seg * 8) * 2;
            asm volatile("cp.async.ca.shared.global [%0], [%1], 16;"
                         :: "r"(sa), "l"(gp));
        }
    };

    load_stage(0, 0);
    asm volatile("cp.async.commit_group;");

    for (int kb = 0; kb < nK; kb++) {
        const int cur = kb & 1;
        if (kb + 1 < nK) {
            load_stage(cur ^ 1, kb + 1);
            asm volatile("cp.async.commit_group;");
            asm volatile("cp.async.wait_group 1;");
        } else {
            asm volatile("cp.async.wait_group 0;");
        }
        __syncthreads();

        const uint32_t uAh = smem_base + (uint32_t)(cur * STAGE_E) * 2;
        const uint32_t uAl = uAh + (uint32_t)TILE_E * 2;
        const uint32_t uB  = uAh + (uint32_t)(2 * TILE_E) * 2;

#pragma unroll
        for (int ks = 0; ks < 32; ks += 16) {
            uint32_t bb[4][2];
#pragma unroll
            for (int np = 0; np < 2; np++) {
                uint32_t r4[4];
                uint32_t off = (uint32_t)((n0 + np * 16 + bRow) * BKP + ks + bCol) * 2;
                ldsm_x4(r4, uB + off);
                bb[np * 2][0] = r4[0]; bb[np * 2][1] = r4[1];
                bb[np * 2 + 1][0] = r4[2]; bb[np * 2 + 1][1] = r4[3];
            }
#pragma unroll
            for (int mi = 0; mi < 4; mi++) {
                uint32_t off = (uint32_t)((m0 + mi * 16 + aRow) * BKP + ks + aCol) * 2;
                uint32_t ah[4], al[4];
                ldsm_x4(ah, uAh + off);
                ldsm_x4(al, uAl + off);
#pragma unroll
                for (int ni = 0; ni < 4; ni++) mma_f16(acc[mi][ni], ah, bb[ni]);
#pragma unroll
                for (int ni = 0; ni < 4; ni++) mma_f16(acc[mi][ni], al, bb[ni]);
            }
        }
        __syncthreads();
    }

#pragma unroll
    for (int mi = 0; mi < 4; mi++) {
#pragma unroll
        for (int ni = 0; ni < 4; ni++) {
            int row = bm + m0 + mi * 16 + g;
            int col = bn + n0 + ni * 8 + t2;
            *(float2*)&C[(size_t)row * N + col] =
                make_float2(acc[mi][ni][0], acc[mi][ni][1]);
            *(float2*)&C[(size_t)(row + 8) * N + col] =
                make_float2(acc[mi][ni][2], acc[mi][ni][3]);
        }
    }
}

// ================= RoPE + RMSNorm -> fp16 Q(h/l), K(h/l), V ================
__global__ void rope_norm_kernel(const float* __restrict__ qw,
                                 const float* __restrict__ kw) {
    const int h = blockIdx.x, t = blockIdx.y, b = blockIdx.z;
    const int hd = threadIdx.x;
    __shared__ float sq[128], sk[128];
    __shared__ float red[8];

    const size_t row = (size_t)(b * Tt + t) * (3 * Dd);
    float qv = g_qkv[row + h * HDd + hd];
    float kv = g_qkv[row + Dd + h * HDd + hd];
    float vv = g_qkv[row + 2 * Dd + h * HDd + hd];
    sq[hd] = qv;
    sk[hd] = kv;
    __syncthreads();

    const int j = hd & 63;
    const int ci = (b * Tt + t) * 64 + j;
    const float c = g_cos[ci], s = g_sin[ci];
    float rq, rk;
    if (hd < 64) {
        rq = sq[hd] * c - sq[hd + 64] * s;
        rk = sk[hd] * c - sk[hd + 64] * s;
    } else {
        rq = sq[hd] * c + sq[hd - 64] * s;
        rk = sk[hd] * c + sk[hd - 64] * s;
    }
    float s2q = rq * rq, s2k = rk * rk;
#pragma unroll
    for (int m = 16; m >= 1; m >>= 1) {
        s2q += __shfl_xor_sync(0xffffffffu, s2q, m);
        s2k += __shfl_xor_sync(0xffffffffu, s2k, m);
    }
    const int w = hd >> 5;
    if ((hd & 31) == 0) { red[w] = s2q; red[4 + w] = s2k; }
    __syncthreads();
    float sumq = red[0] + red[1] + red[2] + red[3];
    float sumk = red[4] + red[5] + red[6] + red[7];
    float iq = rsqrtf(sumq * (1.0f / 128.0f) + 1e-6f);
    float ik = rsqrtf(sumk * (1.0f / 128.0f) + 1e-6f);

    const float qsc = 0.08838834764831845f;
    float qf = rq * iq * qw[hd] * qsc;
    float kf = rk * ik * kw[hd];

    const size_t o = (size_t)((b * Hh + h) * Tt + t) * HDd + hd;
    __half qh = __float2half_rn(qf);
    __half kh = __float2half_rn(kf);
    g_qh[o] = qh;
    g_ql[o] = __float2half_rn(qf - __half2float(qh));
    g_kh[o] = kh;
    g_kl[o] = __float2half_rn(kf - __half2float(kh));
    g_v[o] = __float2half_rn(vv);
}

// ================= Tensor-core flash attention (fp16, 2-stage KV) ===========
#define AP 136
#define PP 72
#define Q_E (128 * AP)
#define K_E (64 * AP)
#define P_E (128 * PP)
#define KV_STAGE (3 * K_E)
#define OFF_QH 0
#define OFF_QL (Q_E)
#define OFF_KV0 (2 * Q_E)
#define OFF_PH (2 * Q_E + 2 * KV_STAGE)
#define OFF_PL (2 * Q_E + 2 * KV_STAGE + P_E)
#define ATTN_SMEM ((2 * Q_E + 2 * KV_STAGE + 2 * P_E) * 2)   // 210944 B

__global__ __launch_bounds__(256, 1) void attn_mma_kernel() {
    extern __shared__ __align__(128) __half sma[];
    const int tid = threadIdx.x;
    const int lane = tid & 31;
    const int w = tid >> 5;
    const int g = lane >> 2;
    const int t2 = (lane & 3) * 2;
    // LPT: longest CTAs (largest qb) launch first
    const int qb = (int)gridDim.x - 1 - (int)blockIdx.x;
    const int h = blockIdx.y, b = blockIdx.z;
    const int qg0 = qb * 128;
    const size_t hb = (size_t)(b * Hh + h) * Tt * HDd;
    const uint32_t sbase = smem_u32(sma);

    const int aRow = lane & 15;
    const int aCol = (lane >> 4) << 3;
    const int bRow = (lane & 7) + ((lane >> 4) << 3);
    const int bCol = lane & 8;

    {
        const __half* qs[2] = {g_qh + hb + (size_t)qg0 * HDd,
                               g_ql + hb + (size_t)qg0 * HDd};
#pragma unroll
        for (int i = 0; i < 16; i++) {
            int idx = tid + i * 256;
            int arr = idx >> 11;
            int rem = idx & 2047;
            int row = rem >> 4;
            int seg = rem & 15;
            uint4 v = *(const uint4*)(qs[arr] + (size_t)row * HDd + seg * 8);
            *(uint4*)(sma + arr * Q_E + row * AP + seg * 8) = v;
        }
    }

    float o[16][4];
#pragma unroll
    for (int ni = 0; ni < 16; ni++)
#pragma unroll
        for (int c = 0; c < 4; c++) o[ni][c] = 0.0f;
    float m_run[2] = {-1e30f, -1e30f}, l_run[2] = {0.0f, 0.0f};

    const int nkb = 2 * qb + 2;
    const int qwr = qg0 + w * 16;

    const uint32_t uQh = sbase + (uint32_t)OFF_QH * 2;
    const uint32_t uQl = sbase + (uint32_t)OFF_QL * 2;
    const uint32_t uPh = sbase + (uint32_t)OFF_PH * 2;
    const uint32_t uPl = sbase + (uint32_t)OFF_PL * 2;

    // double-buffered KV loader (stage = kb & 1)
    auto load_kv = [&](int kb) {
        const int st = kb & 1;
        const int kg = kb * 64;
        const uint32_t stb = (uint32_t)(OFF_KV0 + st * KV_STAGE);
#pragma unroll
        for (int i = 0; i < 12; i++) {
            int idx = tid + i * 256;          // 0..3071
            int arr = idx >> 10;              // 0..2
            int rem = idx & 1023;
            int row = rem >> 4;
            int seg = rem & 15;
            const __half* src = (arr == 0 ? g_kh : arr == 1 ? g_kl : g_v);
            const __half* gp = src + hb + (size_t)(kg + row) * HDd + seg * 8;
            uint32_t sa = sbase + (uint32_t)(stb + arr * K_E + row * AP + seg * 8) * 2;
            asm volatile("cp.async.ca.shared.global [%0], [%1], 16;"
                         :: "r"(sa), "l"(gp));
        }
    };

    load_kv(0);
    asm volatile("cp.async.commit_group;");

    for (int kb = 0; kb < nkb; kb++) {
        const int kg0 = kb * 64;
        if (kb + 1 < nkb) {
            load_kv(kb + 1);
            asm volatile("cp.async.commit_group;");
            asm volatile("cp.async.wait_group 1;");
        } else {
            asm volatile("cp.async.wait_group 0;");
        }
        __syncthreads();   // stage kb ready; Q ready on first pass

        const int st = kb & 1;
        const uint32_t uKh = sbase + (uint32_t)(OFF_KV0 + st * KV_STAGE) * 2;
        const uint32_t uKl = uKh + (uint32_t)K_E * 2;
        const uint32_t uV  = uKh + (uint32_t)(2 * K_E) * 2;

        const bool active = (kg0 <= qwr + 15);
        if (active) {
            // ---- S = Q K^T, 3-pass fp16 ----
            float s[8][4];
#pragma unroll
            for (int ni = 0; ni < 8; ni++)
#pragma unroll
                for (int c = 0; c < 4; c++) s[ni][c] = 0.0f;

#pragma unroll
            for (int kc = 0; kc < 8; kc++) {
                const int colb = kc * 16;
                uint32_t offA = (uint32_t)((w * 16 + aRow) * AP + colb + aCol) * 2;
                uint32_t ah[4], al[4];
                ldsm_x4(ah, uQh + offA);
                ldsm_x4(al, uQl + offA);
                uint32_t kbh[8][2], kbl[8][2];
#pragma unroll
                for (int np = 0; np < 4; np++) {
                    uint32_t offB = (uint32_t)((np * 16 + bRow) * AP + colb + bCol) * 2;
                    uint32_t r4[4];
                    ldsm_x4(r4, uKh + offB);
                    kbh[np * 2][0] = r4[0]; kbh[np * 2][1] = r4[1];
                    kbh[np * 2 + 1][0] = r4[2]; kbh[np * 2 + 1][1] = r4[3];
                    ldsm_x4(r4, uKl + offB);
                    kbl[np * 2][0] = r4[0]; kbl[np * 2][1] = r4[1];
                    kbl[np * 2 + 1][0] = r4[2]; kbl[np * 2 + 1][1] = r4[3];
                }
#pragma unroll
                for (int ni = 0; ni < 8; ni++) mma_f16(s[ni], ah, kbh[ni]);
#pragma unroll
                for (int ni = 0; ni < 8; ni++) mma_f16(s[ni], ah, kbl[ni]);
#pragma unroll
                for (int ni = 0; ni < 8; ni++) mma_f16(s[ni], al, kbh[ni]);
            }

            if (kg0 + 63 > qwr) {
#pragma unroll
                for (int ni = 0; ni < 8; ni++)
#pragma unroll
                    for (int c = 0; c < 4; c++) {
                        int key = kg0 + ni * 8 + t2 + (c & 1);
                        int qr = qwr + g + ((c & 2) ? 8 : 0);
                        if (key > qr) s[ni][c] = -1e30f;
                    }
            }

            __half* sPh = sma + OFF_PH;
            __half* sPl = sma + OFF_PL;
#pragma unroll
            for (int r = 0; r < 2; r++) {
                float mt = -1e30f;
#pragma unroll
                for (int ni = 0; ni < 8; ni++)
                    mt = fmaxf(mt, fmaxf(s[ni][2 * r], s[ni][2 * r + 1]));
                mt = fmaxf(mt, __shfl_xor_sync(0xffffffffu, mt, 1));
                mt = fmaxf(mt, __shfl_xor_sync(0xffffffffu, mt, 2));
                float mnew = fmaxf(m_run[r], mt);
                float corr = __expf(m_run[r] - mnew);
                m_run[r] = mnew;
                float psum = 0.0f;
                const int prow = w * 16 + g + r * 8;
#pragma unroll
                for (int ni = 0; ni < 8; ni++) {
                    float p0 = __expf(s[ni][2 * r] - mnew);
                    float p1 = __expf(s[ni][2 * r + 1] - mnew);
                    psum += p0 + p1;
                    __half2 h2 = __floats2half2_rn(p0, p1);
                    float l0 = p0 - __half2float(__low2half(h2));
                    float l1 = p1 - __half2float(__high2half(h2));
                    __half2 l2 = __floats2half2_rn(l0, l1);
                    *(uint32_t*)&sPh[prow * PP + ni * 8 + t2] = *(uint32_t*)&h2;
                    *(uint32_t*)&sPl[prow * PP + ni * 8 + t2] = *(uint32_t*)&l2;
                }
                psum += __shfl_xor_sync(0xffffffffu, psum, 1);
                psum += __shfl_xor_sync(0xffffffffu, psum, 2);
                l_run[r] = l_run[r] * corr + psum;
#pragma unroll
                for (int ni = 0; ni < 16; ni++) {
                    o[ni][2 * r] *= corr;
                    o[ni][2 * r + 1] *= corr;
                }
            }
            __syncwarp();   // P rows warp-private

            // ---- O += P V, 2-pass (V via ldsm.trans) ----
#pragma unroll
            for (int kc = 0; kc < 4; kc++) {
                const int colb = kc * 16;
                uint32_t offA = (uint32_t)((w * 16 + aRow) * PP + colb + aCol) * 2;
                uint32_t ah[4], al[4];
                ldsm_x4(ah, uPh + offA);
                ldsm_x4(al, uPl + offA);
#pragma unroll
                for (int np = 0; np < 8; np++) {
                    uint32_t offV = (uint32_t)((kc * 16 + aRow) * AP + np * 16 + aCol) * 2;
                    uint32_t r4[4];
                    uint32_t bA[2], bB[2];
                    ldsm_x4_trans(r4, uV + offV);
                    bA[0] = r4[0]; bA[1] = r4[1]; bB[0] = r4[2]; bB[1] = r4[3];
                    mma_f16(o[np * 2], ah, bA);
                    mma_f16(o[np * 2], al, bA);
                    mma_f16(o[np * 2 + 1], ah, bB);
                    mma_f16(o[np * 2 + 1], al, bB);
                }
            }
        }
        __syncthreads();   // compute done before next iter's loads reuse stage
    }

    // ---- epilogue: normalize, split fp16 hi/lo, write [B,T,D] ----
#pragma unroll
    for (int r = 0; r < 2; r++) {
        float inv = 1.0f / l_run[r];
        int t = qg0 + w * 16 + g + r * 8;
        size_t rowo = (size_t)(b * Tt + t) * Dd + h * HDd;
#pragma unroll
        for (int ni = 0; ni < 16; ni++) {
            float v0 = o[ni][2 * r] * inv;
            float v1 = o[ni][2 * r + 1] * inv;
            __half2 h2 = __floats2half2_rn(v0, v1);
            float l0 = v0 - __half2float(__low2half(h2));
            float l1 = v1 - __half2float(__high2half(h2));
            __half2 l2 = __floats2half2_rn(l0, l1);
            *(uint32_t*)&g_aoh[rowo + ni * 8 + t2] = *(uint32_t*)&h2;
            *(uint32_t*)&g_aol[rowo + ni * 8 + t2] = *(uint32_t*)&l2;
        }
    }
}

// ================= launch ===================================================
extern "C" void kernel_launch(void* const* d_in, const int* in_sizes, int n_in,
                              void* d_out, int out_size) {
    const float* x = (const float*)d_in[0];
    const int* positions = (const int*)d_in[2];
    const float* qkv_w = (const float*)d_in[3];
    const float* out_w = (const float*)d_in[4];
    const float* q_norm_w = (const float*)d_in[5];
    const float* k_norm_w = (const float*)d_in[6];
    float* out = (float*)d_out;
    (void)in_sizes; (void)n_in; (void)out_size;

    void *p_qkv, *p_xh, *p_xl, *p_aoh, *p_aol, *p_wq, *p_wo;
    cudaGetSymbolAddress(&p_qkv, g_qkv);
    cudaGetSymbolAddress(&p_xh, g_xh);
    cudaGetSymbolAddress(&p_xl, g_xl);
    cudaGetSymbolAddress(&p_aoh, g_aoh);
    cudaGetSymbolAddress(&p_aol, g_aol);
    cudaGetSymbolAddress(&p_wq, g_wq);
    cudaGetSymbolAddress(&p_wo, g_wo);

    static int attr_set = 0;
    if (!attr_set) {
        cudaFuncSetAttribute(gemm_mma_kernel, cudaFuncAttributeMaxDynamicSharedMemorySize, GEMM_SMEM);
        cudaFuncSetAttribute(attn_mma_kernel, cudaFuncAttributeMaxDynamicSharedMemorySize, ATTN_SMEM);
        attr_set = 1;
    }

    const int M = Bb * Tt;

    rope_table_kernel<<<(Bb * Tt * 64 + 255) / 256, 256>>>(positions);
    convert_split_kernel<<<(M * Dd / 4 + 255) / 256, 256>>>(
        x, (__half*)p_xh, (__half*)p_xl, M * Dd / 4);
    transpose_kernel<<<dim3(3 * Dd / 32, Dd / 32, 2), dim3(32, 8)>>>(qkv_w, out_w);
    gemm_mma_kernel<<<dim3(3 * Dd / 128, M / 128), 256, GEMM_SMEM>>>(
        (const __half*)p_xh, (const __half*)p_xl, (const __half*)p_wq,
        (float*)p_qkv, M, 3 * Dd, Dd);
    rope_norm_kernel<<<dim3(Hh, Tt, Bb), 128>>>(q_norm_w, k_norm_w);
    attn_mma_kernel<<<dim3(Tt / 128, Hh, Bb), 256, ATTN_SMEM>>>();
    gemm_mma_kernel<<<dim3(Dd / 128, M / 128), 256, GEMM_SMEM>>>(
        (const __half*)p_aoh, (const __half*)p_aol, (const __half*)p_wo,
        out, M, Dd, Dd);
}

// round 17
// speedup vs baseline: 5.0339x; 1.2060x over previous
#include <cuda_runtime.h>
#include <cuda_fp16.h>
#include <math.h>
#include <stdint.h>

#define Bb 2
#define Tt 2048
#define Dd 2048
#define Hh 16
#define HDd 128

// ================= scratch ==================================================
__device__ float g_qkv[(size_t)Bb * Tt * 3 * Dd];
__device__ float g_cos[(size_t)Bb * Tt * 64];
__device__ float g_sin[(size_t)Bb * Tt * 64];
__device__ __half g_x16[(size_t)Bb * Tt * Dd];       // x fp16 single
__device__ __half g_aoh[(size_t)Bb * Tt * Dd];
__device__ __half g_aol[(size_t)Bb * Tt * Dd];
__device__ __half g_wq[(size_t)3 * Dd * Dd];
__device__ __half g_wo[(size_t)Dd * Dd];
__device__ __half g_qh[(size_t)Bb * Hh * Tt * HDd];
__device__ __half g_ql[(size_t)Bb * Hh * Tt * HDd];
__device__ __half g_kh[(size_t)Bb * Hh * Tt * HDd];
__device__ __half g_kl[(size_t)Bb * Hh * Tt * HDd];
__device__ __half g_v[(size_t)Bb * Hh * Tt * HDd];

__device__ __forceinline__ uint32_t smem_u32(const void* p) {
    uint32_t a;
    asm("{ .reg .u64 t; cvta.to.shared.u64 t, %1; cvt.u32.u64 %0, t; }" : "=r"(a) : "l"(p));
    return a;
}

__device__ __forceinline__ void ldsm_x4(uint32_t* r, uint32_t addr) {
    asm volatile("ldmatrix.sync.aligned.m8n8.x4.shared.b16 {%0,%1,%2,%3}, [%4];"
                 : "=r"(r[0]), "=r"(r[1]), "=r"(r[2]), "=r"(r[3]) : "r"(addr));
}

__device__ __forceinline__ void ldsm_x4_trans(uint32_t* r, uint32_t addr) {
    asm volatile("ldmatrix.sync.aligned.m8n8.x4.trans.shared.b16 {%0,%1,%2,%3}, [%4];"
                 : "=r"(r[0]), "=r"(r[1]), "=r"(r[2]), "=r"(r[3]) : "r"(addr));
}

__device__ __forceinline__ void mma_f16(float* d, const uint32_t* a, const uint32_t* b) {
    asm volatile(
        "mma.sync.aligned.m16n8k16.row.col.f32.f16.f16.f32 "
        "{%0,%1,%2,%3}, {%4,%5,%6,%7}, {%8,%9}, {%0,%1,%2,%3};"
        : "+f"(d[0]), "+f"(d[1]), "+f"(d[2]), "+f"(d[3])
        : "r"(a[0]), "r"(a[1]), "r"(a[2]), "r"(a[3]), "r"(b[0]), "r"(b[1]));
}

// ================= RoPE table ==============================================
__global__ void rope_table_kernel(const int* __restrict__ positions) {
    int idx = blockIdx.x * blockDim.x + threadIdx.x;
    if (idx >= Bb * Tt * 64) return;
    int j = idx & 63;
    int bt = idx >> 6;
    int pos = positions[bt];
    float inv_freq = exp2f(-(float)j * (13.287712379549449f / 64.0f));
    float ang = (float)pos * inv_freq;
    float s, c;
    sincosf(ang, &s, &c);
    g_cos[idx] = c;
    g_sin[idx] = s;
}

// ================= convert x to single fp16 =================================
__global__ void convert_kernel(const float* __restrict__ in,
                               __half* __restrict__ o16, int n4) {
    int i = blockIdx.x * blockDim.x + threadIdx.x;
    if (i >= n4) return;
    float4 v = ((const float4*)in)[i];
    ((__half2*)o16)[2 * i + 0] = __floats2half2_rn(v.x, v.y);
    ((__half2*)o16)[2 * i + 1] = __floats2half2_rn(v.z, v.w);
}

// ================= transpose + convert weights to single fp16 ===============
__global__ void transpose_kernel(const float* __restrict__ W0,
                                 const float* __restrict__ W1) {
    __shared__ float t[32][33];
    int z = blockIdx.z;
    int Ncols = z ? Dd : 3 * Dd;
    const float* W = z ? W1 : W0;
    __half* Th = z ? g_wo : g_wq;
    int n0 = blockIdx.x * 32, k0 = blockIdx.y * 32;
    if (n0 >= Ncols) return;
    int tx = threadIdx.x, ty = threadIdx.y;
#pragma unroll
    for (int i = ty; i < 32; i += 8)
        t[i][tx] = W[(size_t)(k0 + i) * Ncols + n0 + tx];
    __syncthreads();
#pragma unroll
    for (int i = ty; i < 32; i += 8) {
        size_t o = (size_t)(n0 + i) * Dd + k0 + tx;
        Th[o] = __float2half_rn(t[tx][i]);
    }
}

// ================= shared GEMM constants ====================================
#define BKP 40
#define TILE_E (128 * BKP)

// ================= fp16 1-pass GEMM: C = A @ B^T (both single fp16) =========
#define G1_STAGE (2 * TILE_E)
#define GEMM1_SMEM (2 * G1_STAGE * 2)    // 40960 B

__global__ __launch_bounds__(256, 2) void gemm1_kernel(
    const __half* __restrict__ A, const __half* __restrict__ B,
    float* __restrict__ C, int M, int N, int K) {
    extern __shared__ __align__(128) __half smem[];
    const int tid = threadIdx.x;
    const int lane = tid & 31;
    const int wid = tid >> 5;
    const int g = lane >> 2;
    const int t2 = (lane & 3) * 2;
    const int wm = wid & 1, wn = wid >> 1;
    const int m0 = wm * 64, n0 = wn * 32;
    const int bm = blockIdx.y * 128;
    const int bn = blockIdx.x * 128;

    const __half* srcs[2] = {A + (size_t)bm * K, B + (size_t)bn * K};

    uint32_t smem_base = smem_u32(smem);

    const int aRow = lane & 15;
    const int aCol = (lane >> 4) << 3;
    const int bRow = (lane & 7) + ((lane >> 4) << 3);
    const int bCol = lane & 8;

    float acc[4][4][4];
#pragma unroll
    for (int mi = 0; mi < 4; mi++)
#pragma unroll
        for (int ni = 0; ni < 4; ni++)
#pragma unroll
            for (int c = 0; c < 4; c++) acc[mi][ni][c] = 0.0f;

    const int nK = K >> 5;

    auto load_stage = [&](int s, int kb) {
        const int k0 = kb * 32;
#pragma unroll
        for (int i = 0; i < 4; i++) {
            int idx = i * 256 + tid;          // 0..1023
            int tile = idx >> 9;              // 0..1
            int rem = idx & 511;
            int row = rem >> 2;
            int seg = rem & 3;
            const __half* gp = srcs[tile] + (size_t)row * K + k0 + seg * 8;
            uint32_t sa = smem_base +
                (uint32_t)(s * G1_STAGE + tile * TILE_E + row * BKP + seg * 8) * 2;
            asm volatile("cp.async.ca.shared.global [%0], [%1], 16;"
                         :: "r"(sa), "l"(gp));
        }
    };

    load_stage(0, 0);
    asm volatile("cp.async.commit_group;");

    for (int kb = 0; kb < nK; kb++) {
        const int cur = kb & 1;
        if (kb + 1 < nK) {
            load_stage(cur ^ 1, kb + 1);
            asm volatile("cp.async.commit_group;");
            asm volatile("cp.async.wait_group 1;");
        } else {
            asm volatile("cp.async.wait_group 0;");
        }
        __syncthreads();

        const uint32_t uA = smem_base + (uint32_t)(cur * G1_STAGE) * 2;
        const uint32_t uB = uA + (uint32_t)TILE_E * 2;

#pragma unroll
        for (int ks = 0; ks < 32; ks += 16) {
            uint32_t bb[4][2];
#pragma unroll
            for (int np = 0; np < 2; np++) {
                uint32_t r4[4];
                uint32_t off = (uint32_t)((n0 + np * 16 + bRow) * BKP + ks + bCol) * 2;
                ldsm_x4(r4, uB + off);
                bb[np * 2][0] = r4[0]; bb[np * 2][1] = r4[1];
                bb[np * 2 + 1][0] = r4[2]; bb[np * 2 + 1][1] = r4[3];
            }
#pragma unroll
            for (int mi = 0; mi < 4; mi++) {
                uint32_t off = (uint32_t)((m0 + mi * 16 + aRow) * BKP + ks + aCol) * 2;
                uint32_t aa[4];
                ldsm_x4(aa, uA + off);
#pragma unroll
                for (int ni = 0; ni < 4; ni++) mma_f16(acc[mi][ni], aa, bb[ni]);
            }
        }
        __syncthreads();
    }

#pragma unroll
    for (int mi = 0; mi < 4; mi++) {
#pragma unroll
        for (int ni = 0; ni < 4; ni++) {
            int row = bm + m0 + mi * 16 + g;
            int col = bn + n0 + ni * 8 + t2;
            *(float2*)&C[(size_t)row * N + col] =
                make_float2(acc[mi][ni][0], acc[mi][ni][1]);
            *(float2*)&C[(size_t)(row + 8) * N + col] =
                make_float2(acc[mi][ni][2], acc[mi][ni][3]);
        }
    }
}

// ================= fp16 2-pass GEMM (out-proj, unchanged) ===================
#define STAGE_E (3 * TILE_E)
#define GEMM_SMEM (2 * STAGE_E * 2)

__global__ __launch_bounds__(256, 2) void gemm_mma_kernel(
    const __half* __restrict__ Ah, const __half* __restrict__ Al,
    const __half* __restrict__ B,
    float* __restrict__ C, int M, int N, int K) {
    extern __shared__ __align__(128) __half smem[];
    const int tid = threadIdx.x;
    const int lane = tid & 31;
    const int wid = tid >> 5;
    const int g = lane >> 2;
    const int t2 = (lane & 3) * 2;
    const int wm = wid & 1, wn = wid >> 1;
    const int m0 = wm * 64, n0 = wn * 32;
    const int bm = blockIdx.y * 128;
    const int bn = blockIdx.x * 128;

    const __half* srcs[3] = {Ah + (size_t)bm * K, Al + (size_t)bm * K,
                             B + (size_t)bn * K};

    uint32_t smem_base = smem_u32(smem);

    const int aRow = lane & 15;
    const int aCol = (lane >> 4) << 3;
    const int bRow = (lane & 7) + ((lane >> 4) << 3);
    const int bCol = lane & 8;

    float acc[4][4][4];
#pragma unroll
    for (int mi = 0; mi < 4; mi++)
#pragma unroll
        for (int ni = 0; ni < 4; ni++)
#pragma unroll
            for (int c = 0; c < 4; c++) acc[mi][ni][c] = 0.0f;

    const int nK = K >> 5;

    auto load_stage = [&](int s, int kb) {
        const int k0 = kb * 32;
#pragma unroll
        for (int i = 0; i < 6; i++) {
            int idx = i * 256 + tid;
            int tile = idx >> 9;
            int rem = idx & 511;
            int row = rem >> 2;
            int seg = rem & 3;
            const __half* gp = srcs[tile] + (size_t)row * K + k0 + seg * 8;
            uint32_t sa = smem_base +
                (uint32_t)(s * STAGE_E + tile * TILE_E + row * BKP + seg * 8) * 2;
            asm volatile("cp.async.ca.shared.global [%0], [%1], 16;"
                         :: "r"(sa), "l"(gp));
        }
    };

    load_stage(0, 0);
    asm volatile("cp.async.commit_group;");

    for (int kb = 0; kb < nK; kb++) {
        const int cur = kb & 1;
        if (kb + 1 < nK) {
            load_stage(cur ^ 1, kb + 1);
            asm volatile("cp.async.commit_group;");
            asm volatile("cp.async.wait_group 1;");
        } else {
            asm volatile("cp.async.wait_group 0;");
        }
        __syncthreads();

        const uint32_t uAh = smem_base + (uint32_t)(cur * STAGE_E) * 2;
        const uint32_t uAl = uAh + (uint32_t)TILE_E * 2;
        const uint32_t uB  = uAh + (uint32_t)(2 * TILE_E) * 2;

#pragma unroll
        for (int ks = 0; ks < 32; ks += 16) {
            uint32_t bb[4][2];
#pragma unroll
            for (int np = 0; np < 2; np++) {
                uint32_t r4[4];
                uint32_t off = (uint32_t)((n0 + np * 16 + bRow) * BKP + ks + bCol) * 2;
                ldsm_x4(r4, uB + off);
                bb[np * 2][0] = r4[0]; bb[np * 2][1] = r4[1];
                bb[np * 2 + 1][0] = r4[2]; bb[np * 2 + 1][1] = r4[3];
            }
#pragma unroll
            for (int mi = 0; mi < 4; mi++) {
                uint32_t off = (uint32_t)((m0 + mi * 16 + aRow) * BKP + ks + aCol) * 2;
                uint32_t ah[4], al[4];
                ldsm_x4(ah, uAh + off);
                ldsm_x4(al, uAl + off);
#pragma unroll
                for (int ni = 0; ni < 4; ni++) mma_f16(acc[mi][ni], ah, bb[ni]);
#pragma unroll
                for (int ni = 0; ni < 4; ni++) mma_f16(acc[mi][ni], al, bb[ni]);
            }
        }
        __syncthreads();
    }

#pragma unroll
    for (int mi = 0; mi < 4; mi++) {
#pragma unroll
        for (int ni = 0; ni < 4; ni++) {
            int row = bm + m0 + mi * 16 + g;
            int col = bn + n0 + ni * 8 + t2;
            *(float2*)&C[(size_t)row * N + col] =
                make_float2(acc[mi][ni][0], acc[mi][ni][1]);
            *(float2*)&C[(size_t)(row + 8) * N + col] =
                make_float2(acc[mi][ni][2], acc[mi][ni][3]);
        }
    }
}

// ================= RoPE + RMSNorm -> fp16 Q(h/l), K(h/l), V ================
__global__ void rope_norm_kernel(const float* __restrict__ qw,
                                 const float* __restrict__ kw) {
    const int h = blockIdx.x, t = blockIdx.y, b = blockIdx.z;
    const int hd = threadIdx.x;
    __shared__ float sq[128], sk[128];
    __shared__ float red[8];

    const size_t row = (size_t)(b * Tt + t) * (3 * Dd);
    float qv = g_qkv[row + h * HDd + hd];
    float kv = g_qkv[row + Dd + h * HDd + hd];
    float vv = g_qkv[row + 2 * Dd + h * HDd + hd];
    sq[hd] = qv;
    sk[hd] = kv;
    __syncthreads();

    const int j = hd & 63;
    const int ci = (b * Tt + t) * 64 + j;
    const float c = g_cos[ci], s = g_sin[ci];
    float rq, rk;
    if (hd < 64) {
        rq = sq[hd] * c - sq[hd + 64] * s;
        rk = sk[hd] * c - sk[hd + 64] * s;
    } else {
        rq = sq[hd] * c + sq[hd - 64] * s;
        rk = sk[hd] * c + sk[hd - 64] * s;
    }
    float s2q = rq * rq, s2k = rk * rk;
#pragma unroll
    for (int m = 16; m >= 1; m >>= 1) {
        s2q += __shfl_xor_sync(0xffffffffu, s2q, m);
        s2k += __shfl_xor_sync(0xffffffffu, s2k, m);
    }
    const int w = hd >> 5;
    if ((hd & 31) == 0) { red[w] = s2q; red[4 + w] = s2k; }
    __syncthreads();
    float sumq = red[0] + red[1] + red[2] + red[3];
    float sumk = red[4] + red[5] + red[6] + red[7];
    float iq = rsqrtf(sumq * (1.0f / 128.0f) + 1e-6f);
    float ik = rsqrtf(sumk * (1.0f / 128.0f) + 1e-6f);

    const float qsc = 0.08838834764831845f;
    float qf = rq * iq * qw[hd] * qsc;
    float kf = rk * ik * kw[hd];

    const size_t o = (size_t)((b * Hh + h) * Tt + t) * HDd + hd;
    __half qh = __float2half_rn(qf);
    __half kh = __float2half_rn(kf);
    g_qh[o] = qh;
    g_ql[o] = __float2half_rn(qf - __half2float(qh));
    g_kh[o] = kh;
    g_kl[o] = __float2half_rn(kf - __half2float(kh));
    g_v[o] = __float2half_rn(vv);
}

// ================= Tensor-core flash attention (fp16, 2-stage KV) ===========
#define AP 136
#define PP 72
#define Q_E (128 * AP)
#define K_E (64 * AP)
#define P_E (128 * PP)
#define KV_STAGE (3 * K_E)
#define OFF_QH 0
#define OFF_QL (Q_E)
#define OFF_KV0 (2 * Q_E)
#define OFF_PH (2 * Q_E + 2 * KV_STAGE)
#define OFF_PL (2 * Q_E + 2 * KV_STAGE + P_E)
#define ATTN_SMEM ((2 * Q_E + 2 * KV_STAGE + 2 * P_E) * 2)

__global__ __launch_bounds__(256, 1) void attn_mma_kernel() {
    extern __shared__ __align__(128) __half sma[];
    const int tid = threadIdx.x;
    const int lane = tid & 31;
    const int w = tid >> 5;
    const int g = lane >> 2;
    const int t2 = (lane & 3) * 2;
    const int qb = (int)gridDim.x - 1 - (int)blockIdx.x;
    const int h = blockIdx.y, b = blockIdx.z;
    const int qg0 = qb * 128;
    const size_t hb = (size_t)(b * Hh + h) * Tt * HDd;
    const uint32_t sbase = smem_u32(sma);

    const int aRow = lane & 15;
    const int aCol = (lane >> 4) << 3;
    const int bRow = (lane & 7) + ((lane >> 4) << 3);
    const int bCol = lane & 8;

    {
        const __half* qs[2] = {g_qh + hb + (size_t)qg0 * HDd,
                               g_ql + hb + (size_t)qg0 * HDd};
#pragma unroll
        for (int i = 0; i < 16; i++) {
            int idx = tid + i * 256;
            int arr = idx >> 11;
            int rem = idx & 2047;
            int row = rem >> 4;
            int seg = rem & 15;
            uint4 v = *(const uint4*)(qs[arr] + (size_t)row * HDd + seg * 8);
            *(uint4*)(sma + arr * Q_E + row * AP + seg * 8) = v;
        }
    }

    float o[16][4];
#pragma unroll
    for (int ni = 0; ni < 16; ni++)
#pragma unroll
        for (int c = 0; c < 4; c++) o[ni][c] = 0.0f;
    float m_run[2] = {-1e30f, -1e30f}, l_run[2] = {0.0f, 0.0f};

    const int nkb = 2 * qb + 2;
    const int qwr = qg0 + w * 16;

    const uint32_t uQh = sbase + (uint32_t)OFF_QH * 2;
    const uint32_t uQl = sbase + (uint32_t)OFF_QL * 2;
    const uint32_t uPh = sbase + (uint32_t)OFF_PH * 2;
    const uint32_t uPl = sbase + (uint32_t)OFF_PL * 2;

    auto load_kv = [&](int kb) {
        const int st = kb & 1;
        const int kg = kb * 64;
        const uint32_t stb = (uint32_t)(OFF_KV0 + st * KV_STAGE);
#pragma unroll
        for (int i = 0; i < 12; i++) {
            int idx = tid + i * 256;
            int arr = idx >> 10;
            int rem = idx & 1023;
            int row = rem >> 4;
            int seg = rem & 15;
            const __half* src = (arr == 0 ? g_kh : arr == 1 ? g_kl : g_v);
            const __half* gp = src + hb + (size_t)(kg + row) * HDd + seg * 8;
            uint32_t sa = sbase + (uint32_t)(stb + arr * K_E + row * AP + seg * 8) * 2;
            asm volatile("cp.async.ca.shared.global [%0], [%1], 16;"
                         :: "r"(sa), "l"(gp));
        }
    };

    load_kv(0);
    asm volatile("cp.async.commit_group;");

    for (int kb = 0; kb < nkb; kb++) {
        const int kg0 = kb * 64;
        if (kb + 1 < nkb) {
            load_kv(kb + 1);
            asm volatile("cp.async.commit_group;");
            asm volatile("cp.async.wait_group 1;");
        } else {
            asm volatile("cp.async.wait_group 0;");
        }
        __syncthreads();

        const int st = kb & 1;
        const uint32_t uKh = sbase + (uint32_t)(OFF_KV0 + st * KV_STAGE) * 2;
        const uint32_t uKl = uKh + (uint32_t)K_E * 2;
        const uint32_t uV  = uKh + (uint32_t)(2 * K_E) * 2;

        const bool active = (kg0 <= qwr + 15);
        if (active) {
            float s[8][4];
#pragma unroll
            for (int ni = 0; ni < 8; ni++)
#pragma unroll
                for (int c = 0; c < 4; c++) s[ni][c] = 0.0f;

#pragma unroll
            for (int kc = 0; kc < 8; kc++) {
                const int colb = kc * 16;
                uint32_t offA = (uint32_t)((w * 16 + aRow) * AP + colb + aCol) * 2;
                uint32_t ah[4], al[4];
                ldsm_x4(ah, uQh + offA);
                ldsm_x4(al, uQl + offA);
                uint32_t kbh[8][2], kbl[8][2];
#pragma unroll
                for (int np = 0; np < 4; np++) {
                    uint32_t offB = (uint32_t)((np * 16 + bRow) * AP + colb + bCol) * 2;
                    uint32_t r4[4];
                    ldsm_x4(r4, uKh + offB);
                    kbh[np * 2][0] = r4[0]; kbh[np * 2][1] = r4[1];
                    kbh[np * 2 + 1][0] = r4[2]; kbh[np * 2 + 1][1] = r4[3];
                    ldsm_x4(r4, uKl + offB);
                    kbl[np * 2][0] = r4[0]; kbl[np * 2][1] = r4[1];
                    kbl[np * 2 + 1][0] = r4[2]; kbl[np * 2 + 1][1] = r4[3];
                }
#pragma unroll
                for (int ni = 0; ni < 8; ni++) mma_f16(s[ni], ah, kbh[ni]);
#pragma unroll
                for (int ni = 0; ni < 8; ni++) mma_f16(s[ni], ah, kbl[ni]);
#pragma unroll
                for (int ni = 0; ni < 8; ni++) mma_f16(s[ni], al, kbh[ni]);
            }

            if (kg0 + 63 > qwr) {
#pragma unroll
                for (int ni = 0; ni < 8; ni++)
#pragma unroll
                    for (int c = 0; c < 4; c++) {
                        int key = kg0 + ni * 8 + t2 + (c & 1);
                        int qr = qwr + g + ((c & 2) ? 8 : 0);
                        if (key > qr) s[ni][c] = -1e30f;
                    }
            }

            __half* sPh = sma + OFF_PH;
            __half* sPl = sma + OFF_PL;
#pragma unroll
            for (int r = 0; r < 2; r++) {
                float mt = -1e30f;
#pragma unroll
                for (int ni = 0; ni < 8; ni++)
                    mt = fmaxf(mt, fmaxf(s[ni][2 * r], s[ni][2 * r + 1]));
                mt = fmaxf(mt, __shfl_xor_sync(0xffffffffu, mt, 1));
                mt = fmaxf(mt, __shfl_xor_sync(0xffffffffu, mt, 2));
                float mnew = fmaxf(m_run[r], mt);
                float corr = __expf(m_run[r] - mnew);
                m_run[r] = mnew;
                float psum = 0.0f;
                const int prow = w * 16 + g + r * 8;
#pragma unroll
                for (int ni = 0; ni < 8; ni++) {
                    float p0 = __expf(s[ni][2 * r] - mnew);
                    float p1 = __expf(s[ni][2 * r + 1] - mnew);
                    psum += p0 + p1;
                    __half2 h2 = __floats2half2_rn(p0, p1);
                    float l0 = p0 - __half2float(__low2half(h2));
                    float l1 = p1 - __half2float(__high2half(h2));
                    __half2 l2 = __floats2half2_rn(l0, l1);
                    *(uint32_t*)&sPh[prow * PP + ni * 8 + t2] = *(uint32_t*)&h2;
                    *(uint32_t*)&sPl[prow * PP + ni * 8 + t2] = *(uint32_t*)&l2;
                }
                psum += __shfl_xor_sync(0xffffffffu, psum, 1);
                psum += __shfl_xor_sync(0xffffffffu, psum, 2);
                l_run[r] = l_run[r] * corr + psum;
#pragma unroll
                for (int ni = 0; ni < 16; ni++) {
                    o[ni][2 * r] *= corr;
                    o[ni][2 * r + 1] *= corr;
                }
            }
            __syncwarp();

#pragma unroll
            for (int kc = 0; kc < 4; kc++) {
                const int colb = kc * 16;
                uint32_t offA = (uint32_t)((w * 16 + aRow) * PP + colb + aCol) * 2;
                uint32_t ah[4], al[4];
                ldsm_x4(ah, uPh + offA);
                ldsm_x4(al, uPl + offA);
#pragma unroll
                for (int np = 0; np < 8; np++) {
                    uint32_t offV = (uint32_t)((kc * 16 + aRow) * AP + np * 16 + aCol) * 2;
                    uint32_t r4[4];
                    uint32_t bA[2], bB[2];
                    ldsm_x4_trans(r4, uV + offV);
                    bA[0] = r4[0]; bA[1] = r4[1]; bB[0] = r4[2]; bB[1] = r4[3];
                    mma_f16(o[np * 2], ah, bA);
                    mma_f16(o[np * 2], al, bA);
                    mma_f16(o[np * 2 + 1], ah, bB);
                    mma_f16(o[np * 2 + 1], al, bB);
                }
            }
        }
        __syncthreads();
    }

#pragma unroll
    for (int r = 0; r < 2; r++) {
        float inv = 1.0f / l_run[r];
        int t = qg0 + w * 16 + g + r * 8;
        size_t rowo = (size_t)(b * Tt + t) * Dd + h * HDd;
#pragma unroll
        for (int ni = 0; ni < 16; ni++) {
            float v0 = o[ni][2 * r] * inv;
            float v1 = o[ni][2 * r + 1] * inv;
            __half2 h2 = __floats2half2_rn(v0, v1);
            float l0 = v0 - __half2float(__low2half(h2));
            float l1 = v1 - __half2float(__high2half(h2));
            __half2 l2 = __floats2half2_rn(l0, l1);
            *(uint32_t*)&g_aoh[rowo + ni * 8 + t2] = *(uint32_t*)&h2;
            *(uint32_t*)&g_aol[rowo + ni * 8 + t2] = *(uint32_t*)&l2;
        }
    }
}

// ================= launch ===================================================
extern "C" void kernel_launch(void* const* d_in, const int* in_sizes, int n_in,
                              void* d_out, int out_size) {
    const float* x = (const float*)d_in[0];
    const int* positions = (const int*)d_in[2];
    const float* qkv_w = (const float*)d_in[3];
    const float* out_w = (const float*)d_in[4];
    const float* q_norm_w = (const float*)d_in[5];
    const float* k_norm_w = (const float*)d_in[6];
    float* out = (float*)d_out;
    (void)in_sizes; (void)n_in; (void)out_size;

    void *p_qkv, *p_x16, *p_aoh, *p_aol, *p_wq, *p_wo;
    cudaGetSymbolAddress(&p_qkv, g_qkv);
    cudaGetSymbolAddress(&p_x16, g_x16);
    cudaGetSymbolAddress(&p_aoh, g_aoh);
    cudaGetSymbolAddress(&p_aol, g_aol);
    cudaGetSymbolAddress(&p_wq, g_wq);
    cudaGetSymbolAddress(&p_wo, g_wo);

    static int attr_set = 0;
    if (!attr_set) {
        cudaFuncSetAttribute(gemm1_kernel, cudaFuncAttributeMaxDynamicSharedMemorySize, GEMM1_SMEM);
        cudaFuncSetAttribute(gemm_mma_kernel, cudaFuncAttributeMaxDynamicSharedMemorySize, GEMM_SMEM);
        cudaFuncSetAttribute(attn_mma_kernel, cudaFuncAttributeMaxDynamicSharedMemorySize, ATTN_SMEM);
        attr_set = 1;
    }

    const int M = Bb * Tt;

    rope_table_kernel<<<(Bb * Tt * 64 + 255) / 256, 256>>>(positions);
    convert_kernel<<<(M * Dd / 4 + 255) / 256, 256>>>(x, (__half*)p_x16, M * Dd / 4);
    transpose_kernel<<<dim3(3 * Dd / 32, Dd / 32, 2), dim3(32, 8)>>>(qkv_w, out_w);
    gemm1_kernel<<<dim3(3 * Dd / 128, M / 128), 256, GEMM1_SMEM>>>(
        (const __half*)p_x16, (const __half*)p_wq, (float*)p_qkv, M, 3 * Dd, Dd);
    rope_norm_kernel<<<dim3(Hh, Tt, Bb), 128>>>(q_norm_w, k_norm_w);
    attn_mma_kernel<<<dim3(Tt / 128, Hh, Bb), 256, ATTN_SMEM>>>();
    gemm_mma_kernel<<<dim3(Dd / 128, M / 128), 256, GEMM_SMEM>>>(
        (const __half*)p_aoh, (const __half*)p_aol, (const __half*)p_wo,
        out, M, Dd, Dd);
}